// round 9
// baseline (speedup 1.0000x reference)
#include <cuda_runtime.h>
#include <cuda_bf16.h>
#include <math.h>
#include <stdint.h>

// ---------------------------------------------------------------------------
// PhysicsGraphFusion: B=1024 graphs, N=7 nodes, D=1024 dim.
// Round 6: split-bf16 GEMM with 256x128 CTA tile / 64x64 warp tile
// (mma:LDS = 1.5:1) and cp.async double-buffered loader (no prefetch regs).
// ---------------------------------------------------------------------------

#define BB   1024
#define NN   7
#define DD   1024
#define MM   (BB*NN)          // 7168
#define NP   (5*DD)           // 5120 packed projection width

static const size_t OFF_FUSED = 0;
static const size_t OFF_UPD   = (size_t)BB*DD;
static const size_t OFF_IMP   = OFF_UPD + (size_t)MM*DD;
static const size_t OFF_ATTN  = OFF_IMP + (size_t)MM;
static const size_t OFF_PHYS  = OFF_ATTN + (size_t)BB*NN*NN;
static const size_t OFF_ALIGN = OFF_PHYS + 1;

// ---------------- device scratch (static; no runtime allocation) -----------
__device__ float    g_qkv [ (size_t)MM*NP ];
__device__ float    g_cc  [ (size_t)BB*DD ];
__device__ float    g_msg [ (size_t)MM*DD ];
__device__ float    g_hid [ (size_t)MM*DD ];
__device__ float    g_bpack[ NP ];
__device__ float    g_implog[ MM ];
__device__ float    g_phys_part [ BB ];
__device__ float    g_align_part[ BB ];

// activation planes (bf16 stored as uint32 k-pairs, row-major)
__device__ uint32_t g_nodes_h[ (size_t)MM*DD/2 ];
__device__ uint32_t g_nodes_l[ (size_t)MM*DD/2 ];
__device__ uint32_t g_cat_h  [ (size_t)MM*DD ];     // width 2048 -> 1024 u32
__device__ uint32_t g_cat_l  [ (size_t)MM*DD ];
__device__ uint32_t g_hidp_h [ (size_t)MM*DD/2 ];
__device__ uint32_t g_hidp_l [ (size_t)MM*DD/2 ];

// weight planes (k-pair packed uint32 [K/2][Nc])
__device__ uint32_t g_Wproj_h[ (size_t)(DD/2)*NP ];
__device__ uint32_t g_Wproj_l[ (size_t)(DD/2)*NP ];
__device__ uint32_t g_Wc_h   [ (size_t)(DD/2)*DD ];
__device__ uint32_t g_Wc_l   [ (size_t)(DD/2)*DD ];
__device__ uint32_t g_Wu1_h  [ (size_t)DD*DD ];
__device__ uint32_t g_Wu1_l  [ (size_t)DD*DD ];
__device__ uint32_t g_Wu2_h  [ (size_t)(DD/2)*DD ];
__device__ uint32_t g_Wu2_l  [ (size_t)(DD/2)*DD ];
__device__ uint32_t g_Wi1_h  [ (size_t)DD*DD ];
__device__ uint32_t g_Wi1_l  [ (size_t)DD*DD ];

__constant__ float c_adj[49] = {
    1,1,0,0,1,1,1,
    1,1,1,1,1,1,1,
    0,1,1,0,1,0,1,
    0,1,0,1,1,1,1,
    1,1,1,1,1,1,1,
    1,1,0,1,1,1,1,
    1,1,1,1,1,1,1 };

__device__ __forceinline__ float geluf(float x) {
    return 0.5f * x * (1.0f + erff(x * 0.70710678118654752440f));
}

__device__ __forceinline__ unsigned short bf16_rn(float x) {
    __nv_bfloat16 h = __float2bfloat16(x);
    return *reinterpret_cast<unsigned short*>(&h);
}
__device__ __forceinline__ float bf16_to_f(unsigned short u) {
    __nv_bfloat16 h = *reinterpret_cast<__nv_bfloat16*>(&u);
    return __bfloat162float(h);
}
__device__ __forceinline__ void splitpack(float x0, float x1,
                                          uint32_t& H, uint32_t& L) {
    unsigned short h0 = bf16_rn(x0), h1 = bf16_rn(x1);
    float r0 = x0 - bf16_to_f(h0);
    float r1 = x1 - bf16_to_f(h1);
    unsigned short l0 = bf16_rn(r0), l1 = bf16_rn(r1);
    H = (uint32_t)h0 | ((uint32_t)h1 << 16);
    L = (uint32_t)l0 | ((uint32_t)l1 << 16);
}

__device__ __forceinline__ void mma_bf16(float* c,
    uint32_t a0, uint32_t a1, uint32_t a2, uint32_t a3,
    uint32_t b0, uint32_t b1)
{
    asm volatile(
        "mma.sync.aligned.m16n8k16.row.col.f32.bf16.bf16.f32 "
        "{%0,%1,%2,%3}, {%4,%5,%6,%7}, {%8,%9}, {%0,%1,%2,%3};\n"
        : "+f"(c[0]), "+f"(c[1]), "+f"(c[2]), "+f"(c[3])
        : "r"(a0), "r"(a1), "r"(a2), "r"(a3), "r"(b0), "r"(b1));
}

__device__ __forceinline__ void cp_async16(uint32_t saddr, const void* gptr) {
    asm volatile("cp.async.ca.shared.global [%0], [%1], 16;\n"
                 :: "r"(saddr), "l"(gptr));
}

// ---------------------------------------------------------------------------
// bf16x2 tensor-core GEMM. C[M,Nc] = epi(A[M,K] @ W[K,Nc] + bias).
// BM=256, BN=128, BK=32. 256 threads = 8 warps (4x2), warp tile 64x64.
// smem/buffer: Ah[256][20] Al[256][20] Bh[16][136] Bl[16][136] (u32 words).
// Double-buffered via cp.async. M%256==0, Nc%128==0, K%32==0.
// ---------------------------------------------------------------------------
#define A_ST 20
#define B_ST 136
#define A_PL (256*A_ST)           // 5120
#define B_PL (16*B_ST)            // 2176
#define BUF_U32 (2*A_PL + 2*B_PL) // 14592
#define SMEM_GEMM_BYTES (2*BUF_U32*4)  // 116736

__global__ __launch_bounds__(256)
void gemm_bf16x2_kernel(int M, int Nc, int K,
    const uint32_t* __restrict__ Ah, const uint32_t* __restrict__ Al, int lda32,
    const uint32_t* __restrict__ Bh, const uint32_t* __restrict__ Bl,
    const float* __restrict__ bias,
    const float* __restrict__ resid,
    float* __restrict__ Cf,
    uint32_t* __restrict__ ChH, uint32_t* __restrict__ ChL,
    int applyGelu)
{
    extern __shared__ uint32_t smem[];
    const uint32_t smem_base = (uint32_t)__cvta_generic_to_shared(smem);

    const int tid  = threadIdx.x;
    const int lane = tid & 31;
    const int wid  = tid >> 5;
    const int wm   = wid & 3;      // 0..3 -> 64-row slices
    const int wn   = wid >> 2;     // 0..1 -> 64-col slices
    const int gid  = lane >> 2;    // 0..7
    const int tig  = lane & 3;     // 0..3

    const int brow = blockIdx.y;
    const int bcol = blockIdx.x;

    // A loader: 2048 uint4 slots (2 planes x 256 rows x 4), 8 per thread
    int aPl[8], aRow[8], aC[8], aSm[8];
    #pragma unroll
    for (int it = 0; it < 8; it++) {
        int idx = it * 256 + tid;
        aPl[it]  = idx >> 10;
        int s    = idx & 1023;
        aRow[it] = s >> 2;
        aC[it]   = (s & 3) << 2;
        aSm[it]  = aPl[it] * A_PL + aRow[it] * A_ST + aC[it];
    }
    // B loader: 1024 uint4 slots (2 planes x 16 kp x 32), 4 per thread
    int bPl[4], bKp[4], bC[4], bSm[4];
    #pragma unroll
    for (int it = 0; it < 4; it++) {
        int idx = it * 256 + tid;
        bPl[it] = idx >> 9;
        int s   = idx & 511;
        bKp[it] = s >> 5;
        bC[it]  = (s & 31) << 2;
        bSm[it] = 2 * A_PL + bPl[it] * B_PL + bKp[it] * B_ST + bC[it];
    }

    const uint32_t* Asrc[2] = { Ah + (size_t)(brow * 256) * lda32,
                                Al + (size_t)(brow * 256) * lda32 };
    const uint32_t* Bsrc[2] = { Bh + bcol * 128, Bl + bcol * 128 };

    float acc[4][8][4];
    #pragma unroll
    for (int mi = 0; mi < 4; mi++)
        #pragma unroll
        for (int ni = 0; ni < 8; ni++)
            #pragma unroll
            for (int r = 0; r < 4; r++) acc[mi][ni][r] = 0.0f;

    // issue chunk 0 into buffer 0
    #pragma unroll
    for (int it = 0; it < 8; it++)
        cp_async16(smem_base + aSm[it] * 4,
                   Asrc[aPl[it]] + (size_t)aRow[it] * lda32 + aC[it]);
    #pragma unroll
    for (int it = 0; it < 4; it++)
        cp_async16(smem_base + bSm[it] * 4,
                   Bsrc[bPl[it]] + (size_t)bKp[it] * Nc + bC[it]);
    asm volatile("cp.async.commit_group;\n");
    asm volatile("cp.async.wait_group 0;\n" ::: "memory");
    __syncthreads();

    const int nChunks = K >> 5;
    for (int c = 0; c < nChunks; c++) {
        const uint32_t* buf = smem + (size_t)(c & 1) * BUF_U32;
        const uint32_t* sAh = buf;
        const uint32_t* sAl = buf + A_PL;
        const uint32_t* sBh = buf + 2 * A_PL;
        const uint32_t* sBl = buf + 2 * A_PL + B_PL;

        const bool more = (c + 1 < nChunks);
        if (more) {
            const uint32_t nb = (uint32_t)(((c + 1) & 1) * BUF_U32) * 4;
            const int kb32 = ((c + 1) << 5) >> 1;
            #pragma unroll
            for (int it = 0; it < 8; it++)
                cp_async16(smem_base + nb + aSm[it] * 4,
                           Asrc[aPl[it]] + (size_t)aRow[it] * lda32 + kb32 + aC[it]);
            #pragma unroll
            for (int it = 0; it < 4; it++)
                cp_async16(smem_base + nb + bSm[it] * 4,
                           Bsrc[bPl[it]] + (size_t)(kb32 + bKp[it]) * Nc + bC[it]);
            asm volatile("cp.async.commit_group;\n");
        }

        #pragma unroll
        for (int ks = 0; ks < 2; ks++) {
            uint32_t fah[4][4], fal[4][4];
            #pragma unroll
            for (int mi = 0; mi < 4; mi++) {
                int r0 = (wm * 64 + mi * 16 + gid) * A_ST + ks * 8 + tig;
                fah[mi][0] = sAh[r0];
                fah[mi][1] = sAh[r0 + 8 * A_ST];
                fah[mi][2] = sAh[r0 + 4];
                fah[mi][3] = sAh[r0 + 8 * A_ST + 4];
                fal[mi][0] = sAl[r0];
                fal[mi][1] = sAl[r0 + 8 * A_ST];
                fal[mi][2] = sAl[r0 + 4];
                fal[mi][3] = sAl[r0 + 8 * A_ST + 4];
            }
            #pragma unroll
            for (int ni = 0; ni < 8; ni++) {
                int kb = (ks * 8 + tig) * B_ST + wn * 64 + ni * 8 + gid;
                uint32_t bh0 = sBh[kb];
                uint32_t bh1 = sBh[kb + 4 * B_ST];
                uint32_t bl0 = sBl[kb];
                uint32_t bl1 = sBl[kb + 4 * B_ST];
                #pragma unroll
                for (int mi = 0; mi < 4; mi++) {
                    mma_bf16(acc[mi][ni], fah[mi][0], fah[mi][1], fah[mi][2], fah[mi][3], bh0, bh1);
                    mma_bf16(acc[mi][ni], fah[mi][0], fah[mi][1], fah[mi][2], fah[mi][3], bl0, bl1);
                    mma_bf16(acc[mi][ni], fal[mi][0], fal[mi][1], fal[mi][2], fal[mi][3], bh0, bh1);
                }
            }
        }

        if (more)
            asm volatile("cp.async.wait_group 0;\n" ::: "memory");
        __syncthreads();
    }

    // ---- epilogue ----
    const int Nc2 = Nc >> 1;
    #pragma unroll
    for (int mi = 0; mi < 4; mi++) {
        #pragma unroll
        for (int ni = 0; ni < 8; ni++) {
            int row0 = brow * 256 + wm * 64 + mi * 16 + gid;
            int col0 = bcol * 128 + wn * 64 + ni * 8 + tig * 2;
            #pragma unroll
            for (int half = 0; half < 2; half++) {
                int row = row0 + half * 8;
                size_t base = (size_t)row * Nc + col0;
                float v0 = acc[mi][ni][half * 2 + 0];
                float v1 = acc[mi][ni][half * 2 + 1];
                if (bias) { v0 += bias[col0]; v1 += bias[col0 + 1]; }
                if (applyGelu) { v0 = geluf(v0); v1 = geluf(v1); }
                if (resid) { v0 += resid[base]; v1 += resid[base + 1]; }
                if (Cf) { Cf[base] = v0; Cf[base + 1] = v1; }
                if (ChH) {
                    uint32_t H, L;
                    splitpack(v0, v1, H, L);
                    size_t pidx = (size_t)row * Nc2 + (col0 >> 1);
                    ChH[pidx] = H;
                    ChL[pidx] = L;
                }
            }
        }
    }
}

// ---------------------------------------------------------------------------
// pre-split / pack kernels
// ---------------------------------------------------------------------------
__global__ void split_nodes_kernel(const float* __restrict__ nodes)
{
    size_t i = (size_t)blockIdx.x * blockDim.x + threadIdx.x;
    if (i >= (size_t)MM * DD / 2) return;
    float x0 = nodes[2 * i], x1 = nodes[2 * i + 1];
    splitpack(x0, x1, g_nodes_h[i], g_nodes_l[i]);
}

__global__ void pack_proj_w_kernel(const float* __restrict__ Wq,
                                   const float* __restrict__ Wk,
                                   const float* __restrict__ Wv,
                                   const float* __restrict__ We1)
{
    size_t i = (size_t)blockIdx.x * blockDim.x + threadIdx.x;
    if (i >= (size_t)(DD / 2) * NP) return;
    int kp = (int)(i / NP);
    int c  = (int)(i % NP);
    int seg = c >> 10, cc = c & 1023;
    const float* src;
    if      (seg == 0) src = Wq;
    else if (seg == 1) src = Wk;
    else if (seg == 2) src = Wv;
    else if (seg == 3) src = We1;
    else               src = We1 + (size_t)DD * DD;
    float w0 = src[(size_t)(2 * kp) * DD + cc];
    float w1 = src[(size_t)(2 * kp + 1) * DD + cc];
    splitpack(w0, w1, g_Wproj_h[i], g_Wproj_l[i]);
}

__global__ void pack_w_gen_kernel(const float* __restrict__ W, int K, int Nc,
                                  uint32_t* __restrict__ H, uint32_t* __restrict__ L)
{
    size_t i = (size_t)blockIdx.x * blockDim.x + threadIdx.x;
    if (i >= (size_t)(K / 2) * Nc) return;
    int kp = (int)(i / Nc);
    int n  = (int)(i % Nc);
    float w0 = W[(size_t)(2 * kp) * Nc + n];
    float w1 = W[(size_t)(2 * kp + 1) * Nc + n];
    splitpack(w0, w1, H[i], L[i]);
}

__global__ void pack_b_kernel(const float* __restrict__ bq,
                              const float* __restrict__ bk,
                              const float* __restrict__ bv)
{
    int c = blockIdx.x * blockDim.x + threadIdx.x;
    if (c >= NP) return;
    int seg = c >> 10, cc = c & 1023;
    float v = 0.0f;
    if      (seg == 0) v = bq[cc];
    else if (seg == 1) v = bk[cc];
    else if (seg == 2) v = bv[cc];
    g_bpack[c] = v;
}

// cat planes = split([nodes | msg]) width 2048
__global__ void concat_nm_kernel(const float* __restrict__ nodes)
{
    size_t i = (size_t)blockIdx.x * blockDim.x + threadIdx.x;
    if (i >= (size_t)MM * DD) return;
    size_t row = i / DD;
    int dp = (int)(i % DD);
    size_t srcbase = row * DD;
    float x0, x1;
    if (dp < DD / 2) { x0 = nodes[srcbase + 2 * dp];      x1 = nodes[srcbase + 2 * dp + 1]; }
    else { int d2 = 2 * dp - DD; x0 = g_msg[srcbase + d2]; x1 = g_msg[srcbase + d2 + 1]; }
    splitpack(x0, x1, g_cat_h[row * DD + dp], g_cat_l[row * DD + dp]);
}

// cat planes = split([updated | updated[b,N-1] broadcast])
__global__ void concat_ug_kernel(const float* __restrict__ upd)
{
    size_t i = (size_t)blockIdx.x * blockDim.x + threadIdx.x;
    if (i >= (size_t)MM * DD) return;
    size_t row = i / DD;
    int dp = (int)(i % DD);
    size_t b = row / NN;
    float x0, x1;
    if (dp < DD / 2) {
        x0 = upd[row * DD + 2 * dp]; x1 = upd[row * DD + 2 * dp + 1];
    } else {
        int d2 = 2 * dp - DD;
        size_t gr = (b * NN + (NN - 1)) * (size_t)DD;
        x0 = upd[gr + d2]; x1 = upd[gr + d2 + 1];
    }
    splitpack(x0, x1, g_cat_h[row * DD + dp], g_cat_l[row * DD + dp]);
}

// ---------------------------------------------------------------------------
// attention / small kernels
// ---------------------------------------------------------------------------
__global__ __launch_bounds__(256)
void attn_kernel(const float* __restrict__ be1,
                 const float* __restrict__ We2,
                 const float* __restrict__ be2,
                 float* __restrict__ out_attn)
{
    const int b    = blockIdx.x;
    const int tid  = threadIdx.x;
    const int lane = tid & 31;
    const int wid  = tid >> 5;

    __shared__ float s_logit[49];
    __shared__ float s_attn[49];

    const float* base = g_qkv + (size_t)b * NN * NP;
    const float* cc   = g_cc  + (size_t)b * DD;

    for (int p = wid; p < 49; p += 8) {
        const int n = p / 7, m = p % 7;
        const float* qn  = base + (size_t)n * NP + 0*DD;
        const float* km  = base + (size_t)m * NP + 1*DD;
        const float* lan = base + (size_t)n * NP + 3*DD;
        const float* rbm = base + (size_t)m * NP + 4*DD;
        float qk = 0.0f, e = 0.0f;
        for (int d = lane; d < DD; d += 32) {
            qk = fmaf(qn[d], km[d], qk);
            float h = lan[d] + rbm[d] + cc[d] + be1[d];
            e  = fmaf(geluf(h), We2[d], e);
        }
        #pragma unroll
        for (int o = 16; o > 0; o >>= 1) {
            qk += __shfl_down_sync(0xffffffffu, qk, o);
            e  += __shfl_down_sync(0xffffffffu, e,  o);
        }
        if (lane == 0)
            s_logit[p] = qk * (1.0f / 32.0f) + e + be2[0]
                       + (c_adj[p] - 1.0f) * 10000.0f;
    }
    __syncthreads();

    if (tid < 7) {
        const int n = tid;
        float mx = -1e30f;
        #pragma unroll
        for (int m = 0; m < 7; m++) mx = fmaxf(mx, s_logit[n * 7 + m]);
        float ex[7], s = 0.0f;
        #pragma unroll
        for (int m = 0; m < 7; m++) { ex[m] = expf(s_logit[n * 7 + m] - mx); s += ex[m]; }
        #pragma unroll
        for (int m = 0; m < 7; m++) {
            float a = ex[m] / s;
            s_attn[n * 7 + m] = a;
            out_attn[(size_t)b * 49 + n * 7 + m] = a;
        }
    }
    __syncthreads();

    float* msg = g_msg + (size_t)b * NN * DD;
    for (int d = tid; d < DD; d += 256) {
        float vv[7];
        #pragma unroll
        for (int m = 0; m < 7; m++) vv[m] = base[(size_t)m * NP + 2*DD + d];
        #pragma unroll
        for (int n = 0; n < 7; n++) {
            float acc = 0.0f;
            #pragma unroll
            for (int m = 0; m < 7; m++) acc = fmaf(s_attn[n * 7 + m], vv[m], acc);
            msg[n * DD + d] = acc;
        }
    }
}

__global__ __launch_bounds__(128)
void gemv_imp_kernel(const float* __restrict__ Wi2, const float* __restrict__ bi2)
{
    const int row = blockIdx.x;
    const int tid = threadIdx.x;
    const float* h = g_hid + (size_t)row * DD;
    float s = 0.0f;
    for (int d = tid; d < DD; d += 128) s = fmaf(h[d], Wi2[d], s);
    #pragma unroll
    for (int o = 16; o > 0; o >>= 1) s += __shfl_down_sync(0xffffffffu, s, o);
    __shared__ float red[4];
    if ((tid & 31) == 0) red[tid >> 5] = s;
    __syncthreads();
    if (tid == 0)
        g_implog[row] = red[0] + red[1] + red[2] + red[3] + bi2[0];
}

__global__ void imp_kernel(float* __restrict__ out_imp)
{
    const int b = blockIdx.x;
    if (threadIdx.x != 0) return;
    float l[7], mx = -1e30f;
    #pragma unroll
    for (int n = 0; n < 7; n++) { l[n] = g_implog[b * 7 + n]; mx = fmaxf(mx, l[n]); }
    float s = 0.0f;
    #pragma unroll
    for (int n = 0; n < 7; n++) { l[n] = expf(l[n] - mx); s += l[n]; }
    float imp[7];
    #pragma unroll
    for (int n = 0; n < 7; n++) imp[n] = l[n] / s;

    const float cap[7] = {1.f,1.f,1.f,0.26f,1.f,1.f,0.24f};
    const float fr [7] = {1.f,1.f,1.f,0.f,  1.f,1.f,0.f };
    float capped[7], sc = 0.0f, fm = 0.0f;
    #pragma unroll
    for (int n = 0; n < 7; n++) {
        capped[n] = fminf(imp[n], cap[n]);
        sc += capped[n];
        fm += imp[n] * fr[n];
    }
    float residual = fmaxf(1.0f - sc, 0.0f);
    float redis[7], sr = 0.0f;
    #pragma unroll
    for (int n = 0; n < 7; n++) {
        float fs = (fm > 1e-6f) ? imp[n] * fr[n] / fmaxf(fm, 1e-6f) : fr[n] / 5.0f;
        redis[n] = capped[n] + fs * residual;
        sr += redis[n];
    }
    #pragma unroll
    for (int n = 0; n < 7; n++)
        out_imp[b * 7 + n] = redis[n] / fmaxf(sr, 1e-6f);
}

__global__ __launch_bounds__(256)
void fused_kernel(const float* __restrict__ out_imp,
                  const float* __restrict__ upd,
                  float* __restrict__ out_fused)
{
    const int b = blockIdx.x;
    const int tid = threadIdx.x;
    __shared__ float w[7];
    if (tid < 7) w[tid] = out_imp[b * 7 + tid];
    __syncthreads();
    const float* u = upd + (size_t)b * NN * DD;
    for (int d = tid; d < DD; d += 256) {
        float acc = 0.0f;
        #pragma unroll
        for (int n = 0; n < 7; n++) acc = fmaf(w[n], u[n * DD + d], acc);
        out_fused[(size_t)b * DD + d] = acc;
    }
}

__global__ __launch_bounds__(256)
void physalign_kernel(const float* __restrict__ upd,
                      const float* __restrict__ fused)
{
    const int b = blockIdx.x;
    const int tid = threadIdx.x;
    const int lane = tid & 31, wid = tid >> 5;
    __shared__ float dots[57];
    const float* u = upd   + (size_t)b * NN * DD;
    const float* f = fused + (size_t)b * DD;

    for (int t = wid; t < 57; t += 8) {
        const float *x, *y;
        if (t < 49)      { x = u + (t / 7) * DD; y = u + (t % 7) * DD; }
        else if (t < 56) { x = u + (t - 49) * DD; y = f; }
        else             { x = f; y = f; }
        float s = 0.0f;
        for (int d = lane; d < DD; d += 32) s = fmaf(x[d], y[d], s);
        #pragma unroll
        for (int o = 16; o > 0; o >>= 1) s += __shfl_down_sync(0xffffffffu, s, o);
        if (lane == 0) dots[t] = s;
    }
    __syncthreads();

    if (tid == 0) {
        float norms[7];
        #pragma unroll
        for (int n = 0; n < 7; n++) norms[n] = sqrtf(dots[n * 7 + n]);
        float edge = 0.0f, non = 0.0f;
        #pragma unroll
        for (int n = 0; n < 7; n++) {
            #pragma unroll
            for (int m = 0; m < 7; m++) {
                float cs = dots[n * 7 + m] / fmaxf(norms[n] * norms[m], 1e-8f);
                float a = c_adj[n * 7 + m];
                edge += (1.0f - cs) * a;
                float nonmask = (1.0f - a) * ((n == m) ? 0.0f : 1.0f);
                non += fmaxf(cs - 0.35f, 0.0f) * nonmask;
            }
        }
        g_phys_part[b] = edge / 41.0f + 0.5f * non / 8.0f;

        float fn = sqrtf(dots[56]);
        float al = 0.0f;
        #pragma unroll
        for (int n = 0; n < 7; n++) {
            float cs = dots[49 + n] / (fmaxf(norms[n], 1e-12f) * fmaxf(fn, 1e-12f));
            al += 1.0f - cs;
        }
        g_align_part[b] = al;
    }
}

__global__ __launch_bounds__(256)
void final_reduce_kernel(float* __restrict__ out)
{
    const int tid = threadIdx.x;
    float p = 0.0f, a = 0.0f;
    for (int b = tid; b < BB; b += 256) { p += g_phys_part[b]; a += g_align_part[b]; }
    __shared__ float sp[256], sa[256];
    sp[tid] = p; sa[tid] = a;
    __syncthreads();
    for (int s = 128; s > 0; s >>= 1) {
        if (tid < s) { sp[tid] += sp[tid + s]; sa[tid] += sa[tid + s]; }
        __syncthreads();
    }
    if (tid == 0) {
        out[OFF_PHYS]  = sp[0];
        out[OFF_ALIGN] = sa[0] / (float)(BB * NN);
    }
}

// ---------------------------------------------------------------------------
extern "C" void kernel_launch(void* const* d_in, const int* in_sizes, int n_in,
                              void* d_out, int out_size)
{
    const float* nodes = (const float*)d_in[0];
    const float* Wq    = (const float*)d_in[1];
    const float* bq    = (const float*)d_in[2];
    const float* Wk    = (const float*)d_in[3];
    const float* bk    = (const float*)d_in[4];
    const float* Wv    = (const float*)d_in[5];
    const float* bv    = (const float*)d_in[6];
    const float* We1   = (const float*)d_in[7];
    const float* be1   = (const float*)d_in[8];
    const float* We2   = (const float*)d_in[9];
    const float* be2   = (const float*)d_in[10];
    const float* Wu1   = (const float*)d_in[11];
    const float* bu1   = (const float*)d_in[12];
    const float* Wu2   = (const float*)d_in[13];
    const float* bu2   = (const float*)d_in[14];
    const float* Wi1   = (const float*)d_in[15];
    const float* bi1   = (const float*)d_in[16];
    const float* Wi2   = (const float*)d_in[17];
    const float* bi2   = (const float*)d_in[18];

    float* out       = (float*)d_out;
    float* out_fused = out + OFF_FUSED;
    float* out_upd   = out + OFF_UPD;
    float* out_imp   = out + OFF_IMP;
    float* out_attn  = out + OFF_ATTN;

    float* qkv = nullptr; cudaGetSymbolAddress((void**)&qkv, g_qkv);
    float* cc  = nullptr; cudaGetSymbolAddress((void**)&cc,  g_cc);
    float* hid = nullptr; cudaGetSymbolAddress((void**)&hid, g_hid);
    float* bpk = nullptr; cudaGetSymbolAddress((void**)&bpk, g_bpack);

    uint32_t *ndH=nullptr,*ndL=nullptr,*ctH=nullptr,*ctL=nullptr,*hpH=nullptr,*hpL=nullptr;
    cudaGetSymbolAddress((void**)&ndH, g_nodes_h);
    cudaGetSymbolAddress((void**)&ndL, g_nodes_l);
    cudaGetSymbolAddress((void**)&ctH, g_cat_h);
    cudaGetSymbolAddress((void**)&ctL, g_cat_l);
    cudaGetSymbolAddress((void**)&hpH, g_hidp_h);
    cudaGetSymbolAddress((void**)&hpL, g_hidp_l);

    uint32_t *WprH=nullptr,*WprL=nullptr,*WcH=nullptr,*WcL=nullptr;
    uint32_t *Wu1H=nullptr,*Wu1L=nullptr,*Wu2H=nullptr,*Wu2L=nullptr,*Wi1H=nullptr,*Wi1L=nullptr;
    cudaGetSymbolAddress((void**)&WprH, g_Wproj_h);
    cudaGetSymbolAddress((void**)&WprL, g_Wproj_l);
    cudaGetSymbolAddress((void**)&WcH,  g_Wc_h);
    cudaGetSymbolAddress((void**)&WcL,  g_Wc_l);
    cudaGetSymbolAddress((void**)&Wu1H, g_Wu1_h);
    cudaGetSymbolAddress((void**)&Wu1L, g_Wu1_l);
    cudaGetSymbolAddress((void**)&Wu2H, g_Wu2_h);
    cudaGetSymbolAddress((void**)&Wu2L, g_Wu2_l);
    cudaGetSymbolAddress((void**)&Wi1H, g_Wi1_h);
    cudaGetSymbolAddress((void**)&Wi1L, g_Wi1_l);

    cudaFuncSetAttribute(gemm_bf16x2_kernel,
                         cudaFuncAttributeMaxDynamicSharedMemorySize,
                         SMEM_GEMM_BYTES);

    dim3 blk(256);
    const size_t shm = SMEM_GEMM_BYTES;

    // ---- pre-split activations / pack weights ----
    {
        size_t n;
        n = (size_t)MM * DD / 2;
        split_nodes_kernel<<<(unsigned)((n + 255) / 256), blk>>>(nodes);
        n = (size_t)(DD / 2) * NP;
        pack_proj_w_kernel<<<(unsigned)((n + 255) / 256), blk>>>(Wq, Wk, Wv, We1);
        pack_b_kernel<<<(NP + 255) / 256, blk>>>(bq, bk, bv);
        n = (size_t)(DD / 2) * DD;
        pack_w_gen_kernel<<<(unsigned)((n + 255) / 256), blk>>>(
            We1 + (size_t)2 * DD * DD, DD, DD, WcH, WcL);
        pack_w_gen_kernel<<<(unsigned)((n + 255) / 256), blk>>>(Wu2, DD, DD, Wu2H, Wu2L);
        n = (size_t)DD * DD;
        pack_w_gen_kernel<<<(unsigned)((n + 255) / 256), blk>>>(Wu1, 2 * DD, DD, Wu1H, Wu1L);
        pack_w_gen_kernel<<<(unsigned)((n + 255) / 256), blk>>>(Wi1, 2 * DD, DD, Wi1H, Wi1L);
    }

    // ---- merged projections: [7168,1024] x [1024,5120] -> qkv ----
    dim3 grid_proj(NP / 128, MM / 256);     // 40 x 28
    gemm_bf16x2_kernel<<<grid_proj, blk, shm>>>(MM, NP, DD,
        ndH, ndL, DD / 2, WprH, WprL, bpk, nullptr, qkv, nullptr, nullptr, 0);

    // ---- cc projection (last node rows) ----
    dim3 grid_cc(DD / 128, BB / 256);       // 8 x 4
    gemm_bf16x2_kernel<<<grid_cc, blk, shm>>>(BB, DD, DD,
        ndH + (size_t)(NN - 1) * DD / 2, ndL + (size_t)(NN - 1) * DD / 2, NN * DD / 2,
        WcH, WcL, nullptr, nullptr, cc, nullptr, nullptr, 0);

    // ---- attention ----
    attn_kernel<<<BB, blk>>>(be1, We2, be2, out_attn);

    // ---- update MLP ----
    dim3 grid_big(DD / 128, MM / 256);      // 8 x 28
    {
        size_t n = (size_t)MM * DD;
        concat_nm_kernel<<<(unsigned)((n + 255) / 256), blk>>>(nodes);
    }
    gemm_bf16x2_kernel<<<grid_big, blk, shm>>>(MM, DD, 2 * DD,
        ctH, ctL, DD, Wu1H, Wu1L, bu1, nullptr, nullptr, hpH, hpL, 1);
    gemm_bf16x2_kernel<<<grid_big, blk, shm>>>(MM, DD, DD,
        hpH, hpL, DD / 2, Wu2H, Wu2L, bu2, nodes, out_upd, nullptr, nullptr, 0);

    // ---- importance MLP ----
    {
        size_t n = (size_t)MM * DD;
        concat_ug_kernel<<<(unsigned)((n + 255) / 256), blk>>>(out_upd);
    }
    gemm_bf16x2_kernel<<<grid_big, blk, shm>>>(MM, DD, 2 * DD,
        ctH, ctL, DD, Wi1H, Wi1L, bi1, nullptr, hid, nullptr, nullptr, 1);
    gemv_imp_kernel<<<MM, 128>>>(Wi2, bi2);
    imp_kernel<<<BB, 32>>>(out_imp);

    // ---- fused output + losses ----
    fused_kernel<<<BB, blk>>>(out_imp, out_upd, out_fused);
    physalign_kernel<<<BB, blk>>>(out_upd, out_fused);
    final_reduce_kernel<<<1, blk>>>(out);
}

// round 10
// speedup vs baseline: 1.2199x; 1.2199x over previous
#include <cuda_runtime.h>
#include <cuda_bf16.h>
#include <math.h>
#include <stdint.h>

// ---------------------------------------------------------------------------
// PhysicsGraphFusion: B=1024 graphs, N=7 nodes, D=1024 dim.
// Round 9: R5-proven split-bf16 GEMM (128x128 CTA / 32x64 warp tile)
// + cp.async loader (no staging regs) + __launch_bounds__(256,2)
// => 2 CTAs/SM, 16 warps for latency hiding.
// ---------------------------------------------------------------------------

#define BB   1024
#define NN   7
#define DD   1024
#define MM   (BB*NN)          // 7168
#define NP   (5*DD)           // 5120 packed projection width

static const size_t OFF_FUSED = 0;
static const size_t OFF_UPD   = (size_t)BB*DD;
static const size_t OFF_IMP   = OFF_UPD + (size_t)MM*DD;
static const size_t OFF_ATTN  = OFF_IMP + (size_t)MM;
static const size_t OFF_PHYS  = OFF_ATTN + (size_t)BB*NN*NN;
static const size_t OFF_ALIGN = OFF_PHYS + 1;

// ---------------- device scratch (static; no runtime allocation) -----------
__device__ float    g_qkv [ (size_t)MM*NP ];
__device__ float    g_cc  [ (size_t)BB*DD ];
__device__ float    g_msg [ (size_t)MM*DD ];
__device__ float    g_hid [ (size_t)MM*DD ];
__device__ float    g_bpack[ NP ];
__device__ float    g_implog[ MM ];
__device__ float    g_phys_part [ BB ];
__device__ float    g_align_part[ BB ];

// activation planes (bf16 stored as uint32 k-pairs, row-major)
__device__ uint32_t g_nodes_h[ (size_t)MM*DD/2 ];
__device__ uint32_t g_nodes_l[ (size_t)MM*DD/2 ];
__device__ uint32_t g_cat_h  [ (size_t)MM*DD ];     // width 2048 -> 1024 u32
__device__ uint32_t g_cat_l  [ (size_t)MM*DD ];
__device__ uint32_t g_hidp_h [ (size_t)MM*DD/2 ];
__device__ uint32_t g_hidp_l [ (size_t)MM*DD/2 ];

// weight planes (k-pair packed uint32 [K/2][Nc])
__device__ uint32_t g_Wproj_h[ (size_t)(DD/2)*NP ];
__device__ uint32_t g_Wproj_l[ (size_t)(DD/2)*NP ];
__device__ uint32_t g_Wc_h   [ (size_t)(DD/2)*DD ];
__device__ uint32_t g_Wc_l   [ (size_t)(DD/2)*DD ];
__device__ uint32_t g_Wu1_h  [ (size_t)DD*DD ];
__device__ uint32_t g_Wu1_l  [ (size_t)DD*DD ];
__device__ uint32_t g_Wu2_h  [ (size_t)(DD/2)*DD ];
__device__ uint32_t g_Wu2_l  [ (size_t)(DD/2)*DD ];
__device__ uint32_t g_Wi1_h  [ (size_t)DD*DD ];
__device__ uint32_t g_Wi1_l  [ (size_t)DD*DD ];

__constant__ float c_adj[49] = {
    1,1,0,0,1,1,1,
    1,1,1,1,1,1,1,
    0,1,1,0,1,0,1,
    0,1,0,1,1,1,1,
    1,1,1,1,1,1,1,
    1,1,0,1,1,1,1,
    1,1,1,1,1,1,1 };

__device__ __forceinline__ float geluf(float x) {
    return 0.5f * x * (1.0f + erff(x * 0.70710678118654752440f));
}

__device__ __forceinline__ unsigned short bf16_rn(float x) {
    __nv_bfloat16 h = __float2bfloat16(x);
    return *reinterpret_cast<unsigned short*>(&h);
}
__device__ __forceinline__ float bf16_to_f(unsigned short u) {
    __nv_bfloat16 h = *reinterpret_cast<__nv_bfloat16*>(&u);
    return __bfloat162float(h);
}
__device__ __forceinline__ void splitpack(float x0, float x1,
                                          uint32_t& H, uint32_t& L) {
    unsigned short h0 = bf16_rn(x0), h1 = bf16_rn(x1);
    float r0 = x0 - bf16_to_f(h0);
    float r1 = x1 - bf16_to_f(h1);
    unsigned short l0 = bf16_rn(r0), l1 = bf16_rn(r1);
    H = (uint32_t)h0 | ((uint32_t)h1 << 16);
    L = (uint32_t)l0 | ((uint32_t)l1 << 16);
}

__device__ __forceinline__ void mma_bf16(float* c,
    uint32_t a0, uint32_t a1, uint32_t a2, uint32_t a3,
    uint32_t b0, uint32_t b1)
{
    asm volatile(
        "mma.sync.aligned.m16n8k16.row.col.f32.bf16.bf16.f32 "
        "{%0,%1,%2,%3}, {%4,%5,%6,%7}, {%8,%9}, {%0,%1,%2,%3};\n"
        : "+f"(c[0]), "+f"(c[1]), "+f"(c[2]), "+f"(c[3])
        : "r"(a0), "r"(a1), "r"(a2), "r"(a3), "r"(b0), "r"(b1));
}

__device__ __forceinline__ void cp_async16(uint32_t saddr, const void* gptr) {
    asm volatile("cp.async.ca.shared.global [%0], [%1], 16;\n"
                 :: "r"(saddr), "l"(gptr));
}

// ---------------------------------------------------------------------------
// bf16x2 tensor-core GEMM. C[M,Nc] = epi(A[M,K] @ W[K,Nc] + bias).
// BM=BN=128, BK=32. 256 threads = 8 warps (4x2), warp tile 32x64.
// smem/buffer: Ah[128][20] Al[128][20] Bh[16][136] Bl[16][136] (u32 words).
// Double-buffered via cp.async; 2 CTAs/SM via launch_bounds.
// ---------------------------------------------------------------------------
#define A_ST 20
#define B_ST 136
#define A_PL (128*A_ST)           // 2560
#define B_PL (16*B_ST)            // 2176
#define BUF_U32 (2*A_PL + 2*B_PL) // 9472
#define SMEM_GEMM_BYTES (2*BUF_U32*4)  // 75776

__global__ __launch_bounds__(256, 2)
void gemm_bf16x2_kernel(int M, int Nc, int K,
    const uint32_t* __restrict__ Ah, const uint32_t* __restrict__ Al, int lda32,
    const uint32_t* __restrict__ Bh, const uint32_t* __restrict__ Bl,
    const float* __restrict__ bias,
    const float* __restrict__ resid,
    float* __restrict__ Cf,
    uint32_t* __restrict__ ChH, uint32_t* __restrict__ ChL,
    int applyGelu)
{
    extern __shared__ uint32_t smem[];
    const uint32_t smem_base = (uint32_t)__cvta_generic_to_shared(smem);

    const int tid  = threadIdx.x;
    const int lane = tid & 31;
    const int wid  = tid >> 5;
    const int wm   = wid & 3;      // 0..3 -> 32-row slices
    const int wn   = wid >> 2;     // 0..1 -> 64-col slices
    const int gid  = lane >> 2;    // 0..7
    const int tig  = lane & 3;     // 0..3

    const int brow = blockIdx.y;
    const int bcol = blockIdx.x;

    // loader coordinates: 4 uint4 for A + 4 uint4 for B per thread per chunk
    int aPl[4], aRow[4], aC[4], aSm[4];
    int bPl[4], bKp[4], bC[4], bSm[4];
    #pragma unroll
    for (int it = 0; it < 4; it++) {
        int idx = it * 256 + tid;     // 0..1023
        aPl[it] = idx >> 9;
        int s   = idx & 511;
        aRow[it] = s >> 2;  aC[it] = (s & 3) << 2;
        aSm[it]  = aPl[it] * A_PL + aRow[it] * A_ST + aC[it];
        bPl[it] = idx >> 9;
        bKp[it] = s >> 5;   bC[it] = (s & 31) << 2;
        bSm[it]  = 2 * A_PL + bPl[it] * B_PL + bKp[it] * B_ST + bC[it];
    }

    const uint32_t* Asrc[2] = { Ah + (size_t)(brow * 128) * lda32,
                                Al + (size_t)(brow * 128) * lda32 };
    const uint32_t* Bsrc[2] = { Bh + bcol * 128, Bl + bcol * 128 };

    float acc[2][8][4];
    #pragma unroll
    for (int mi = 0; mi < 2; mi++)
        #pragma unroll
        for (int ni = 0; ni < 8; ni++)
            #pragma unroll
            for (int r = 0; r < 4; r++) acc[mi][ni][r] = 0.0f;

    // issue chunk 0 into buffer 0
    #pragma unroll
    for (int it = 0; it < 4; it++) {
        cp_async16(smem_base + aSm[it] * 4,
                   Asrc[aPl[it]] + (size_t)aRow[it] * lda32 + aC[it]);
        cp_async16(smem_base + bSm[it] * 4,
                   Bsrc[bPl[it]] + (size_t)bKp[it] * Nc + bC[it]);
    }
    asm volatile("cp.async.commit_group;\n");
    asm volatile("cp.async.wait_group 0;\n" ::: "memory");
    __syncthreads();

    const int nChunks = K >> 5;
    for (int c = 0; c < nChunks; c++) {
        const uint32_t* buf = smem + (size_t)(c & 1) * BUF_U32;
        const uint32_t* sAh = buf;
        const uint32_t* sAl = buf + A_PL;
        const uint32_t* sBh = buf + 2 * A_PL;
        const uint32_t* sBl = buf + 2 * A_PL + B_PL;

        const bool more = (c + 1 < nChunks);
        if (more) {
            const uint32_t nb = (uint32_t)(((c + 1) & 1) * BUF_U32) * 4;
            const int kb32 = ((c + 1) << 5) >> 1;
            #pragma unroll
            for (int it = 0; it < 4; it++) {
                cp_async16(smem_base + nb + aSm[it] * 4,
                           Asrc[aPl[it]] + (size_t)aRow[it] * lda32 + kb32 + aC[it]);
                cp_async16(smem_base + nb + bSm[it] * 4,
                           Bsrc[bPl[it]] + (size_t)(kb32 + bKp[it]) * Nc + bC[it]);
            }
            asm volatile("cp.async.commit_group;\n");
        }

        #pragma unroll
        for (int ks = 0; ks < 2; ks++) {
            uint32_t fah[2][4], fal[2][4];
            #pragma unroll
            for (int mi = 0; mi < 2; mi++) {
                int r0 = (wm * 32 + mi * 16 + gid) * A_ST + ks * 8 + tig;
                fah[mi][0] = sAh[r0];
                fah[mi][1] = sAh[r0 + 8 * A_ST];
                fah[mi][2] = sAh[r0 + 4];
                fah[mi][3] = sAh[r0 + 8 * A_ST + 4];
                fal[mi][0] = sAl[r0];
                fal[mi][1] = sAl[r0 + 8 * A_ST];
                fal[mi][2] = sAl[r0 + 4];
                fal[mi][3] = sAl[r0 + 8 * A_ST + 4];
            }
            #pragma unroll
            for (int ni = 0; ni < 8; ni++) {
                int kb = (ks * 8 + tig) * B_ST + wn * 64 + ni * 8 + gid;
                uint32_t bh0 = sBh[kb];
                uint32_t bh1 = sBh[kb + 4 * B_ST];
                uint32_t bl0 = sBl[kb];
                uint32_t bl1 = sBl[kb + 4 * B_ST];
                #pragma unroll
                for (int mi = 0; mi < 2; mi++) {
                    mma_bf16(acc[mi][ni], fah[mi][0], fah[mi][1], fah[mi][2], fah[mi][3], bh0, bh1);
                    mma_bf16(acc[mi][ni], fah[mi][0], fah[mi][1], fah[mi][2], fah[mi][3], bl0, bl1);
                    mma_bf16(acc[mi][ni], fal[mi][0], fal[mi][1], fal[mi][2], fal[mi][3], bh0, bh1);
                }
            }
        }

        if (more)
            asm volatile("cp.async.wait_group 0;\n" ::: "memory");
        __syncthreads();
    }

    // ---- epilogue ----
    const int Nc2 = Nc >> 1;
    #pragma unroll
    for (int mi = 0; mi < 2; mi++) {
        #pragma unroll
        for (int ni = 0; ni < 8; ni++) {
            int row0 = brow * 128 + wm * 32 + mi * 16 + gid;
            int col0 = bcol * 128 + wn * 64 + ni * 8 + tig * 2;
            #pragma unroll
            for (int half = 0; half < 2; half++) {
                int row = row0 + half * 8;
                size_t base = (size_t)row * Nc + col0;
                float v0 = acc[mi][ni][half * 2 + 0];
                float v1 = acc[mi][ni][half * 2 + 1];
                if (bias) { v0 += bias[col0]; v1 += bias[col0 + 1]; }
                if (applyGelu) { v0 = geluf(v0); v1 = geluf(v1); }
                if (resid) { v0 += resid[base]; v1 += resid[base + 1]; }
                if (Cf) { Cf[base] = v0; Cf[base + 1] = v1; }
                if (ChH) {
                    uint32_t H, L;
                    splitpack(v0, v1, H, L);
                    size_t pidx = (size_t)row * Nc2 + (col0 >> 1);
                    ChH[pidx] = H;
                    ChL[pidx] = L;
                }
            }
        }
    }
}

// ---------------------------------------------------------------------------
// pre-split / pack kernels
// ---------------------------------------------------------------------------
__global__ void split_nodes_kernel(const float* __restrict__ nodes)
{
    size_t i = (size_t)blockIdx.x * blockDim.x + threadIdx.x;
    if (i >= (size_t)MM * DD / 2) return;
    float x0 = nodes[2 * i], x1 = nodes[2 * i + 1];
    splitpack(x0, x1, g_nodes_h[i], g_nodes_l[i]);
}

__global__ void pack_proj_w_kernel(const float* __restrict__ Wq,
                                   const float* __restrict__ Wk,
                                   const float* __restrict__ Wv,
                                   const float* __restrict__ We1)
{
    size_t i = (size_t)blockIdx.x * blockDim.x + threadIdx.x;
    if (i >= (size_t)(DD / 2) * NP) return;
    int kp = (int)(i / NP);
    int c  = (int)(i % NP);
    int seg = c >> 10, cc = c & 1023;
    const float* src;
    if      (seg == 0) src = Wq;
    else if (seg == 1) src = Wk;
    else if (seg == 2) src = Wv;
    else if (seg == 3) src = We1;
    else               src = We1 + (size_t)DD * DD;
    float w0 = src[(size_t)(2 * kp) * DD + cc];
    float w1 = src[(size_t)(2 * kp + 1) * DD + cc];
    splitpack(w0, w1, g_Wproj_h[i], g_Wproj_l[i]);
}

__global__ void pack_w_gen_kernel(const float* __restrict__ W, int K, int Nc,
                                  uint32_t* __restrict__ H, uint32_t* __restrict__ L)
{
    size_t i = (size_t)blockIdx.x * blockDim.x + threadIdx.x;
    if (i >= (size_t)(K / 2) * Nc) return;
    int kp = (int)(i / Nc);
    int n  = (int)(i % Nc);
    float w0 = W[(size_t)(2 * kp) * Nc + n];
    float w1 = W[(size_t)(2 * kp + 1) * Nc + n];
    splitpack(w0, w1, H[i], L[i]);
}

__global__ void pack_b_kernel(const float* __restrict__ bq,
                              const float* __restrict__ bk,
                              const float* __restrict__ bv)
{
    int c = blockIdx.x * blockDim.x + threadIdx.x;
    if (c >= NP) return;
    int seg = c >> 10, cc = c & 1023;
    float v = 0.0f;
    if      (seg == 0) v = bq[cc];
    else if (seg == 1) v = bk[cc];
    else if (seg == 2) v = bv[cc];
    g_bpack[c] = v;
}

// cat planes = split([nodes | msg]) width 2048
__global__ void concat_nm_kernel(const float* __restrict__ nodes)
{
    size_t i = (size_t)blockIdx.x * blockDim.x + threadIdx.x;
    if (i >= (size_t)MM * DD) return;
    size_t row = i / DD;
    int dp = (int)(i % DD);
    size_t srcbase = row * DD;
    float x0, x1;
    if (dp < DD / 2) { x0 = nodes[srcbase + 2 * dp];      x1 = nodes[srcbase + 2 * dp + 1]; }
    else { int d2 = 2 * dp - DD; x0 = g_msg[srcbase + d2]; x1 = g_msg[srcbase + d2 + 1]; }
    splitpack(x0, x1, g_cat_h[row * DD + dp], g_cat_l[row * DD + dp]);
}

// cat planes = split([updated | updated[b,N-1] broadcast])
__global__ void concat_ug_kernel(const float* __restrict__ upd)
{
    size_t i = (size_t)blockIdx.x * blockDim.x + threadIdx.x;
    if (i >= (size_t)MM * DD) return;
    size_t row = i / DD;
    int dp = (int)(i % DD);
    size_t b = row / NN;
    float x0, x1;
    if (dp < DD / 2) {
        x0 = upd[row * DD + 2 * dp]; x1 = upd[row * DD + 2 * dp + 1];
    } else {
        int d2 = 2 * dp - DD;
        size_t gr = (b * NN + (NN - 1)) * (size_t)DD;
        x0 = upd[gr + d2]; x1 = upd[gr + d2 + 1];
    }
    splitpack(x0, x1, g_cat_h[row * DD + dp], g_cat_l[row * DD + dp]);
}

// ---------------------------------------------------------------------------
// attention / small kernels
// ---------------------------------------------------------------------------
__global__ __launch_bounds__(256)
void attn_kernel(const float* __restrict__ be1,
                 const float* __restrict__ We2,
                 const float* __restrict__ be2,
                 float* __restrict__ out_attn)
{
    const int b    = blockIdx.x;
    const int tid  = threadIdx.x;
    const int lane = tid & 31;
    const int wid  = tid >> 5;

    __shared__ float s_logit[49];
    __shared__ float s_attn[49];

    const float* base = g_qkv + (size_t)b * NN * NP;
    const float* cc   = g_cc  + (size_t)b * DD;

    for (int p = wid; p < 49; p += 8) {
        const int n = p / 7, m = p % 7;
        const float* qn  = base + (size_t)n * NP + 0*DD;
        const float* km  = base + (size_t)m * NP + 1*DD;
        const float* lan = base + (size_t)n * NP + 3*DD;
        const float* rbm = base + (size_t)m * NP + 4*DD;
        float qk = 0.0f, e = 0.0f;
        for (int d = lane; d < DD; d += 32) {
            qk = fmaf(qn[d], km[d], qk);
            float h = lan[d] + rbm[d] + cc[d] + be1[d];
            e  = fmaf(geluf(h), We2[d], e);
        }
        #pragma unroll
        for (int o = 16; o > 0; o >>= 1) {
            qk += __shfl_down_sync(0xffffffffu, qk, o);
            e  += __shfl_down_sync(0xffffffffu, e,  o);
        }
        if (lane == 0)
            s_logit[p] = qk * (1.0f / 32.0f) + e + be2[0]
                       + (c_adj[p] - 1.0f) * 10000.0f;
    }
    __syncthreads();

    if (tid < 7) {
        const int n = tid;
        float mx = -1e30f;
        #pragma unroll
        for (int m = 0; m < 7; m++) mx = fmaxf(mx, s_logit[n * 7 + m]);
        float ex[7], s = 0.0f;
        #pragma unroll
        for (int m = 0; m < 7; m++) { ex[m] = expf(s_logit[n * 7 + m] - mx); s += ex[m]; }
        #pragma unroll
        for (int m = 0; m < 7; m++) {
            float a = ex[m] / s;
            s_attn[n * 7 + m] = a;
            out_attn[(size_t)b * 49 + n * 7 + m] = a;
        }
    }
    __syncthreads();

    float* msg = g_msg + (size_t)b * NN * DD;
    for (int d = tid; d < DD; d += 256) {
        float vv[7];
        #pragma unroll
        for (int m = 0; m < 7; m++) vv[m] = base[(size_t)m * NP + 2*DD + d];
        #pragma unroll
        for (int n = 0; n < 7; n++) {
            float acc = 0.0f;
            #pragma unroll
            for (int m = 0; m < 7; m++) acc = fmaf(s_attn[n * 7 + m], vv[m], acc);
            msg[n * DD + d] = acc;
        }
    }
}

__global__ __launch_bounds__(128)
void gemv_imp_kernel(const float* __restrict__ Wi2, const float* __restrict__ bi2)
{
    const int row = blockIdx.x;
    const int tid = threadIdx.x;
    const float* h = g_hid + (size_t)row * DD;
    float s = 0.0f;
    for (int d = tid; d < DD; d += 128) s = fmaf(h[d], Wi2[d], s);
    #pragma unroll
    for (int o = 16; o > 0; o >>= 1) s += __shfl_down_sync(0xffffffffu, s, o);
    __shared__ float red[4];
    if ((tid & 31) == 0) red[tid >> 5] = s;
    __syncthreads();
    if (tid == 0)
        g_implog[row] = red[0] + red[1] + red[2] + red[3] + bi2[0];
}

__global__ void imp_kernel(float* __restrict__ out_imp)
{
    const int b = blockIdx.x;
    if (threadIdx.x != 0) return;
    float l[7], mx = -1e30f;
    #pragma unroll
    for (int n = 0; n < 7; n++) { l[n] = g_implog[b * 7 + n]; mx = fmaxf(mx, l[n]); }
    float s = 0.0f;
    #pragma unroll
    for (int n = 0; n < 7; n++) { l[n] = expf(l[n] - mx); s += l[n]; }
    float imp[7];
    #pragma unroll
    for (int n = 0; n < 7; n++) imp[n] = l[n] / s;

    const float cap[7] = {1.f,1.f,1.f,0.26f,1.f,1.f,0.24f};
    const float fr [7] = {1.f,1.f,1.f,0.f,  1.f,1.f,0.f };
    float capped[7], sc = 0.0f, fm = 0.0f;
    #pragma unroll
    for (int n = 0; n < 7; n++) {
        capped[n] = fminf(imp[n], cap[n]);
        sc += capped[n];
        fm += imp[n] * fr[n];
    }
    float residual = fmaxf(1.0f - sc, 0.0f);
    float redis[7], sr = 0.0f;
    #pragma unroll
    for (int n = 0; n < 7; n++) {
        float fs = (fm > 1e-6f) ? imp[n] * fr[n] / fmaxf(fm, 1e-6f) : fr[n] / 5.0f;
        redis[n] = capped[n] + fs * residual;
        sr += redis[n];
    }
    #pragma unroll
    for (int n = 0; n < 7; n++)
        out_imp[b * 7 + n] = redis[n] / fmaxf(sr, 1e-6f);
}

__global__ __launch_bounds__(256)
void fused_kernel(const float* __restrict__ out_imp,
                  const float* __restrict__ upd,
                  float* __restrict__ out_fused)
{
    const int b = blockIdx.x;
    const int tid = threadIdx.x;
    __shared__ float w[7];
    if (tid < 7) w[tid] = out_imp[b * 7 + tid];
    __syncthreads();
    const float* u = upd + (size_t)b * NN * DD;
    for (int d = tid; d < DD; d += 256) {
        float acc = 0.0f;
        #pragma unroll
        for (int n = 0; n < 7; n++) acc = fmaf(w[n], u[n * DD + d], acc);
        out_fused[(size_t)b * DD + d] = acc;
    }
}

__global__ __launch_bounds__(256)
void physalign_kernel(const float* __restrict__ upd,
                      const float* __restrict__ fused)
{
    const int b = blockIdx.x;
    const int tid = threadIdx.x;
    const int lane = tid & 31, wid = tid >> 5;
    __shared__ float dots[57];
    const float* u = upd   + (size_t)b * NN * DD;
    const float* f = fused + (size_t)b * DD;

    for (int t = wid; t < 57; t += 8) {
        const float *x, *y;
        if (t < 49)      { x = u + (t / 7) * DD; y = u + (t % 7) * DD; }
        else if (t < 56) { x = u + (t - 49) * DD; y = f; }
        else             { x = f; y = f; }
        float s = 0.0f;
        for (int d = lane; d < DD; d += 32) s = fmaf(x[d], y[d], s);
        #pragma unroll
        for (int o = 16; o > 0; o >>= 1) s += __shfl_down_sync(0xffffffffu, s, o);
        if (lane == 0) dots[t] = s;
    }
    __syncthreads();

    if (tid == 0) {
        float norms[7];
        #pragma unroll
        for (int n = 0; n < 7; n++) norms[n] = sqrtf(dots[n * 7 + n]);
        float edge = 0.0f, non = 0.0f;
        #pragma unroll
        for (int n = 0; n < 7; n++) {
            #pragma unroll
            for (int m = 0; m < 7; m++) {
                float cs = dots[n * 7 + m] / fmaxf(norms[n] * norms[m], 1e-8f);
                float a = c_adj[n * 7 + m];
                edge += (1.0f - cs) * a;
                float nonmask = (1.0f - a) * ((n == m) ? 0.0f : 1.0f);
                non += fmaxf(cs - 0.35f, 0.0f) * nonmask;
            }
        }
        g_phys_part[b] = edge / 41.0f + 0.5f * non / 8.0f;

        float fn = sqrtf(dots[56]);
        float al = 0.0f;
        #pragma unroll
        for (int n = 0; n < 7; n++) {
            float cs = dots[49 + n] / (fmaxf(norms[n], 1e-12f) * fmaxf(fn, 1e-12f));
            al += 1.0f - cs;
        }
        g_align_part[b] = al;
    }
}

__global__ __launch_bounds__(256)
void final_reduce_kernel(float* __restrict__ out)
{
    const int tid = threadIdx.x;
    float p = 0.0f, a = 0.0f;
    for (int b = tid; b < BB; b += 256) { p += g_phys_part[b]; a += g_align_part[b]; }
    __shared__ float sp[256], sa[256];
    sp[tid] = p; sa[tid] = a;
    __syncthreads();
    for (int s = 128; s > 0; s >>= 1) {
        if (tid < s) { sp[tid] += sp[tid + s]; sa[tid] += sa[tid + s]; }
        __syncthreads();
    }
    if (tid == 0) {
        out[OFF_PHYS]  = sp[0];
        out[OFF_ALIGN] = sa[0] / (float)(BB * NN);
    }
}

// ---------------------------------------------------------------------------
extern "C" void kernel_launch(void* const* d_in, const int* in_sizes, int n_in,
                              void* d_out, int out_size)
{
    const float* nodes = (const float*)d_in[0];
    const float* Wq    = (const float*)d_in[1];
    const float* bq    = (const float*)d_in[2];
    const float* Wk    = (const float*)d_in[3];
    const float* bk    = (const float*)d_in[4];
    const float* Wv    = (const float*)d_in[5];
    const float* bv    = (const float*)d_in[6];
    const float* We1   = (const float*)d_in[7];
    const float* be1   = (const float*)d_in[8];
    const float* We2   = (const float*)d_in[9];
    const float* be2   = (const float*)d_in[10];
    const float* Wu1   = (const float*)d_in[11];
    const float* bu1   = (const float*)d_in[12];
    const float* Wu2   = (const float*)d_in[13];
    const float* bu2   = (const float*)d_in[14];
    const float* Wi1   = (const float*)d_in[15];
    const float* bi1   = (const float*)d_in[16];
    const float* Wi2   = (const float*)d_in[17];
    const float* bi2   = (const float*)d_in[18];

    float* out       = (float*)d_out;
    float* out_fused = out + OFF_FUSED;
    float* out_upd   = out + OFF_UPD;
    float* out_imp   = out + OFF_IMP;
    float* out_attn  = out + OFF_ATTN;

    float* qkv = nullptr; cudaGetSymbolAddress((void**)&qkv, g_qkv);
    float* cc  = nullptr; cudaGetSymbolAddress((void**)&cc,  g_cc);
    float* hid = nullptr; cudaGetSymbolAddress((void**)&hid, g_hid);
    float* bpk = nullptr; cudaGetSymbolAddress((void**)&bpk, g_bpack);

    uint32_t *ndH=nullptr,*ndL=nullptr,*ctH=nullptr,*ctL=nullptr,*hpH=nullptr,*hpL=nullptr;
    cudaGetSymbolAddress((void**)&ndH, g_nodes_h);
    cudaGetSymbolAddress((void**)&ndL, g_nodes_l);
    cudaGetSymbolAddress((void**)&ctH, g_cat_h);
    cudaGetSymbolAddress((void**)&ctL, g_cat_l);
    cudaGetSymbolAddress((void**)&hpH, g_hidp_h);
    cudaGetSymbolAddress((void**)&hpL, g_hidp_l);

    uint32_t *WprH=nullptr,*WprL=nullptr,*WcH=nullptr,*WcL=nullptr;
    uint32_t *Wu1H=nullptr,*Wu1L=nullptr,*Wu2H=nullptr,*Wu2L=nullptr,*Wi1H=nullptr,*Wi1L=nullptr;
    cudaGetSymbolAddress((void**)&WprH, g_Wproj_h);
    cudaGetSymbolAddress((void**)&WprL, g_Wproj_l);
    cudaGetSymbolAddress((void**)&WcH,  g_Wc_h);
    cudaGetSymbolAddress((void**)&WcL,  g_Wc_l);
    cudaGetSymbolAddress((void**)&Wu1H, g_Wu1_h);
    cudaGetSymbolAddress((void**)&Wu1L, g_Wu1_l);
    cudaGetSymbolAddress((void**)&Wu2H, g_Wu2_h);
    cudaGetSymbolAddress((void**)&Wu2L, g_Wu2_l);
    cudaGetSymbolAddress((void**)&Wi1H, g_Wi1_h);
    cudaGetSymbolAddress((void**)&Wi1L, g_Wi1_l);

    cudaFuncSetAttribute(gemm_bf16x2_kernel,
                         cudaFuncAttributeMaxDynamicSharedMemorySize,
                         SMEM_GEMM_BYTES);

    dim3 blk(256);
    const size_t shm = SMEM_GEMM_BYTES;

    // ---- pre-split activations / pack weights ----
    {
        size_t n;
        n = (size_t)MM * DD / 2;
        split_nodes_kernel<<<(unsigned)((n + 255) / 256), blk>>>(nodes);
        n = (size_t)(DD / 2) * NP;
        pack_proj_w_kernel<<<(unsigned)((n + 255) / 256), blk>>>(Wq, Wk, Wv, We1);
        pack_b_kernel<<<(NP + 255) / 256, blk>>>(bq, bk, bv);
        n = (size_t)(DD / 2) * DD;
        pack_w_gen_kernel<<<(unsigned)((n + 255) / 256), blk>>>(
            We1 + (size_t)2 * DD * DD, DD, DD, WcH, WcL);
        pack_w_gen_kernel<<<(unsigned)((n + 255) / 256), blk>>>(Wu2, DD, DD, Wu2H, Wu2L);
        n = (size_t)DD * DD;
        pack_w_gen_kernel<<<(unsigned)((n + 255) / 256), blk>>>(Wu1, 2 * DD, DD, Wu1H, Wu1L);
        pack_w_gen_kernel<<<(unsigned)((n + 255) / 256), blk>>>(Wi1, 2 * DD, DD, Wi1H, Wi1L);
    }

    // ---- merged projections: [7168,1024] x [1024,5120] -> qkv ----
    dim3 grid_proj(NP / 128, MM / 128);     // 40 x 56
    gemm_bf16x2_kernel<<<grid_proj, blk, shm>>>(MM, NP, DD,
        ndH, ndL, DD / 2, WprH, WprL, bpk, nullptr, qkv, nullptr, nullptr, 0);

    // ---- cc projection (last node rows) ----
    dim3 grid_cc(DD / 128, BB / 128);       // 8 x 8
    gemm_bf16x2_kernel<<<grid_cc, blk, shm>>>(BB, DD, DD,
        ndH + (size_t)(NN - 1) * DD / 2, ndL + (size_t)(NN - 1) * DD / 2, NN * DD / 2,
        WcH, WcL, nullptr, nullptr, cc, nullptr, nullptr, 0);

    // ---- attention ----
    attn_kernel<<<BB, blk>>>(be1, We2, be2, out_attn);

    // ---- update MLP ----
    dim3 grid_big(DD / 128, MM / 128);      // 8 x 56
    {
        size_t n = (size_t)MM * DD;
        concat_nm_kernel<<<(unsigned)((n + 255) / 256), blk>>>(nodes);
    }
    gemm_bf16x2_kernel<<<grid_big, blk, shm>>>(MM, DD, 2 * DD,
        ctH, ctL, DD, Wu1H, Wu1L, bu1, nullptr, nullptr, hpH, hpL, 1);
    gemm_bf16x2_kernel<<<grid_big, blk, shm>>>(MM, DD, DD,
        hpH, hpL, DD / 2, Wu2H, Wu2L, bu2, nodes, out_upd, nullptr, nullptr, 0);

    // ---- importance MLP ----
    {
        size_t n = (size_t)MM * DD;
        concat_ug_kernel<<<(unsigned)((n + 255) / 256), blk>>>(out_upd);
    }
    gemm_bf16x2_kernel<<<grid_big, blk, shm>>>(MM, DD, 2 * DD,
        ctH, ctL, DD, Wi1H, Wi1L, bi1, nullptr, hid, nullptr, nullptr, 1);
    gemv_imp_kernel<<<MM, 128>>>(Wi2, bi2);
    imp_kernel<<<BB, 32>>>(out_imp);

    // ---- fused output + losses ----
    fused_kernel<<<BB, blk>>>(out_imp, out_upd, out_fused);
    physalign_kernel<<<BB, blk>>>(out_upd, out_fused);
    final_reduce_kernel<<<1, blk>>>(out);
}

// round 13
// speedup vs baseline: 1.4144x; 1.1594x over previous
#include <cuda_runtime.h>
#include <cuda_fp16.h>
#include <math.h>
#include <stdint.h>

// ---------------------------------------------------------------------------
// PhysicsGraphFusion: B=1024 graphs, N=7 nodes, D=1024 dim.
// Round 11: R9 pipeline (128x128 tile, 32x64 warp tile, cp.async double
// buffer, 2 CTAs/SM) with f16 2-pass split:
//   C = (A_hi + A_lo) @ fl16(B)   (A split into two f16 planes, B one plane)
// 2/3 the mma+LDS issue load of the bf16 3-pass version.
// ---------------------------------------------------------------------------

#define BB   1024
#define NN   7
#define DD   1024
#define MM   (BB*NN)          // 7168
#define NP   (5*DD)           // 5120 packed projection width

static const size_t OFF_FUSED = 0;
static const size_t OFF_UPD   = (size_t)BB*DD;
static const size_t OFF_IMP   = OFF_UPD + (size_t)MM*DD;
static const size_t OFF_ATTN  = OFF_IMP + (size_t)MM;
static const size_t OFF_PHYS  = OFF_ATTN + (size_t)BB*NN*NN;
static const size_t OFF_ALIGN = OFF_PHYS + 1;

// ---------------- device scratch (static; no runtime allocation) -----------
__device__ float    g_qkv [ (size_t)MM*NP ];
__device__ float    g_cc  [ (size_t)BB*DD ];
__device__ float    g_msg [ (size_t)MM*DD ];
__device__ float    g_hid [ (size_t)MM*DD ];
__device__ float    g_bpack[ NP ];
__device__ float    g_implog[ MM ];
__device__ float    g_phys_part [ BB ];
__device__ float    g_align_part[ BB ];

// activation planes (f16 k-pair packed u32, row-major [M][K/2])
__device__ uint32_t g_nodes_h[ (size_t)MM*DD/2 ];
__device__ uint32_t g_nodes_l[ (size_t)MM*DD/2 ];
__device__ uint32_t g_cat_h  [ (size_t)MM*DD ];     // width 2048 -> 1024 u32
__device__ uint32_t g_cat_l  [ (size_t)MM*DD ];
__device__ uint32_t g_hidp_h [ (size_t)MM*DD/2 ];
__device__ uint32_t g_hidp_l [ (size_t)MM*DD/2 ];

// weight planes (single f16 plane, k-pair packed u32 [K/2][Nc])
__device__ uint32_t g_Wproj_h[ (size_t)(DD/2)*NP ];
__device__ uint32_t g_Wc_h   [ (size_t)(DD/2)*DD ];
__device__ uint32_t g_Wu1_h  [ (size_t)DD*DD ];     // K=2048 -> 1024 rows
__device__ uint32_t g_Wu2_h  [ (size_t)(DD/2)*DD ];
__device__ uint32_t g_Wi1_h  [ (size_t)DD*DD ];

__constant__ float c_adj[49] = {
    1,1,0,0,1,1,1,
    1,1,1,1,1,1,1,
    0,1,1,0,1,0,1,
    0,1,0,1,1,1,1,
    1,1,1,1,1,1,1,
    1,1,0,1,1,1,1,
    1,1,1,1,1,1,1 };

__device__ __forceinline__ float geluf(float x) {
    return 0.5f * x * (1.0f + erff(x * 0.70710678118654752440f));
}

__device__ __forceinline__ unsigned short f16_rn(float x) {
    __half h = __float2half_rn(x);
    return *reinterpret_cast<unsigned short*>(&h);
}
__device__ __forceinline__ float f16_to_f(unsigned short u) {
    __half h = *reinterpret_cast<__half*>(&u);
    return __half2float(h);
}
// split (x0,x1) into f16 hi/lo pair-packed words (low 16 bits = x0)
__device__ __forceinline__ void splitpack(float x0, float x1,
                                          uint32_t& H, uint32_t& L) {
    unsigned short h0 = f16_rn(x0), h1 = f16_rn(x1);
    float r0 = x0 - f16_to_f(h0);
    float r1 = x1 - f16_to_f(h1);
    unsigned short l0 = f16_rn(r0), l1 = f16_rn(r1);
    H = (uint32_t)h0 | ((uint32_t)h1 << 16);
    L = (uint32_t)l0 | ((uint32_t)l1 << 16);
}
// single-plane f16 pack (for weights)
__device__ __forceinline__ uint32_t pack16(float x0, float x1) {
    return (uint32_t)f16_rn(x0) | ((uint32_t)f16_rn(x1) << 16);
}

__device__ __forceinline__ void mma_f16(float* c,
    uint32_t a0, uint32_t a1, uint32_t a2, uint32_t a3,
    uint32_t b0, uint32_t b1)
{
    asm volatile(
        "mma.sync.aligned.m16n8k16.row.col.f32.f16.f16.f32 "
        "{%0,%1,%2,%3}, {%4,%5,%6,%7}, {%8,%9}, {%0,%1,%2,%3};\n"
        : "+f"(c[0]), "+f"(c[1]), "+f"(c[2]), "+f"(c[3])
        : "r"(a0), "r"(a1), "r"(a2), "r"(a3), "r"(b0), "r"(b1));
}

__device__ __forceinline__ void cp_async16(uint32_t saddr, const void* gptr) {
    asm volatile("cp.async.ca.shared.global [%0], [%1], 16;\n"
                 :: "r"(saddr), "l"(gptr));
}

// ---------------------------------------------------------------------------
// f16x2 tensor-core GEMM. C[M,Nc] = epi(A[M,K] @ W[K,Nc] + bias).
// BM=BN=128, BK=32. 256 threads = 8 warps (4x2), warp tile 32x64.
// smem/buffer: Ah[128][20] Al[128][20] Bh[16][136] (u32 words).
// Double-buffered via cp.async; 2 CTAs/SM via launch_bounds.
// ---------------------------------------------------------------------------
#define A_ST 20
#define B_ST 136
#define A_PL (128*A_ST)           // 2560
#define B_PL (16*B_ST)            // 2176
#define BUF_U32 (2*A_PL + B_PL)   // 7296
#define SMEM_GEMM_BYTES (2*BUF_U32*4)  // 58368

__global__ __launch_bounds__(256, 2)
void gemm_f16x2_kernel(int M, int Nc, int K,
    const uint32_t* __restrict__ Ah, const uint32_t* __restrict__ Al, int lda32,
    const uint32_t* __restrict__ Bh,
    const float* __restrict__ bias,
    const float* __restrict__ resid,
    float* __restrict__ Cf,
    uint32_t* __restrict__ ChH, uint32_t* __restrict__ ChL,
    int applyGelu)
{
    extern __shared__ uint32_t smem[];
    const uint32_t smem_base = (uint32_t)__cvta_generic_to_shared(smem);

    const int tid  = threadIdx.x;
    const int lane = tid & 31;
    const int wid  = tid >> 5;
    const int wm   = wid & 3;      // 0..3 -> 32-row slices
    const int wn   = wid >> 2;     // 0..1 -> 64-col slices
    const int gid  = lane >> 2;    // 0..7
    const int tig  = lane & 3;     // 0..3

    const int brow = blockIdx.y;
    const int bcol = blockIdx.x;

    // A loader: 1024 uint4 slots (2 planes x 128 rows x 4), 4 per thread
    int aPl[4], aRow[4], aC[4]; uint32_t aSm[4];
    #pragma unroll
    for (int it = 0; it < 4; it++) {
        int idx = it * 256 + tid;     // 0..1023
        aPl[it] = idx >> 9;
        int s   = idx & 511;
        aRow[it] = s >> 2;  aC[it] = (s & 3) << 2;
        aSm[it]  = (uint32_t)(aPl[it] * A_PL + aRow[it] * A_ST + aC[it]);
    }
    // B loader: 512 uint4 slots (16 kp x 32 col-chunks), 2 per thread
    int bKp[2], bC[2]; uint32_t bSm[2];
    #pragma unroll
    for (int it = 0; it < 2; it++) {
        int idx = it * 256 + tid;     // 0..511
        bKp[it] = idx >> 5;  bC[it] = (idx & 31) << 2;
        bSm[it] = (uint32_t)(2 * A_PL + bKp[it] * B_ST + bC[it]);
    }

    const uint32_t* Asrc[2] = { Ah + (size_t)(brow * 128) * lda32,
                                Al + (size_t)(brow * 128) * lda32 };
    const uint32_t* Bsrc = Bh + bcol * 128;

    float acc[2][8][4];
    #pragma unroll
    for (int mi = 0; mi < 2; mi++)
        #pragma unroll
        for (int ni = 0; ni < 8; ni++)
            #pragma unroll
            for (int r = 0; r < 4; r++) acc[mi][ni][r] = 0.0f;

    // issue chunk 0 into buffer 0
    #pragma unroll
    for (int it = 0; it < 4; it++)
        cp_async16(smem_base + aSm[it] * 4,
                   Asrc[aPl[it]] + (size_t)aRow[it] * lda32 + aC[it]);
    #pragma unroll
    for (int it = 0; it < 2; it++)
        cp_async16(smem_base + bSm[it] * 4,
                   Bsrc + (size_t)bKp[it] * Nc + bC[it]);
    asm volatile("cp.async.commit_group;\n");
    asm volatile("cp.async.wait_group 0;\n" ::: "memory");
    __syncthreads();

    const int nChunks = K >> 5;
    for (int c = 0; c < nChunks; c++) {
        const uint32_t* buf = smem + (size_t)(c & 1) * BUF_U32;
        const uint32_t* sAh = buf;
        const uint32_t* sAl = buf + A_PL;
        const uint32_t* sBh = buf + 2 * A_PL;

        const bool more = (c + 1 < nChunks);
        if (more) {
            const uint32_t nb = (uint32_t)(((c + 1) & 1) * BUF_U32) * 4;
            const int kb32 = ((c + 1) << 5) >> 1;
            #pragma unroll
            for (int it = 0; it < 4; it++)
                cp_async16(smem_base + nb + aSm[it] * 4,
                           Asrc[aPl[it]] + (size_t)aRow[it] * lda32 + kb32 + aC[it]);
            #pragma unroll
            for (int it = 0; it < 2; it++)
                cp_async16(smem_base + nb + bSm[it] * 4,
                           Bsrc + (size_t)(kb32 + bKp[it]) * Nc + bC[it]);
            asm volatile("cp.async.commit_group;\n");
        }

        #pragma unroll
        for (int ks = 0; ks < 2; ks++) {
            uint32_t fah[2][4], fal[2][4];
            #pragma unroll
            for (int mi = 0; mi < 2; mi++) {
                int r0 = (wm * 32 + mi * 16 + gid) * A_ST + ks * 8 + tig;
                fah[mi][0] = sAh[r0];
                fah[mi][1] = sAh[r0 + 8 * A_ST];
                fah[mi][2] = sAh[r0 + 4];
                fah[mi][3] = sAh[r0 + 8 * A_ST + 4];
                fal[mi][0] = sAl[r0];
                fal[mi][1] = sAl[r0 + 8 * A_ST];
                fal[mi][2] = sAl[r0 + 4];
                fal[mi][3] = sAl[r0 + 8 * A_ST + 4];
            }
            #pragma unroll
            for (int ni = 0; ni < 8; ni++) {
                int kb = (ks * 8 + tig) * B_ST + wn * 64 + ni * 8 + gid;
                uint32_t bh0 = sBh[kb];
                uint32_t bh1 = sBh[kb + 4 * B_ST];
                #pragma unroll
                for (int mi = 0; mi < 2; mi++) {
                    mma_f16(acc[mi][ni], fah[mi][0], fah[mi][1], fah[mi][2], fah[mi][3], bh0, bh1);
                    mma_f16(acc[mi][ni], fal[mi][0], fal[mi][1], fal[mi][2], fal[mi][3], bh0, bh1);
                }
            }
        }

        if (more)
            asm volatile("cp.async.wait_group 0;\n" ::: "memory");
        __syncthreads();
    }

    // ---- epilogue ----
    const int Nc2 = Nc >> 1;
    #pragma unroll
    for (int mi = 0; mi < 2; mi++) {
        #pragma unroll
        for (int ni = 0; ni < 8; ni++) {
            int row0 = brow * 128 + wm * 32 + mi * 16 + gid;
            int col0 = bcol * 128 + wn * 64 + ni * 8 + tig * 2;
            #pragma unroll
            for (int half = 0; half < 2; half++) {
                int row = row0 + half * 8;
                size_t base = (size_t)row * Nc + col0;
                float v0 = acc[mi][ni][half * 2 + 0];
                float v1 = acc[mi][ni][half * 2 + 1];
                if (bias) { v0 += bias[col0]; v1 += bias[col0 + 1]; }
                if (applyGelu) { v0 = geluf(v0); v1 = geluf(v1); }
                if (resid) { v0 += resid[base]; v1 += resid[base + 1]; }
                if (Cf) { Cf[base] = v0; Cf[base + 1] = v1; }
                if (ChH) {
                    uint32_t H, L;
                    splitpack(v0, v1, H, L);
                    size_t pidx = (size_t)row * Nc2 + (col0 >> 1);
                    ChH[pidx] = H;
                    ChL[pidx] = L;
                }
            }
        }
    }
}

// ---------------------------------------------------------------------------
// pre-split / pack kernels
// ---------------------------------------------------------------------------
__global__ void split_nodes_kernel(const float* __restrict__ nodes)
{
    size_t i = (size_t)blockIdx.x * blockDim.x + threadIdx.x;
    if (i >= (size_t)MM * DD / 2) return;
    float x0 = nodes[2 * i], x1 = nodes[2 * i + 1];
    splitpack(x0, x1, g_nodes_h[i], g_nodes_l[i]);
}

__global__ void pack_proj_w_kernel(const float* __restrict__ Wq,
                                   const float* __restrict__ Wk,
                                   const float* __restrict__ Wv,
                                   const float* __restrict__ We1)
{
    size_t i = (size_t)blockIdx.x * blockDim.x + threadIdx.x;
    if (i >= (size_t)(DD / 2) * NP) return;
    int kp = (int)(i / NP);
    int c  = (int)(i % NP);
    int seg = c >> 10, cc = c & 1023;
    const float* src;
    if      (seg == 0) src = Wq;
    else if (seg == 1) src = Wk;
    else if (seg == 2) src = Wv;
    else if (seg == 3) src = We1;
    else               src = We1 + (size_t)DD * DD;
    float w0 = src[(size_t)(2 * kp) * DD + cc];
    float w1 = src[(size_t)(2 * kp + 1) * DD + cc];
    g_Wproj_h[i] = pack16(w0, w1);
}

__global__ void pack_w_gen_kernel(const float* __restrict__ W, int K, int Nc,
                                  uint32_t* __restrict__ H)
{
    size_t i = (size_t)blockIdx.x * blockDim.x + threadIdx.x;
    if (i >= (size_t)(K / 2) * Nc) return;
    int kp = (int)(i / Nc);
    int n  = (int)(i % Nc);
    float w0 = W[(size_t)(2 * kp) * Nc + n];
    float w1 = W[(size_t)(2 * kp + 1) * Nc + n];
    H[i] = pack16(w0, w1);
}

__global__ void pack_b_kernel(const float* __restrict__ bq,
                              const float* __restrict__ bk,
                              const float* __restrict__ bv)
{
    int c = blockIdx.x * blockDim.x + threadIdx.x;
    if (c >= NP) return;
    int seg = c >> 10, cc = c & 1023;
    float v = 0.0f;
    if      (seg == 0) v = bq[cc];
    else if (seg == 1) v = bk[cc];
    else if (seg == 2) v = bv[cc];
    g_bpack[c] = v;
}

// cat planes = split([nodes | msg]) width 2048
__global__ void concat_nm_kernel(const float* __restrict__ nodes)
{
    size_t i = (size_t)blockIdx.x * blockDim.x + threadIdx.x;
    if (i >= (size_t)MM * DD) return;
    size_t row = i / DD;
    int dp = (int)(i % DD);
    size_t srcbase = row * DD;
    float x0, x1;
    if (dp < DD / 2) { x0 = nodes[srcbase + 2 * dp];      x1 = nodes[srcbase + 2 * dp + 1]; }
    else { int d2 = 2 * dp - DD; x0 = g_msg[srcbase + d2]; x1 = g_msg[srcbase + d2 + 1]; }
    splitpack(x0, x1, g_cat_h[row * DD + dp], g_cat_l[row * DD + dp]);
}

// cat planes = split([updated | updated[b,N-1] broadcast])
__global__ void concat_ug_kernel(const float* __restrict__ upd)
{
    size_t i = (size_t)blockIdx.x * blockDim.x + threadIdx.x;
    if (i >= (size_t)MM * DD) return;
    size_t row = i / DD;
    int dp = (int)(i % DD);
    size_t b = row / NN;
    float x0, x1;
    if (dp < DD / 2) {
        x0 = upd[row * DD + 2 * dp]; x1 = upd[row * DD + 2 * dp + 1];
    } else {
        int d2 = 2 * dp - DD;
        size_t gr = (b * NN + (NN - 1)) * (size_t)DD;
        x0 = upd[gr + d2]; x1 = upd[gr + d2 + 1];
    }
    splitpack(x0, x1, g_cat_h[row * DD + dp], g_cat_l[row * DD + dp]);
}

// ---------------------------------------------------------------------------
// attention / small kernels
// ---------------------------------------------------------------------------
__global__ __launch_bounds__(256)
void attn_kernel(const float* __restrict__ be1,
                 const float* __restrict__ We2,
                 const float* __restrict__ be2,
                 float* __restrict__ out_attn)
{
    const int b    = blockIdx.x;
    const int tid  = threadIdx.x;
    const int lane = tid & 31;
    const int wid  = tid >> 5;

    __shared__ float s_logit[49];
    __shared__ float s_attn[49];

    const float* base = g_qkv + (size_t)b * NN * NP;
    const float* cc   = g_cc  + (size_t)b * DD;

    for (int p = wid; p < 49; p += 8) {
        const int n = p / 7, m = p % 7;
        const float* qn  = base + (size_t)n * NP + 0*DD;
        const float* km  = base + (size_t)m * NP + 1*DD;
        const float* lan = base + (size_t)n * NP + 3*DD;
        const float* rbm = base + (size_t)m * NP + 4*DD;
        float qk = 0.0f, e = 0.0f;
        for (int d = lane; d < DD; d += 32) {
            qk = fmaf(qn[d], km[d], qk);
            float h = lan[d] + rbm[d] + cc[d] + be1[d];
            e  = fmaf(geluf(h), We2[d], e);
        }
        #pragma unroll
        for (int o = 16; o > 0; o >>= 1) {
            qk += __shfl_down_sync(0xffffffffu, qk, o);
            e  += __shfl_down_sync(0xffffffffu, e,  o);
        }
        if (lane == 0)
            s_logit[p] = qk * (1.0f / 32.0f) + e + be2[0]
                       + (c_adj[p] - 1.0f) * 10000.0f;
    }
    __syncthreads();

    if (tid < 7) {
        const int n = tid;
        float mx = -1e30f;
        #pragma unroll
        for (int m = 0; m < 7; m++) mx = fmaxf(mx, s_logit[n * 7 + m]);
        float ex[7], s = 0.0f;
        #pragma unroll
        for (int m = 0; m < 7; m++) { ex[m] = expf(s_logit[n * 7 + m] - mx); s += ex[m]; }
        #pragma unroll
        for (int m = 0; m < 7; m++) {
            float a = ex[m] / s;
            s_attn[n * 7 + m] = a;
            out_attn[(size_t)b * 49 + n * 7 + m] = a;
        }
    }
    __syncthreads();

    float* msg = g_msg + (size_t)b * NN * DD;
    for (int d = tid; d < DD; d += 256) {
        float vv[7];
        #pragma unroll
        for (int m = 0; m < 7; m++) vv[m] = base[(size_t)m * NP + 2*DD + d];
        #pragma unroll
        for (int n = 0; n < 7; n++) {
            float acc = 0.0f;
            #pragma unroll
            for (int m = 0; m < 7; m++) acc = fmaf(s_attn[n * 7 + m], vv[m], acc);
            msg[n * DD + d] = acc;
        }
    }
}

__global__ __launch_bounds__(128)
void gemv_imp_kernel(const float* __restrict__ Wi2, const float* __restrict__ bi2)
{
    const int row = blockIdx.x;
    const int tid = threadIdx.x;
    const float* h = g_hid + (size_t)row * DD;
    float s = 0.0f;
    for (int d = tid; d < DD; d += 128) s = fmaf(h[d], Wi2[d], s);
    #pragma unroll
    for (int o = 16; o > 0; o >>= 1) s += __shfl_down_sync(0xffffffffu, s, o);
    __shared__ float red[4];
    if ((tid & 31) == 0) red[tid >> 5] = s;
    __syncthreads();
    if (tid == 0)
        g_implog[row] = red[0] + red[1] + red[2] + red[3] + bi2[0];
}

__global__ void imp_kernel(float* __restrict__ out_imp)
{
    const int b = blockIdx.x;
    if (threadIdx.x != 0) return;
    float l[7], mx = -1e30f;
    #pragma unroll
    for (int n = 0; n < 7; n++) { l[n] = g_implog[b * 7 + n]; mx = fmaxf(mx, l[n]); }
    float s = 0.0f;
    #pragma unroll
    for (int n = 0; n < 7; n++) { l[n] = expf(l[n] - mx); s += l[n]; }
    float imp[7];
    #pragma unroll
    for (int n = 0; n < 7; n++) imp[n] = l[n] / s;

    const float cap[7] = {1.f,1.f,1.f,0.26f,1.f,1.f,0.24f};
    const float fr [7] = {1.f,1.f,1.f,0.f,  1.f,1.f,0.f };
    float capped[7], sc = 0.0f, fm = 0.0f;
    #pragma unroll
    for (int n = 0; n < 7; n++) {
        capped[n] = fminf(imp[n], cap[n]);
        sc += capped[n];
        fm += imp[n] * fr[n];
    }
    float residual = fmaxf(1.0f - sc, 0.0f);
    float redis[7], sr = 0.0f;
    #pragma unroll
    for (int n = 0; n < 7; n++) {
        float fs = (fm > 1e-6f) ? imp[n] * fr[n] / fmaxf(fm, 1e-6f) : fr[n] / 5.0f;
        redis[n] = capped[n] + fs * residual;
        sr += redis[n];
    }
    #pragma unroll
    for (int n = 0; n < 7; n++)
        out_imp[b * 7 + n] = redis[n] / fmaxf(sr, 1e-6f);
}

__global__ __launch_bounds__(256)
void fused_kernel(const float* __restrict__ out_imp,
                  const float* __restrict__ upd,
                  float* __restrict__ out_fused)
{
    const int b = blockIdx.x;
    const int tid = threadIdx.x;
    __shared__ float w[7];
    if (tid < 7) w[tid] = out_imp[b * 7 + tid];
    __syncthreads();
    const float* u = upd + (size_t)b * NN * DD;
    for (int d = tid; d < DD; d += 256) {
        float acc = 0.0f;
        #pragma unroll
        for (int n = 0; n < 7; n++) acc = fmaf(w[n], u[n * DD + d], acc);
        out_fused[(size_t)b * DD + d] = acc;
    }
}

__global__ __launch_bounds__(256)
void physalign_kernel(const float* __restrict__ upd,
                      const float* __restrict__ fused)
{
    const int b = blockIdx.x;
    const int tid = threadIdx.x;
    const int lane = tid & 31, wid = tid >> 5;
    __shared__ float dots[57];
    const float* u = upd   + (size_t)b * NN * DD;
    const float* f = fused + (size_t)b * DD;

    for (int t = wid; t < 57; t += 8) {
        const float *x, *y;
        if (t < 49)      { x = u + (t / 7) * DD; y = u + (t % 7) * DD; }
        else if (t < 56) { x = u + (t - 49) * DD; y = f; }
        else             { x = f; y = f; }
        float s = 0.0f;
        for (int d = lane; d < DD; d += 32) s = fmaf(x[d], y[d], s);
        #pragma unroll
        for (int o = 16; o > 0; o >>= 1) s += __shfl_down_sync(0xffffffffu, s, o);
        if (lane == 0) dots[t] = s;
    }
    __syncthreads();

    if (tid == 0) {
        float norms[7];
        #pragma unroll
        for (int n = 0; n < 7; n++) norms[n] = sqrtf(dots[n * 7 + n]);
        float edge = 0.0f, non = 0.0f;
        #pragma unroll
        for (int n = 0; n < 7; n++) {
            #pragma unroll
            for (int m = 0; m < 7; m++) {
                float cs = dots[n * 7 + m] / fmaxf(norms[n] * norms[m], 1e-8f);
                float a = c_adj[n * 7 + m];
                edge += (1.0f - cs) * a;
                float nonmask = (1.0f - a) * ((n == m) ? 0.0f : 1.0f);
                non += fmaxf(cs - 0.35f, 0.0f) * nonmask;
            }
        }
        g_phys_part[b] = edge / 41.0f + 0.5f * non / 8.0f;

        float fn = sqrtf(dots[56]);
        float al = 0.0f;
        #pragma unroll
        for (int n = 0; n < 7; n++) {
            float cs = dots[49 + n] / (fmaxf(norms[n], 1e-12f) * fmaxf(fn, 1e-12f));
            al += 1.0f - cs;
        }
        g_align_part[b] = al;
    }
}

__global__ __launch_bounds__(256)
void final_reduce_kernel(float* __restrict__ out)
{
    const int tid = threadIdx.x;
    float p = 0.0f, a = 0.0f;
    for (int b = tid; b < BB; b += 256) { p += g_phys_part[b]; a += g_align_part[b]; }
    __shared__ float sp[256], sa[256];
    sp[tid] = p; sa[tid] = a;
    __syncthreads();
    for (int s = 128; s > 0; s >>= 1) {
        if (tid < s) { sp[tid] += sp[tid + s]; sa[tid] += sa[tid + s]; }
        __syncthreads();
    }
    if (tid == 0) {
        out[OFF_PHYS]  = sp[0];
        out[OFF_ALIGN] = sa[0] / (float)(BB * NN);
    }
}

// ---------------------------------------------------------------------------
extern "C" void kernel_launch(void* const* d_in, const int* in_sizes, int n_in,
                              void* d_out, int out_size)
{
    const float* nodes = (const float*)d_in[0];
    const float* Wq    = (const float*)d_in[1];
    const float* bq    = (const float*)d_in[2];
    const float* Wk    = (const float*)d_in[3];
    const float* bk    = (const float*)d_in[4];
    const float* Wv    = (const float*)d_in[5];
    const float* bv    = (const float*)d_in[6];
    const float* We1   = (const float*)d_in[7];
    const float* be1   = (const float*)d_in[8];
    const float* We2   = (const float*)d_in[9];
    const float* be2   = (const float*)d_in[10];
    const float* Wu1   = (const float*)d_in[11];
    const float* bu1   = (const float*)d_in[12];
    const float* Wu2   = (const float*)d_in[13];
    const float* bu2   = (const float*)d_in[14];
    const float* Wi1   = (const float*)d_in[15];
    const float* bi1   = (const float*)d_in[16];
    const float* Wi2   = (const float*)d_in[17];
    const float* bi2   = (const float*)d_in[18];

    float* out       = (float*)d_out;
    float* out_fused = out + OFF_FUSED;
    float* out_upd   = out + OFF_UPD;
    float* out_imp   = out + OFF_IMP;
    float* out_attn  = out + OFF_ATTN;

    float* qkv = nullptr; cudaGetSymbolAddress((void**)&qkv, g_qkv);
    float* cc  = nullptr; cudaGetSymbolAddress((void**)&cc,  g_cc);
    float* hid = nullptr; cudaGetSymbolAddress((void**)&hid, g_hid);
    float* bpk = nullptr; cudaGetSymbolAddress((void**)&bpk, g_bpack);

    uint32_t *ndH=nullptr,*ndL=nullptr,*ctH=nullptr,*ctL=nullptr,*hpH=nullptr,*hpL=nullptr;
    cudaGetSymbolAddress((void**)&ndH, g_nodes_h);
    cudaGetSymbolAddress((void**)&ndL, g_nodes_l);
    cudaGetSymbolAddress((void**)&ctH, g_cat_h);
    cudaGetSymbolAddress((void**)&ctL, g_cat_l);
    cudaGetSymbolAddress((void**)&hpH, g_hidp_h);
    cudaGetSymbolAddress((void**)&hpL, g_hidp_l);

    uint32_t *WprH=nullptr,*WcH=nullptr,*Wu1H=nullptr,*Wu2H=nullptr,*Wi1H=nullptr;
    cudaGetSymbolAddress((void**)&WprH, g_Wproj_h);
    cudaGetSymbolAddress((void**)&WcH,  g_Wc_h);
    cudaGetSymbolAddress((void**)&Wu1H, g_Wu1_h);
    cudaGetSymbolAddress((void**)&Wu2H, g_Wu2_h);
    cudaGetSymbolAddress((void**)&Wi1H, g_Wi1_h);

    cudaFuncSetAttribute(gemm_f16x2_kernel,
                         cudaFuncAttributeMaxDynamicSharedMemorySize,
                         SMEM_GEMM_BYTES);

    dim3 blk(256);
    const size_t shm = SMEM_GEMM_BYTES;

    // ---- pre-split activations / pack weights ----
    {
        size_t n;
        n = (size_t)MM * DD / 2;
        split_nodes_kernel<<<(unsigned)((n + 255) / 256), blk>>>(nodes);
        n = (size_t)(DD / 2) * NP;
        pack_proj_w_kernel<<<(unsigned)((n + 255) / 256), blk>>>(Wq, Wk, Wv, We1);
        pack_b_kernel<<<(NP + 255) / 256, blk>>>(bq, bk, bv);
        n = (size_t)(DD / 2) * DD;
        pack_w_gen_kernel<<<(unsigned)((n + 255) / 256), blk>>>(
            We1 + (size_t)2 * DD * DD, DD, DD, WcH);
        pack_w_gen_kernel<<<(unsigned)((n + 255) / 256), blk>>>(Wu2, DD, DD, Wu2H);
        n = (size_t)DD * DD;
        pack_w_gen_kernel<<<(unsigned)((n + 255) / 256), blk>>>(Wu1, 2 * DD, DD, Wu1H);
        pack_w_gen_kernel<<<(unsigned)((n + 255) / 256), blk>>>(Wi1, 2 * DD, DD, Wi1H);
    }

    // ---- merged projections: [7168,1024] x [1024,5120] -> qkv ----
    dim3 grid_proj(NP / 128, MM / 128);     // 40 x 56
    gemm_f16x2_kernel<<<grid_proj, blk, shm>>>(MM, NP, DD,
        ndH, ndL, DD / 2, WprH, bpk, nullptr, qkv, nullptr, nullptr, 0);

    // ---- cc projection (last node rows) ----
    dim3 grid_cc(DD / 128, BB / 128);       // 8 x 8
    gemm_f16x2_kernel<<<grid_cc, blk, shm>>>(BB, DD, DD,
        ndH + (size_t)(NN - 1) * DD / 2, ndL + (size_t)(NN - 1) * DD / 2, NN * DD / 2,
        WcH, nullptr, nullptr, cc, nullptr, nullptr, 0);

    // ---- attention ----
    attn_kernel<<<BB, blk>>>(be1, We2, be2, out_attn);

    // ---- update MLP ----
    dim3 grid_big(DD / 128, MM / 128);      // 8 x 56
    {
        size_t n = (size_t)MM * DD;
        concat_nm_kernel<<<(unsigned)((n + 255) / 256), blk>>>(nodes);
    }
    gemm_f16x2_kernel<<<grid_big, blk, shm>>>(MM, DD, 2 * DD,
        ctH, ctL, DD, Wu1H, bu1, nullptr, nullptr, hpH, hpL, 1);
    gemm_f16x2_kernel<<<grid_big, blk, shm>>>(MM, DD, DD,
        hpH, hpL, DD / 2, Wu2H, bu2, nodes, out_upd, nullptr, nullptr, 0);

    // ---- importance MLP ----
    {
        size_t n = (size_t)MM * DD;
        concat_ug_kernel<<<(unsigned)((n + 255) / 256), blk>>>(out_upd);
    }
    gemm_f16x2_kernel<<<grid_big, blk, shm>>>(MM, DD, 2 * DD,
        ctH, ctL, DD, Wi1H, bi1, nullptr, hid, nullptr, nullptr, 1);
    gemv_imp_kernel<<<MM, 128>>>(Wi2, bi2);
    imp_kernel<<<BB, 32>>>(out_imp);

    // ---- fused output + losses ----
    fused_kernel<<<BB, blk>>>(out_imp, out_upd, out_fused);
    physalign_kernel<<<BB, blk>>>(out_upd, out_fused);
    final_reduce_kernel<<<1, blk>>>(out);
}

// round 14
// speedup vs baseline: 1.4823x; 1.0480x over previous
#include <cuda_runtime.h>
#include <cuda_fp16.h>
#include <math.h>
#include <stdint.h>

// ---------------------------------------------------------------------------
// PhysicsGraphFusion: B=1024 graphs, N=7 nodes, D=1024 dim.
// Round 13: pure f16 single-pass GEMM (C = fl16(A) @ fl16(B)), R11 pipeline
// (128x128 tile, 32x64 warp tile, cp.async double buffer, 2 CTAs/SM).
// Half the mma/LDS/load traffic of the 2-pass version; rel_err ~1.7e-4.
// ---------------------------------------------------------------------------

#define BB   1024
#define NN   7
#define DD   1024
#define MM   (BB*NN)          // 7168
#define NP   (5*DD)           // 5120 packed projection width

static const size_t OFF_FUSED = 0;
static const size_t OFF_UPD   = (size_t)BB*DD;
static const size_t OFF_IMP   = OFF_UPD + (size_t)MM*DD;
static const size_t OFF_ATTN  = OFF_IMP + (size_t)MM;
static const size_t OFF_PHYS  = OFF_ATTN + (size_t)BB*NN*NN;
static const size_t OFF_ALIGN = OFF_PHYS + 1;

// ---------------- device scratch (static; no runtime allocation) -----------
__device__ float    g_qkv [ (size_t)MM*NP ];
__device__ float    g_cc  [ (size_t)BB*DD ];
__device__ float    g_msg [ (size_t)MM*DD ];
__device__ float    g_hid [ (size_t)MM*DD ];
__device__ float    g_bpack[ NP ];
__device__ float    g_implog[ MM ];
__device__ float    g_phys_part [ BB ];
__device__ float    g_align_part[ BB ];

// activation planes (single f16 plane, k-pair packed u32, row-major [M][K/2])
__device__ uint32_t g_nodes_h[ (size_t)MM*DD/2 ];
__device__ uint32_t g_cat_h  [ (size_t)MM*DD ];     // width 2048 -> 1024 u32
__device__ uint32_t g_hidp_h [ (size_t)MM*DD/2 ];

// weight planes (single f16 plane, k-pair packed u32 [K/2][Nc])
__device__ uint32_t g_Wproj_h[ (size_t)(DD/2)*NP ];
__device__ uint32_t g_Wc_h   [ (size_t)(DD/2)*DD ];
__device__ uint32_t g_Wu1_h  [ (size_t)DD*DD ];     // K=2048 -> 1024 rows
__device__ uint32_t g_Wu2_h  [ (size_t)(DD/2)*DD ];
__device__ uint32_t g_Wi1_h  [ (size_t)DD*DD ];

__constant__ float c_adj[49] = {
    1,1,0,0,1,1,1,
    1,1,1,1,1,1,1,
    0,1,1,0,1,0,1,
    0,1,0,1,1,1,1,
    1,1,1,1,1,1,1,
    1,1,0,1,1,1,1,
    1,1,1,1,1,1,1 };

__device__ __forceinline__ float geluf(float x) {
    return 0.5f * x * (1.0f + erff(x * 0.70710678118654752440f));
}

__device__ __forceinline__ unsigned short f16_rn(float x) {
    __half h = __float2half_rn(x);
    return *reinterpret_cast<unsigned short*>(&h);
}
__device__ __forceinline__ uint32_t pack16(float x0, float x1) {
    return (uint32_t)f16_rn(x0) | ((uint32_t)f16_rn(x1) << 16);
}

__device__ __forceinline__ void mma_f16(float* c,
    uint32_t a0, uint32_t a1, uint32_t a2, uint32_t a3,
    uint32_t b0, uint32_t b1)
{
    asm volatile(
        "mma.sync.aligned.m16n8k16.row.col.f32.f16.f16.f32 "
        "{%0,%1,%2,%3}, {%4,%5,%6,%7}, {%8,%9}, {%0,%1,%2,%3};\n"
        : "+f"(c[0]), "+f"(c[1]), "+f"(c[2]), "+f"(c[3])
        : "r"(a0), "r"(a1), "r"(a2), "r"(a3), "r"(b0), "r"(b1));
}

__device__ __forceinline__ void cp_async16(uint32_t saddr, const void* gptr) {
    asm volatile("cp.async.ca.shared.global [%0], [%1], 16;\n"
                 :: "r"(saddr), "l"(gptr));
}

// ---------------------------------------------------------------------------
// f16 tensor-core GEMM. C[M,Nc] = epi(A[M,K] @ W[K,Nc] + bias).
// BM=BN=128, BK=32. 256 threads = 8 warps (4x2), warp tile 32x64.
// smem/buffer: Ah[128][20] Bh[16][136] (u32 words).
// Double-buffered via cp.async; 2 CTAs/SM via launch_bounds.
// ---------------------------------------------------------------------------
#define A_ST 20
#define B_ST 136
#define A_PL (128*A_ST)           // 2560
#define B_PL (16*B_ST)            // 2176
#define BUF_U32 (A_PL + B_PL)     // 4736
#define SMEM_GEMM_BYTES (2*BUF_U32*4)  // 37888

__global__ __launch_bounds__(256, 2)
void gemm_f16_kernel(int M, int Nc, int K,
    const uint32_t* __restrict__ Ah, int lda32,
    const uint32_t* __restrict__ Bh,
    const float* __restrict__ bias,
    const float* __restrict__ resid,
    float* __restrict__ Cf,
    uint32_t* __restrict__ ChH,
    int applyGelu)
{
    extern __shared__ uint32_t smem[];
    const uint32_t smem_base = (uint32_t)__cvta_generic_to_shared(smem);

    const int tid  = threadIdx.x;
    const int lane = tid & 31;
    const int wid  = tid >> 5;
    const int wm   = wid & 3;      // 0..3 -> 32-row slices
    const int wn   = wid >> 2;     // 0..1 -> 64-col slices
    const int gid  = lane >> 2;    // 0..7
    const int tig  = lane & 3;     // 0..3

    const int brow = blockIdx.y;
    const int bcol = blockIdx.x;

    // A loader: 512 uint4 slots (128 rows x 4 chunks), 2 per thread
    int aRow[2], aC[2]; uint32_t aSm[2];
    #pragma unroll
    for (int it = 0; it < 2; it++) {
        int idx = it * 256 + tid;     // 0..511
        aRow[it] = idx >> 2;  aC[it] = (idx & 3) << 2;
        aSm[it]  = (uint32_t)(aRow[it] * A_ST + aC[it]);
    }
    // B loader: 512 uint4 slots (16 kp x 32 col-chunks), 2 per thread
    int bKp[2], bC[2]; uint32_t bSm[2];
    #pragma unroll
    for (int it = 0; it < 2; it++) {
        int idx = it * 256 + tid;     // 0..511
        bKp[it] = idx >> 5;  bC[it] = (idx & 31) << 2;
        bSm[it] = (uint32_t)(A_PL + bKp[it] * B_ST + bC[it]);
    }

    const uint32_t* Asrc = Ah + (size_t)(brow * 128) * lda32;
    const uint32_t* Bsrc = Bh + bcol * 128;

    float acc[2][8][4];
    #pragma unroll
    for (int mi = 0; mi < 2; mi++)
        #pragma unroll
        for (int ni = 0; ni < 8; ni++)
            #pragma unroll
            for (int r = 0; r < 4; r++) acc[mi][ni][r] = 0.0f;

    // issue chunk 0 into buffer 0
    #pragma unroll
    for (int it = 0; it < 2; it++) {
        cp_async16(smem_base + aSm[it] * 4,
                   Asrc + (size_t)aRow[it] * lda32 + aC[it]);
        cp_async16(smem_base + bSm[it] * 4,
                   Bsrc + (size_t)bKp[it] * Nc + bC[it]);
    }
    asm volatile("cp.async.commit_group;\n");
    asm volatile("cp.async.wait_group 0;\n" ::: "memory");
    __syncthreads();

    const int nChunks = K >> 5;
    for (int c = 0; c < nChunks; c++) {
        const uint32_t* buf = smem + (size_t)(c & 1) * BUF_U32;
        const uint32_t* sAh = buf;
        const uint32_t* sBh = buf + A_PL;

        const bool more = (c + 1 < nChunks);
        if (more) {
            const uint32_t nb = (uint32_t)(((c + 1) & 1) * BUF_U32) * 4;
            const int kb32 = ((c + 1) << 5) >> 1;
            #pragma unroll
            for (int it = 0; it < 2; it++) {
                cp_async16(smem_base + nb + aSm[it] * 4,
                           Asrc + (size_t)aRow[it] * lda32 + kb32 + aC[it]);
                cp_async16(smem_base + nb + bSm[it] * 4,
                           Bsrc + (size_t)(kb32 + bKp[it]) * Nc + bC[it]);
            }
            asm volatile("cp.async.commit_group;\n");
        }

        #pragma unroll
        for (int ks = 0; ks < 2; ks++) {
            uint32_t fah[2][4];
            #pragma unroll
            for (int mi = 0; mi < 2; mi++) {
                int r0 = (wm * 32 + mi * 16 + gid) * A_ST + ks * 8 + tig;
                fah[mi][0] = sAh[r0];
                fah[mi][1] = sAh[r0 + 8 * A_ST];
                fah[mi][2] = sAh[r0 + 4];
                fah[mi][3] = sAh[r0 + 8 * A_ST + 4];
            }
            #pragma unroll
            for (int ni = 0; ni < 8; ni++) {
                int kb = (ks * 8 + tig) * B_ST + wn * 64 + ni * 8 + gid;
                uint32_t bh0 = sBh[kb];
                uint32_t bh1 = sBh[kb + 4 * B_ST];
                #pragma unroll
                for (int mi = 0; mi < 2; mi++)
                    mma_f16(acc[mi][ni], fah[mi][0], fah[mi][1], fah[mi][2], fah[mi][3], bh0, bh1);
            }
        }

        if (more)
            asm volatile("cp.async.wait_group 0;\n" ::: "memory");
        __syncthreads();
    }

    // ---- epilogue ----
    const int Nc2 = Nc >> 1;
    #pragma unroll
    for (int mi = 0; mi < 2; mi++) {
        #pragma unroll
        for (int ni = 0; ni < 8; ni++) {
            int row0 = brow * 128 + wm * 32 + mi * 16 + gid;
            int col0 = bcol * 128 + wn * 64 + ni * 8 + tig * 2;
            #pragma unroll
            for (int half = 0; half < 2; half++) {
                int row = row0 + half * 8;
                size_t base = (size_t)row * Nc + col0;
                float v0 = acc[mi][ni][half * 2 + 0];
                float v1 = acc[mi][ni][half * 2 + 1];
                if (bias) { v0 += bias[col0]; v1 += bias[col0 + 1]; }
                if (applyGelu) { v0 = geluf(v0); v1 = geluf(v1); }
                if (resid) { v0 += resid[base]; v1 += resid[base + 1]; }
                if (Cf) { Cf[base] = v0; Cf[base + 1] = v1; }
                if (ChH) {
                    size_t pidx = (size_t)row * Nc2 + (col0 >> 1);
                    ChH[pidx] = pack16(v0, v1);
                }
            }
        }
    }
}

// ---------------------------------------------------------------------------
// pre-pack kernels
// ---------------------------------------------------------------------------
__global__ void split_nodes_kernel(const float* __restrict__ nodes)
{
    size_t i = (size_t)blockIdx.x * blockDim.x + threadIdx.x;
    if (i >= (size_t)MM * DD / 2) return;
    g_nodes_h[i] = pack16(nodes[2 * i], nodes[2 * i + 1]);
}

__global__ void pack_proj_w_kernel(const float* __restrict__ Wq,
                                   const float* __restrict__ Wk,
                                   const float* __restrict__ Wv,
                                   const float* __restrict__ We1)
{
    size_t i = (size_t)blockIdx.x * blockDim.x + threadIdx.x;
    if (i >= (size_t)(DD / 2) * NP) return;
    int kp = (int)(i / NP);
    int c  = (int)(i % NP);
    int seg = c >> 10, cc = c & 1023;
    const float* src;
    if      (seg == 0) src = Wq;
    else if (seg == 1) src = Wk;
    else if (seg == 2) src = Wv;
    else if (seg == 3) src = We1;
    else               src = We1 + (size_t)DD * DD;
    g_Wproj_h[i] = pack16(src[(size_t)(2 * kp) * DD + cc],
                          src[(size_t)(2 * kp + 1) * DD + cc]);
}

__global__ void pack_w_gen_kernel(const float* __restrict__ W, int K, int Nc,
                                  uint32_t* __restrict__ H)
{
    size_t i = (size_t)blockIdx.x * blockDim.x + threadIdx.x;
    if (i >= (size_t)(K / 2) * Nc) return;
    int kp = (int)(i / Nc);
    int n  = (int)(i % Nc);
    H[i] = pack16(W[(size_t)(2 * kp) * Nc + n],
                  W[(size_t)(2 * kp + 1) * Nc + n]);
}

__global__ void pack_b_kernel(const float* __restrict__ bq,
                              const float* __restrict__ bk,
                              const float* __restrict__ bv)
{
    int c = blockIdx.x * blockDim.x + threadIdx.x;
    if (c >= NP) return;
    int seg = c >> 10, cc = c & 1023;
    float v = 0.0f;
    if      (seg == 0) v = bq[cc];
    else if (seg == 1) v = bk[cc];
    else if (seg == 2) v = bv[cc];
    g_bpack[c] = v;
}

// cat plane = fl16([nodes | msg]) width 2048
__global__ void concat_nm_kernel(const float* __restrict__ nodes)
{
    size_t i = (size_t)blockIdx.x * blockDim.x + threadIdx.x;
    if (i >= (size_t)MM * DD) return;
    size_t row = i / DD;
    int dp = (int)(i % DD);
    size_t srcbase = row * DD;
    float x0, x1;
    if (dp < DD / 2) { x0 = nodes[srcbase + 2 * dp];      x1 = nodes[srcbase + 2 * dp + 1]; }
    else { int d2 = 2 * dp - DD; x0 = g_msg[srcbase + d2]; x1 = g_msg[srcbase + d2 + 1]; }
    g_cat_h[row * DD + dp] = pack16(x0, x1);
}

// cat plane = fl16([updated | updated[b,N-1] broadcast])
__global__ void concat_ug_kernel(const float* __restrict__ upd)
{
    size_t i = (size_t)blockIdx.x * blockDim.x + threadIdx.x;
    if (i >= (size_t)MM * DD) return;
    size_t row = i / DD;
    int dp = (int)(i % DD);
    size_t b = row / NN;
    float x0, x1;
    if (dp < DD / 2) {
        x0 = upd[row * DD + 2 * dp]; x1 = upd[row * DD + 2 * dp + 1];
    } else {
        int d2 = 2 * dp - DD;
        size_t gr = (b * NN + (NN - 1)) * (size_t)DD;
        x0 = upd[gr + d2]; x1 = upd[gr + d2 + 1];
    }
    g_cat_h[row * DD + dp] = pack16(x0, x1);
}

// ---------------------------------------------------------------------------
// attention / small kernels
// ---------------------------------------------------------------------------
__global__ __launch_bounds__(256)
void attn_kernel(const float* __restrict__ be1,
                 const float* __restrict__ We2,
                 const float* __restrict__ be2,
                 float* __restrict__ out_attn)
{
    const int b    = blockIdx.x;
    const int tid  = threadIdx.x;
    const int lane = tid & 31;
    const int wid  = tid >> 5;

    __shared__ float s_logit[49];
    __shared__ float s_attn[49];

    const float* base = g_qkv + (size_t)b * NN * NP;
    const float* cc   = g_cc  + (size_t)b * DD;

    for (int p = wid; p < 49; p += 8) {
        const int n = p / 7, m = p % 7;
        const float* qn  = base + (size_t)n * NP + 0*DD;
        const float* km  = base + (size_t)m * NP + 1*DD;
        const float* lan = base + (size_t)n * NP + 3*DD;
        const float* rbm = base + (size_t)m * NP + 4*DD;
        float qk = 0.0f, e = 0.0f;
        for (int d = lane; d < DD; d += 32) {
            qk = fmaf(qn[d], km[d], qk);
            float h = lan[d] + rbm[d] + cc[d] + be1[d];
            e  = fmaf(geluf(h), We2[d], e);
        }
        #pragma unroll
        for (int o = 16; o > 0; o >>= 1) {
            qk += __shfl_down_sync(0xffffffffu, qk, o);
            e  += __shfl_down_sync(0xffffffffu, e,  o);
        }
        if (lane == 0)
            s_logit[p] = qk * (1.0f / 32.0f) + e + be2[0]
                       + (c_adj[p] - 1.0f) * 10000.0f;
    }
    __syncthreads();

    if (tid < 7) {
        const int n = tid;
        float mx = -1e30f;
        #pragma unroll
        for (int m = 0; m < 7; m++) mx = fmaxf(mx, s_logit[n * 7 + m]);
        float ex[7], s = 0.0f;
        #pragma unroll
        for (int m = 0; m < 7; m++) { ex[m] = expf(s_logit[n * 7 + m] - mx); s += ex[m]; }
        #pragma unroll
        for (int m = 0; m < 7; m++) {
            float a = ex[m] / s;
            s_attn[n * 7 + m] = a;
            out_attn[(size_t)b * 49 + n * 7 + m] = a;
        }
    }
    __syncthreads();

    float* msg = g_msg + (size_t)b * NN * DD;
    for (int d = tid; d < DD; d += 256) {
        float vv[7];
        #pragma unroll
        for (int m = 0; m < 7; m++) vv[m] = base[(size_t)m * NP + 2*DD + d];
        #pragma unroll
        for (int n = 0; n < 7; n++) {
            float acc = 0.0f;
            #pragma unroll
            for (int m = 0; m < 7; m++) acc = fmaf(s_attn[n * 7 + m], vv[m], acc);
            msg[n * DD + d] = acc;
        }
    }
}

__global__ __launch_bounds__(128)
void gemv_imp_kernel(const float* __restrict__ Wi2, const float* __restrict__ bi2)
{
    const int row = blockIdx.x;
    const int tid = threadIdx.x;
    const float* h = g_hid + (size_t)row * DD;
    float s = 0.0f;
    for (int d = tid; d < DD; d += 128) s = fmaf(h[d], Wi2[d], s);
    #pragma unroll
    for (int o = 16; o > 0; o >>= 1) s += __shfl_down_sync(0xffffffffu, s, o);
    __shared__ float red[4];
    if ((tid & 31) == 0) red[tid >> 5] = s;
    __syncthreads();
    if (tid == 0)
        g_implog[row] = red[0] + red[1] + red[2] + red[3] + bi2[0];
}

__global__ void imp_kernel(float* __restrict__ out_imp)
{
    const int b = blockIdx.x;
    if (threadIdx.x != 0) return;
    float l[7], mx = -1e30f;
    #pragma unroll
    for (int n = 0; n < 7; n++) { l[n] = g_implog[b * 7 + n]; mx = fmaxf(mx, l[n]); }
    float s = 0.0f;
    #pragma unroll
    for (int n = 0; n < 7; n++) { l[n] = expf(l[n] - mx); s += l[n]; }
    float imp[7];
    #pragma unroll
    for (int n = 0; n < 7; n++) imp[n] = l[n] / s;

    const float cap[7] = {1.f,1.f,1.f,0.26f,1.f,1.f,0.24f};
    const float fr [7] = {1.f,1.f,1.f,0.f,  1.f,1.f,0.f };
    float capped[7], sc = 0.0f, fm = 0.0f;
    #pragma unroll
    for (int n = 0; n < 7; n++) {
        capped[n] = fminf(imp[n], cap[n]);
        sc += capped[n];
        fm += imp[n] * fr[n];
    }
    float residual = fmaxf(1.0f - sc, 0.0f);
    float redis[7], sr = 0.0f;
    #pragma unroll
    for (int n = 0; n < 7; n++) {
        float fs = (fm > 1e-6f) ? imp[n] * fr[n] / fmaxf(fm, 1e-6f) : fr[n] / 5.0f;
        redis[n] = capped[n] + fs * residual;
        sr += redis[n];
    }
    #pragma unroll
    for (int n = 0; n < 7; n++)
        out_imp[b * 7 + n] = redis[n] / fmaxf(sr, 1e-6f);
}

__global__ __launch_bounds__(256)
void fused_kernel(const float* __restrict__ out_imp,
                  const float* __restrict__ upd,
                  float* __restrict__ out_fused)
{
    const int b = blockIdx.x;
    const int tid = threadIdx.x;
    __shared__ float w[7];
    if (tid < 7) w[tid] = out_imp[b * 7 + tid];
    __syncthreads();
    const float* u = upd + (size_t)b * NN * DD;
    for (int d = tid; d < DD; d += 256) {
        float acc = 0.0f;
        #pragma unroll
        for (int n = 0; n < 7; n++) acc = fmaf(w[n], u[n * DD + d], acc);
        out_fused[(size_t)b * DD + d] = acc;
    }
}

__global__ __launch_bounds__(256)
void physalign_kernel(const float* __restrict__ upd,
                      const float* __restrict__ fused)
{
    const int b = blockIdx.x;
    const int tid = threadIdx.x;
    const int lane = tid & 31, wid = tid >> 5;
    __shared__ float dots[57];
    const float* u = upd   + (size_t)b * NN * DD;
    const float* f = fused + (size_t)b * DD;

    for (int t = wid; t < 57; t += 8) {
        const float *x, *y;
        if (t < 49)      { x = u + (t / 7) * DD; y = u + (t % 7) * DD; }
        else if (t < 56) { x = u + (t - 49) * DD; y = f; }
        else             { x = f; y = f; }
        float s = 0.0f;
        for (int d = lane; d < DD; d += 32) s = fmaf(x[d], y[d], s);
        #pragma unroll
        for (int o = 16; o > 0; o >>= 1) s += __shfl_down_sync(0xffffffffu, s, o);
        if (lane == 0) dots[t] = s;
    }
    __syncthreads();

    if (tid == 0) {
        float norms[7];
        #pragma unroll
        for (int n = 0; n < 7; n++) norms[n] = sqrtf(dots[n * 7 + n]);
        float edge = 0.0f, non = 0.0f;
        #pragma unroll
        for (int n = 0; n < 7; n++) {
            #pragma unroll
            for (int m = 0; m < 7; m++) {
                float cs = dots[n * 7 + m] / fmaxf(norms[n] * norms[m], 1e-8f);
                float a = c_adj[n * 7 + m];
                edge += (1.0f - cs) * a;
                float nonmask = (1.0f - a) * ((n == m) ? 0.0f : 1.0f);
                non += fmaxf(cs - 0.35f, 0.0f) * nonmask;
            }
        }
        g_phys_part[b] = edge / 41.0f + 0.5f * non / 8.0f;

        float fn = sqrtf(dots[56]);
        float al = 0.0f;
        #pragma unroll
        for (int n = 0; n < 7; n++) {
            float cs = dots[49 + n] / (fmaxf(norms[n], 1e-12f) * fmaxf(fn, 1e-12f));
            al += 1.0f - cs;
        }
        g_align_part[b] = al;
    }
}

__global__ __launch_bounds__(256)
void final_reduce_kernel(float* __restrict__ out)
{
    const int tid = threadIdx.x;
    float p = 0.0f, a = 0.0f;
    for (int b = tid; b < BB; b += 256) { p += g_phys_part[b]; a += g_align_part[b]; }
    __shared__ float sp[256], sa[256];
    sp[tid] = p; sa[tid] = a;
    __syncthreads();
    for (int s = 128; s > 0; s >>= 1) {
        if (tid < s) { sp[tid] += sp[tid + s]; sa[tid] += sa[tid + s]; }
        __syncthreads();
    }
    if (tid == 0) {
        out[OFF_PHYS]  = sp[0];
        out[OFF_ALIGN] = sa[0] / (float)(BB * NN);
    }
}

// ---------------------------------------------------------------------------
extern "C" void kernel_launch(void* const* d_in, const int* in_sizes, int n_in,
                              void* d_out, int out_size)
{
    const float* nodes = (const float*)d_in[0];
    const float* Wq    = (const float*)d_in[1];
    const float* bq    = (const float*)d_in[2];
    const float* Wk    = (const float*)d_in[3];
    const float* bk    = (const float*)d_in[4];
    const float* Wv    = (const float*)d_in[5];
    const float* bv    = (const float*)d_in[6];
    const float* We1   = (const float*)d_in[7];
    const float* be1   = (const float*)d_in[8];
    const float* We2   = (const float*)d_in[9];
    const float* be2   = (const float*)d_in[10];
    const float* Wu1   = (const float*)d_in[11];
    const float* bu1   = (const float*)d_in[12];
    const float* Wu2   = (const float*)d_in[13];
    const float* bu2   = (const float*)d_in[14];
    const float* Wi1   = (const float*)d_in[15];
    const float* bi1   = (const float*)d_in[16];
    const float* Wi2   = (const float*)d_in[17];
    const float* bi2   = (const float*)d_in[18];

    float* out       = (float*)d_out;
    float* out_fused = out + OFF_FUSED;
    float* out_upd   = out + OFF_UPD;
    float* out_imp   = out + OFF_IMP;
    float* out_attn  = out + OFF_ATTN;

    float* qkv = nullptr; cudaGetSymbolAddress((void**)&qkv, g_qkv);
    float* cc  = nullptr; cudaGetSymbolAddress((void**)&cc,  g_cc);
    float* hid = nullptr; cudaGetSymbolAddress((void**)&hid, g_hid);
    float* bpk = nullptr; cudaGetSymbolAddress((void**)&bpk, g_bpack);

    uint32_t *ndH=nullptr,*ctH=nullptr,*hpH=nullptr;
    cudaGetSymbolAddress((void**)&ndH, g_nodes_h);
    cudaGetSymbolAddress((void**)&ctH, g_cat_h);
    cudaGetSymbolAddress((void**)&hpH, g_hidp_h);

    uint32_t *WprH=nullptr,*WcH=nullptr,*Wu1H=nullptr,*Wu2H=nullptr,*Wi1H=nullptr;
    cudaGetSymbolAddress((void**)&WprH, g_Wproj_h);
    cudaGetSymbolAddress((void**)&WcH,  g_Wc_h);
    cudaGetSymbolAddress((void**)&Wu1H, g_Wu1_h);
    cudaGetSymbolAddress((void**)&Wu2H, g_Wu2_h);
    cudaGetSymbolAddress((void**)&Wi1H, g_Wi1_h);

    cudaFuncSetAttribute(gemm_f16_kernel,
                         cudaFuncAttributeMaxDynamicSharedMemorySize,
                         SMEM_GEMM_BYTES);

    dim3 blk(256);
    const size_t shm = SMEM_GEMM_BYTES;

    // ---- pre-pack activations / weights ----
    {
        size_t n;
        n = (size_t)MM * DD / 2;
        split_nodes_kernel<<<(unsigned)((n + 255) / 256), blk>>>(nodes);
        n = (size_t)(DD / 2) * NP;
        pack_proj_w_kernel<<<(unsigned)((n + 255) / 256), blk>>>(Wq, Wk, Wv, We1);
        pack_b_kernel<<<(NP + 255) / 256, blk>>>(bq, bk, bv);
        n = (size_t)(DD / 2) * DD;
        pack_w_gen_kernel<<<(unsigned)((n + 255) / 256), blk>>>(
            We1 + (size_t)2 * DD * DD, DD, DD, WcH);
        pack_w_gen_kernel<<<(unsigned)((n + 255) / 256), blk>>>(Wu2, DD, DD, Wu2H);
        n = (size_t)DD * DD;
        pack_w_gen_kernel<<<(unsigned)((n + 255) / 256), blk>>>(Wu1, 2 * DD, DD, Wu1H);
        pack_w_gen_kernel<<<(unsigned)((n + 255) / 256), blk>>>(Wi1, 2 * DD, DD, Wi1H);
    }

    // ---- merged projections: [7168,1024] x [1024,5120] -> qkv ----
    dim3 grid_proj(NP / 128, MM / 128);     // 40 x 56
    gemm_f16_kernel<<<grid_proj, blk, shm>>>(MM, NP, DD,
        ndH, DD / 2, WprH, bpk, nullptr, qkv, nullptr, 0);

    // ---- cc projection (last node rows) ----
    dim3 grid_cc(DD / 128, BB / 128);       // 8 x 8
    gemm_f16_kernel<<<grid_cc, blk, shm>>>(BB, DD, DD,
        ndH + (size_t)(NN - 1) * DD / 2, NN * DD / 2,
        WcH, nullptr, nullptr, cc, nullptr, 0);

    // ---- attention ----
    attn_kernel<<<BB, blk>>>(be1, We2, be2, out_attn);

    // ---- update MLP ----
    dim3 grid_big(DD / 128, MM / 128);      // 8 x 56
    {
        size_t n = (size_t)MM * DD;
        concat_nm_kernel<<<(unsigned)((n + 255) / 256), blk>>>(nodes);
    }
    gemm_f16_kernel<<<grid_big, blk, shm>>>(MM, DD, 2 * DD,
        ctH, DD, Wu1H, bu1, nullptr, nullptr, hpH, 1);
    gemm_f16_kernel<<<grid_big, blk, shm>>>(MM, DD, DD,
        hpH, DD / 2, Wu2H, bu2, nodes, out_upd, nullptr, 0);

    // ---- importance MLP ----
    {
        size_t n = (size_t)MM * DD;
        concat_ug_kernel<<<(unsigned)((n + 255) / 256), blk>>>(out_upd);
    }
    gemm_f16_kernel<<<grid_big, blk, shm>>>(MM, DD, 2 * DD,
        ctH, DD, Wi1H, bi1, nullptr, hid, nullptr, 1);
    gemv_imp_kernel<<<MM, 128>>>(Wi2, bi2);
    imp_kernel<<<BB, 32>>>(out_imp);

    // ---- fused output + losses ----
    fused_kernel<<<BB, blk>>>(out_imp, out_upd, out_fused);
    physalign_kernel<<<BB, blk>>>(out_upd, out_fused);
    final_reduce_kernel<<<1, blk>>>(out);
}

// round 15
// speedup vs baseline: 2.2819x; 1.5395x over previous
#include <cuda_runtime.h>
#include <cuda_fp16.h>
#include <math.h>
#include <stdint.h>

// ---------------------------------------------------------------------------
// PhysicsGraphFusion: B=1024 graphs, N=7 nodes, D=1024 dim.
// Round 14: f16 single-pass GEMM (R13 inner loop) + dual-A-source loader
// (concat kernels eliminated; Wu1 reads [nodes|msg] planes, Wi1 reads
// [upd | upd_last] via row remap), attn writes packed msg plane,
// Wu2 epilogue writes packed upd plane.
// ---------------------------------------------------------------------------

#define BB   1024
#define NN   7
#define DD   1024
#define MM   (BB*NN)          // 7168
#define NP   (5*DD)           // 5120 packed projection width

static const size_t OFF_FUSED = 0;
static const size_t OFF_UPD   = (size_t)BB*DD;
static const size_t OFF_IMP   = OFF_UPD + (size_t)MM*DD;
static const size_t OFF_ATTN  = OFF_IMP + (size_t)MM;
static const size_t OFF_PHYS  = OFF_ATTN + (size_t)BB*NN*NN;
static const size_t OFF_ALIGN = OFF_PHYS + 1;

// ---------------- device scratch (static; no runtime allocation) -----------
__device__ float    g_qkv [ (size_t)MM*NP ];
__device__ float    g_cc  [ (size_t)BB*DD ];
__device__ float    g_hid [ (size_t)MM*DD ];
__device__ float    g_bpack[ NP ];
__device__ float    g_implog[ MM ];
__device__ float    g_phys_part [ BB ];
__device__ float    g_align_part[ BB ];

// activation planes (single f16 plane, k-pair packed u32, row-major [M][K/2])
__device__ uint32_t g_nodes_h[ (size_t)MM*DD/2 ];
__device__ uint32_t g_msg_h  [ (size_t)MM*DD/2 ];
__device__ uint32_t g_upd_h  [ (size_t)MM*DD/2 ];
__device__ uint32_t g_hidp_h [ (size_t)MM*DD/2 ];

// weight planes (single f16 plane, k-pair packed u32 [K/2][Nc])
__device__ uint32_t g_Wproj_h[ (size_t)(DD/2)*NP ];
__device__ uint32_t g_Wc_h   [ (size_t)(DD/2)*DD ];
__device__ uint32_t g_Wu1_h  [ (size_t)DD*DD ];     // K=2048 -> 1024 rows
__device__ uint32_t g_Wu2_h  [ (size_t)(DD/2)*DD ];
__device__ uint32_t g_Wi1_h  [ (size_t)DD*DD ];

__constant__ float c_adj[49] = {
    1,1,0,0,1,1,1,
    1,1,1,1,1,1,1,
    0,1,1,0,1,0,1,
    0,1,0,1,1,1,1,
    1,1,1,1,1,1,1,
    1,1,0,1,1,1,1,
    1,1,1,1,1,1,1 };

__device__ __forceinline__ float geluf(float x) {
    return 0.5f * x * (1.0f + erff(x * 0.70710678118654752440f));
}

__device__ __forceinline__ unsigned short f16_rn(float x) {
    __half h = __float2half_rn(x);
    return *reinterpret_cast<unsigned short*>(&h);
}
__device__ __forceinline__ uint32_t pack16(float x0, float x1) {
    return (uint32_t)f16_rn(x0) | ((uint32_t)f16_rn(x1) << 16);
}

__device__ __forceinline__ void mma_f16(float* c,
    uint32_t a0, uint32_t a1, uint32_t a2, uint32_t a3,
    uint32_t b0, uint32_t b1)
{
    asm volatile(
        "mma.sync.aligned.m16n8k16.row.col.f32.f16.f16.f32 "
        "{%0,%1,%2,%3}, {%4,%5,%6,%7}, {%8,%9}, {%0,%1,%2,%3};\n"
        : "+f"(c[0]), "+f"(c[1]), "+f"(c[2]), "+f"(c[3])
        : "r"(a0), "r"(a1), "r"(a2), "r"(a3), "r"(b0), "r"(b1));
}

__device__ __forceinline__ void cp_async16(uint32_t saddr, const void* gptr) {
    asm volatile("cp.async.ca.shared.global [%0], [%1], 16;\n"
                 :: "r"(saddr), "l"(gptr));
}

// ---------------------------------------------------------------------------
// f16 tensor-core GEMM with dual A source.
// C[M,Nc] = epi(A[M,K] @ W[K,Nc] + bias), where A columns [0, 2*kSplit32)
// come from Ah (row r) and columns beyond from Ah2 (row r or (r/7)*7+6).
// BM=BN=128, BK=32. 256 threads = 8 warps (4x2), warp tile 32x64.
// smem/buffer: Ah[128][20] Bh[16][136] (u32 words). cp.async double buffer,
// 2 CTAs/SM.
// ---------------------------------------------------------------------------
#define A_ST 20
#define B_ST 136
#define A_PL (128*A_ST)           // 2560
#define B_PL (16*B_ST)            // 2176
#define BUF_U32 (A_PL + B_PL)     // 4736
#define SMEM_GEMM_BYTES (2*BUF_U32*4)  // 37888

__global__ __launch_bounds__(256, 2)
void gemm_f16_kernel(int M, int Nc, int K,
    const uint32_t* __restrict__ Ah,  int lda32,
    const uint32_t* __restrict__ Ah2, int lda2_32, int kSplit32, int rowmap2,
    const uint32_t* __restrict__ Bh,
    const float* __restrict__ bias,
    const float* __restrict__ resid,
    float* __restrict__ Cf,
    uint32_t* __restrict__ ChH,
    int applyGelu)
{
    extern __shared__ uint32_t smem[];
    const uint32_t smem_base = (uint32_t)__cvta_generic_to_shared(smem);

    const int tid  = threadIdx.x;
    const int lane = tid & 31;
    const int wid  = tid >> 5;
    const int wm   = wid & 3;      // 0..3 -> 32-row slices
    const int wn   = wid >> 2;     // 0..1 -> 64-col slices
    const int gid  = lane >> 2;    // 0..7
    const int tig  = lane & 3;     // 0..3

    const int brow = blockIdx.y;
    const int bcol = blockIdx.x;

    // A loader: 512 uint4 slots (128 rows x 4 chunks), 2 per thread.
    // Row is fixed per thread -> precompute both source base pointers.
    int aC[2]; uint32_t aSm[2];
    const uint32_t* aB1[2];
    const uint32_t* aB2[2];
    #pragma unroll
    for (int it = 0; it < 2; it++) {
        int idx = it * 256 + tid;     // 0..511
        int ar  = idx >> 2;
        aC[it]  = (idx & 3) << 2;
        aSm[it] = (uint32_t)(ar * A_ST + aC[it]);
        int gRow = brow * 128 + ar;
        aB1[it] = Ah + (size_t)gRow * lda32;
        int r2  = rowmap2 ? (gRow / 7) * 7 + 6 : gRow;
        aB2[it] = Ah2 + (size_t)r2 * lda2_32;
    }
    // B loader: 512 uint4 slots (16 kp x 32 col-chunks), 2 per thread
    int bKp[2], bC[2]; uint32_t bSm[2];
    #pragma unroll
    for (int it = 0; it < 2; it++) {
        int idx = it * 256 + tid;     // 0..511
        bKp[it] = idx >> 5;  bC[it] = (idx & 31) << 2;
        bSm[it] = (uint32_t)(A_PL + bKp[it] * B_ST + bC[it]);
    }

    const uint32_t* Bsrc = Bh + bcol * 128;

    float acc[2][8][4];
    #pragma unroll
    for (int mi = 0; mi < 2; mi++)
        #pragma unroll
        for (int ni = 0; ni < 8; ni++)
            #pragma unroll
            for (int r = 0; r < 4; r++) acc[mi][ni][r] = 0.0f;

    // issue chunk 0 into buffer 0
    #pragma unroll
    for (int it = 0; it < 2; it++) {
        const uint32_t* ap = (0 < kSplit32) ? aB1[it] : aB2[it];
        cp_async16(smem_base + aSm[it] * 4, ap + aC[it]);
        cp_async16(smem_base + bSm[it] * 4,
                   Bsrc + (size_t)bKp[it] * Nc + bC[it]);
    }
    asm volatile("cp.async.commit_group;\n");
    asm volatile("cp.async.wait_group 0;\n" ::: "memory");
    __syncthreads();

    const int nChunks = K >> 5;
    for (int c = 0; c < nChunks; c++) {
        const uint32_t* buf = smem + (size_t)(c & 1) * BUF_U32;
        const uint32_t* sAh = buf;
        const uint32_t* sBh = buf + A_PL;

        const bool more = (c + 1 < nChunks);
        if (more) {
            const uint32_t nb = (uint32_t)(((c + 1) & 1) * BUF_U32) * 4;
            const int kb32 = ((c + 1) << 5) >> 1;    // u32 column base
            #pragma unroll
            for (int it = 0; it < 2; it++) {
                const uint32_t* ap = (kb32 < kSplit32)
                    ? (aB1[it] + kb32)
                    : (aB2[it] + (kb32 - kSplit32));
                cp_async16(smem_base + nb + aSm[it] * 4, ap + aC[it]);
                cp_async16(smem_base + nb + bSm[it] * 4,
                           Bsrc + (size_t)(kb32 + bKp[it]) * Nc + bC[it]);
            }
            asm volatile("cp.async.commit_group;\n");
        }

        #pragma unroll
        for (int ks = 0; ks < 2; ks++) {
            uint32_t fah[2][4];
            #pragma unroll
            for (int mi = 0; mi < 2; mi++) {
                int r0 = (wm * 32 + mi * 16 + gid) * A_ST + ks * 8 + tig;
                fah[mi][0] = sAh[r0];
                fah[mi][1] = sAh[r0 + 8 * A_ST];
                fah[mi][2] = sAh[r0 + 4];
                fah[mi][3] = sAh[r0 + 8 * A_ST + 4];
            }
            #pragma unroll
            for (int ni = 0; ni < 8; ni++) {
                int kb = (ks * 8 + tig) * B_ST + wn * 64 + ni * 8 + gid;
                uint32_t bh0 = sBh[kb];
                uint32_t bh1 = sBh[kb + 4 * B_ST];
                #pragma unroll
                for (int mi = 0; mi < 2; mi++)
                    mma_f16(acc[mi][ni], fah[mi][0], fah[mi][1], fah[mi][2], fah[mi][3], bh0, bh1);
            }
        }

        if (more)
            asm volatile("cp.async.wait_group 0;\n" ::: "memory");
        __syncthreads();
    }

    // ---- epilogue ----
    const int Nc2 = Nc >> 1;
    #pragma unroll
    for (int mi = 0; mi < 2; mi++) {
        #pragma unroll
        for (int ni = 0; ni < 8; ni++) {
            int row0 = brow * 128 + wm * 32 + mi * 16 + gid;
            int col0 = bcol * 128 + wn * 64 + ni * 8 + tig * 2;
            #pragma unroll
            for (int half = 0; half < 2; half++) {
                int row = row0 + half * 8;
                size_t base = (size_t)row * Nc + col0;
                float v0 = acc[mi][ni][half * 2 + 0];
                float v1 = acc[mi][ni][half * 2 + 1];
                if (bias) { v0 += bias[col0]; v1 += bias[col0 + 1]; }
                if (applyGelu) { v0 = geluf(v0); v1 = geluf(v1); }
                if (resid) { v0 += resid[base]; v1 += resid[base + 1]; }
                if (Cf) { Cf[base] = v0; Cf[base + 1] = v1; }
                if (ChH) {
                    size_t pidx = (size_t)row * Nc2 + (col0 >> 1);
                    ChH[pidx] = pack16(v0, v1);
                }
            }
        }
    }
}

// ---------------------------------------------------------------------------
// pre-pack kernels
// ---------------------------------------------------------------------------
__global__ void split_nodes_kernel(const float* __restrict__ nodes)
{
    size_t i = (size_t)blockIdx.x * blockDim.x + threadIdx.x;
    if (i >= (size_t)MM * DD / 2) return;
    g_nodes_h[i] = pack16(nodes[2 * i], nodes[2 * i + 1]);
}

__global__ void pack_proj_w_kernel(const float* __restrict__ Wq,
                                   const float* __restrict__ Wk,
                                   const float* __restrict__ Wv,
                                   const float* __restrict__ We1)
{
    size_t i = (size_t)blockIdx.x * blockDim.x + threadIdx.x;
    if (i >= (size_t)(DD / 2) * NP) return;
    int kp = (int)(i / NP);
    int c  = (int)(i % NP);
    int seg = c >> 10, cc = c & 1023;
    const float* src;
    if      (seg == 0) src = Wq;
    else if (seg == 1) src = Wk;
    else if (seg == 2) src = Wv;
    else if (seg == 3) src = We1;
    else               src = We1 + (size_t)DD * DD;
    g_Wproj_h[i] = pack16(src[(size_t)(2 * kp) * DD + cc],
                          src[(size_t)(2 * kp + 1) * DD + cc]);
}

__global__ void pack_w_gen_kernel(const float* __restrict__ W, int K, int Nc,
                                  uint32_t* __restrict__ H)
{
    size_t i = (size_t)blockIdx.x * blockDim.x + threadIdx.x;
    if (i >= (size_t)(K / 2) * Nc) return;
    int kp = (int)(i / Nc);
    int n  = (int)(i % Nc);
    H[i] = pack16(W[(size_t)(2 * kp) * Nc + n],
                  W[(size_t)(2 * kp + 1) * Nc + n]);
}

__global__ void pack_b_kernel(const float* __restrict__ bq,
                              const float* __restrict__ bk,
                              const float* __restrict__ bv)
{
    int c = blockIdx.x * blockDim.x + threadIdx.x;
    if (c >= NP) return;
    int seg = c >> 10, cc = c & 1023;
    float v = 0.0f;
    if      (seg == 0) v = bq[cc];
    else if (seg == 1) v = bk[cc];
    else if (seg == 2) v = bv[cc];
    g_bpack[c] = v;
}

// ---------------------------------------------------------------------------
// attention: edge-MLP + softmax + messages; msg written as packed f16 plane
// ---------------------------------------------------------------------------
__global__ __launch_bounds__(256)
void attn_kernel(const float* __restrict__ be1,
                 const float* __restrict__ We2,
                 const float* __restrict__ be2,
                 float* __restrict__ out_attn)
{
    const int b    = blockIdx.x;
    const int tid  = threadIdx.x;
    const int lane = tid & 31;
    const int wid  = tid >> 5;

    __shared__ float s_logit[49];
    __shared__ float s_attn[49];

    const float* base = g_qkv + (size_t)b * NN * NP;
    const float* cc   = g_cc  + (size_t)b * DD;

    for (int p = wid; p < 49; p += 8) {
        const int n = p / 7, m = p % 7;
        const float* qn  = base + (size_t)n * NP + 0*DD;
        const float* km  = base + (size_t)m * NP + 1*DD;
        const float* lan = base + (size_t)n * NP + 3*DD;
        const float* rbm = base + (size_t)m * NP + 4*DD;
        float qk = 0.0f, e = 0.0f;
        for (int d = lane; d < DD; d += 32) {
            qk = fmaf(qn[d], km[d], qk);
            float h = lan[d] + rbm[d] + cc[d] + be1[d];
            e  = fmaf(geluf(h), We2[d], e);
        }
        #pragma unroll
        for (int o = 16; o > 0; o >>= 1) {
            qk += __shfl_down_sync(0xffffffffu, qk, o);
            e  += __shfl_down_sync(0xffffffffu, e,  o);
        }
        if (lane == 0)
            s_logit[p] = qk * (1.0f / 32.0f) + e + be2[0]
                       + (c_adj[p] - 1.0f) * 10000.0f;
    }
    __syncthreads();

    if (tid < 7) {
        const int n = tid;
        float mx = -1e30f;
        #pragma unroll
        for (int m = 0; m < 7; m++) mx = fmaxf(mx, s_logit[n * 7 + m]);
        float ex[7], s = 0.0f;
        #pragma unroll
        for (int m = 0; m < 7; m++) { ex[m] = expf(s_logit[n * 7 + m] - mx); s += ex[m]; }
        #pragma unroll
        for (int m = 0; m < 7; m++) {
            float a = ex[m] / s;
            s_attn[n * 7 + m] = a;
            out_attn[(size_t)b * 49 + n * 7 + m] = a;
        }
    }
    __syncthreads();

    uint32_t* msgp = g_msg_h + (size_t)b * NN * (DD / 2);
    for (int dp = tid; dp < DD / 2; dp += 256) {
        int d0 = 2 * dp, d1 = d0 + 1;
        float v0[7], v1[7];
        #pragma unroll
        for (int m = 0; m < 7; m++) {
            v0[m] = base[(size_t)m * NP + 2*DD + d0];
            v1[m] = base[(size_t)m * NP + 2*DD + d1];
        }
        #pragma unroll
        for (int n = 0; n < 7; n++) {
            float a0 = 0.0f, a1 = 0.0f;
            #pragma unroll
            for (int m = 0; m < 7; m++) {
                a0 = fmaf(s_attn[n * 7 + m], v0[m], a0);
                a1 = fmaf(s_attn[n * 7 + m], v1[m], a1);
            }
            msgp[(size_t)n * (DD / 2) + dp] = pack16(a0, a1);
        }
    }
}

__global__ __launch_bounds__(128)
void gemv_imp_kernel(const float* __restrict__ Wi2, const float* __restrict__ bi2)
{
    const int row = blockIdx.x;
    const int tid = threadIdx.x;
    const float* h = g_hid + (size_t)row * DD;
    float s = 0.0f;
    for (int d = tid; d < DD; d += 128) s = fmaf(h[d], Wi2[d], s);
    #pragma unroll
    for (int o = 16; o > 0; o >>= 1) s += __shfl_down_sync(0xffffffffu, s, o);
    __shared__ float red[4];
    if ((tid & 31) == 0) red[tid >> 5] = s;
    __syncthreads();
    if (tid == 0)
        g_implog[row] = red[0] + red[1] + red[2] + red[3] + bi2[0];
}

__global__ void imp_kernel(float* __restrict__ out_imp)
{
    const int b = blockIdx.x;
    if (threadIdx.x != 0) return;
    float l[7], mx = -1e30f;
    #pragma unroll
    for (int n = 0; n < 7; n++) { l[n] = g_implog[b * 7 + n]; mx = fmaxf(mx, l[n]); }
    float s = 0.0f;
    #pragma unroll
    for (int n = 0; n < 7; n++) { l[n] = expf(l[n] - mx); s += l[n]; }
    float imp[7];
    #pragma unroll
    for (int n = 0; n < 7; n++) imp[n] = l[n] / s;

    const float cap[7] = {1.f,1.f,1.f,0.26f,1.f,1.f,0.24f};
    const float fr [7] = {1.f,1.f,1.f,0.f,  1.f,1.f,0.f };
    float capped[7], sc = 0.0f, fm = 0.0f;
    #pragma unroll
    for (int n = 0; n < 7; n++) {
        capped[n] = fminf(imp[n], cap[n]);
        sc += capped[n];
        fm += imp[n] * fr[n];
    }
    float residual = fmaxf(1.0f - sc, 0.0f);
    float redis[7], sr = 0.0f;
    #pragma unroll
    for (int n = 0; n < 7; n++) {
        float fs = (fm > 1e-6f) ? imp[n] * fr[n] / fmaxf(fm, 1e-6f) : fr[n] / 5.0f;
        redis[n] = capped[n] + fs * residual;
        sr += redis[n];
    }
    #pragma unroll
    for (int n = 0; n < 7; n++)
        out_imp[b * 7 + n] = redis[n] / fmaxf(sr, 1e-6f);
}

__global__ __launch_bounds__(256)
void fused_kernel(const float* __restrict__ out_imp,
                  const float* __restrict__ upd,
                  float* __restrict__ out_fused)
{
    const int b = blockIdx.x;
    const int tid = threadIdx.x;
    __shared__ float w[7];
    if (tid < 7) w[tid] = out_imp[b * 7 + tid];
    __syncthreads();
    const float* u = upd + (size_t)b * NN * DD;
    for (int d = tid; d < DD; d += 256) {
        float acc = 0.0f;
        #pragma unroll
        for (int n = 0; n < 7; n++) acc = fmaf(w[n], u[n * DD + d], acc);
        out_fused[(size_t)b * DD + d] = acc;
    }
}

__global__ __launch_bounds__(256)
void physalign_kernel(const float* __restrict__ upd,
                      const float* __restrict__ fused)
{
    const int b = blockIdx.x;
    const int tid = threadIdx.x;
    const int lane = tid & 31, wid = tid >> 5;
    __shared__ float dots[57];
    const float* u = upd   + (size_t)b * NN * DD;
    const float* f = fused + (size_t)b * DD;

    for (int t = wid; t < 57; t += 8) {
        const float *x, *y;
        if (t < 49)      { x = u + (t / 7) * DD; y = u + (t % 7) * DD; }
        else if (t < 56) { x = u + (t - 49) * DD; y = f; }
        else             { x = f; y = f; }
        float s = 0.0f;
        for (int d = lane; d < DD; d += 32) s = fmaf(x[d], y[d], s);
        #pragma unroll
        for (int o = 16; o > 0; o >>= 1) s += __shfl_down_sync(0xffffffffu, s, o);
        if (lane == 0) dots[t] = s;
    }
    __syncthreads();

    if (tid == 0) {
        float norms[7];
        #pragma unroll
        for (int n = 0; n < 7; n++) norms[n] = sqrtf(dots[n * 7 + n]);
        float edge = 0.0f, non = 0.0f;
        #pragma unroll
        for (int n = 0; n < 7; n++) {
            #pragma unroll
            for (int m = 0; m < 7; m++) {
                float cs = dots[n * 7 + m] / fmaxf(norms[n] * norms[m], 1e-8f);
                float a = c_adj[n * 7 + m];
                edge += (1.0f - cs) * a;
                float nonmask = (1.0f - a) * ((n == m) ? 0.0f : 1.0f);
                non += fmaxf(cs - 0.35f, 0.0f) * nonmask;
            }
        }
        g_phys_part[b] = edge / 41.0f + 0.5f * non / 8.0f;

        float fn = sqrtf(dots[56]);
        float al = 0.0f;
        #pragma unroll
        for (int n = 0; n < 7; n++) {
            float cs = dots[49 + n] / (fmaxf(norms[n], 1e-12f) * fmaxf(fn, 1e-12f));
            al += 1.0f - cs;
        }
        g_align_part[b] = al;
    }
}

__global__ __launch_bounds__(256)
void final_reduce_kernel(float* __restrict__ out)
{
    const int tid = threadIdx.x;
    float p = 0.0f, a = 0.0f;
    for (int b = tid; b < BB; b += 256) { p += g_phys_part[b]; a += g_align_part[b]; }
    __shared__ float sp[256], sa[256];
    sp[tid] = p; sa[tid] = a;
    __syncthreads();
    for (int s = 128; s > 0; s >>= 1) {
        if (tid < s) { sp[tid] += sp[tid + s]; sa[tid] += sa[tid + s]; }
        __syncthreads();
    }
    if (tid == 0) {
        out[OFF_PHYS]  = sp[0];
        out[OFF_ALIGN] = sa[0] / (float)(BB * NN);
    }
}

// ---------------------------------------------------------------------------
extern "C" void kernel_launch(void* const* d_in, const int* in_sizes, int n_in,
                              void* d_out, int out_size)
{
    const float* nodes = (const float*)d_in[0];
    const float* Wq    = (const float*)d_in[1];
    const float* bq    = (const float*)d_in[2];
    const float* Wk    = (const float*)d_in[3];
    const float* bk    = (const float*)d_in[4];
    const float* Wv    = (const float*)d_in[5];
    const float* bv    = (const float*)d_in[6];
    const float* We1   = (const float*)d_in[7];
    const float* be1   = (const float*)d_in[8];
    const float* We2   = (const float*)d_in[9];
    const float* be2   = (const float*)d_in[10];
    const float* Wu1   = (const float*)d_in[11];
    const float* bu1   = (const float*)d_in[12];
    const float* Wu2   = (const float*)d_in[13];
    const float* bu2   = (const float*)d_in[14];
    const float* Wi1   = (const float*)d_in[15];
    const float* bi1   = (const float*)d_in[16];
    const float* Wi2   = (const float*)d_in[17];
    const float* bi2   = (const float*)d_in[18];

    float* out       = (float*)d_out;
    float* out_fused = out + OFF_FUSED;
    float* out_upd   = out + OFF_UPD;
    float* out_imp   = out + OFF_IMP;
    float* out_attn  = out + OFF_ATTN;

    float* qkv = nullptr; cudaGetSymbolAddress((void**)&qkv, g_qkv);
    float* cc  = nullptr; cudaGetSymbolAddress((void**)&cc,  g_cc);
    float* hid = nullptr; cudaGetSymbolAddress((void**)&hid, g_hid);
    float* bpk = nullptr; cudaGetSymbolAddress((void**)&bpk, g_bpack);

    uint32_t *ndH=nullptr,*msgH=nullptr,*updH=nullptr,*hpH=nullptr;
    cudaGetSymbolAddress((void**)&ndH,  g_nodes_h);
    cudaGetSymbolAddress((void**)&msgH, g_msg_h);
    cudaGetSymbolAddress((void**)&updH, g_upd_h);
    cudaGetSymbolAddress((void**)&hpH,  g_hidp_h);

    uint32_t *WprH=nullptr,*WcH=nullptr,*Wu1H=nullptr,*Wu2H=nullptr,*Wi1H=nullptr;
    cudaGetSymbolAddress((void**)&WprH, g_Wproj_h);
    cudaGetSymbolAddress((void**)&WcH,  g_Wc_h);
    cudaGetSymbolAddress((void**)&Wu1H, g_Wu1_h);
    cudaGetSymbolAddress((void**)&Wu2H, g_Wu2_h);
    cudaGetSymbolAddress((void**)&Wi1H, g_Wi1_h);

    cudaFuncSetAttribute(gemm_f16_kernel,
                         cudaFuncAttributeMaxDynamicSharedMemorySize,
                         SMEM_GEMM_BYTES);

    dim3 blk(256);
    const size_t shm = SMEM_GEMM_BYTES;
    const int HK = DD / 2;   // 512 u32 columns per 1024-K source

    // ---- pre-pack activations / weights ----
    {
        size_t n;
        n = (size_t)MM * DD / 2;
        split_nodes_kernel<<<(unsigned)((n + 255) / 256), blk>>>(nodes);
        n = (size_t)(DD / 2) * NP;
        pack_proj_w_kernel<<<(unsigned)((n + 255) / 256), blk>>>(Wq, Wk, Wv, We1);
        pack_b_kernel<<<(NP + 255) / 256, blk>>>(bq, bk, bv);
        n = (size_t)(DD / 2) * DD;
        pack_w_gen_kernel<<<(unsigned)((n + 255) / 256), blk>>>(
            We1 + (size_t)2 * DD * DD, DD, DD, WcH);
        pack_w_gen_kernel<<<(unsigned)((n + 255) / 256), blk>>>(Wu2, DD, DD, Wu2H);
        n = (size_t)DD * DD;
        pack_w_gen_kernel<<<(unsigned)((n + 255) / 256), blk>>>(Wu1, 2 * DD, DD, Wu1H);
        pack_w_gen_kernel<<<(unsigned)((n + 255) / 256), blk>>>(Wi1, 2 * DD, DD, Wi1H);
    }

    // ---- merged projections: [7168,1024] x [1024,5120] -> qkv ----
    dim3 grid_proj(NP / 128, MM / 128);     // 40 x 56
    gemm_f16_kernel<<<grid_proj, blk, shm>>>(MM, NP, DD,
        ndH, HK, ndH, HK, HK, 0,
        WprH, bpk, nullptr, qkv, nullptr, 0);

    // ---- cc projection (last node rows) ----
    dim3 grid_cc(DD / 128, BB / 128);       // 8 x 8
    gemm_f16_kernel<<<grid_cc, blk, shm>>>(BB, DD, DD,
        ndH + (size_t)(NN - 1) * HK, NN * HK,
        ndH + (size_t)(NN - 1) * HK, NN * HK, HK, 0,
        WcH, nullptr, nullptr, cc, nullptr, 0);

    // ---- attention (writes packed msg plane) ----
    attn_kernel<<<BB, blk>>>(be1, We2, be2, out_attn);

    // ---- update MLP: A = [nodes | msg] via dual source ----
    dim3 grid_big(DD / 128, MM / 128);      // 8 x 56
    gemm_f16_kernel<<<grid_big, blk, shm>>>(MM, DD, 2 * DD,
        ndH, HK, msgH, HK, HK, 0,
        Wu1H, bu1, nullptr, nullptr, hpH, 1);
    gemm_f16_kernel<<<grid_big, blk, shm>>>(MM, DD, DD,
        hpH, HK, hpH, HK, HK, 0,
        Wu2H, bu2, nodes, out_upd, updH, 0);

    // ---- importance MLP: A = [upd | upd_last] via dual source + row remap ----
    gemm_f16_kernel<<<grid_big, blk, shm>>>(MM, DD, 2 * DD,
        updH, HK, updH, HK, HK, 1,
        Wi1H, bi1, nullptr, hid, nullptr, 1);
    gemv_imp_kernel<<<MM, 128>>>(Wi2, bi2);
    imp_kernel<<<BB, 32>>>(out_imp);

    // ---- fused output + losses ----
    fused_kernel<<<BB, blk>>>(out_imp, out_upd, out_fused);
    physalign_kernel<<<BB, blk>>>(out_upd, out_fused);
    final_reduce_kernel<<<1, blk>>>(out);
}

// round 16
// speedup vs baseline: 2.3389x; 1.0250x over previous
#include <cuda_runtime.h>
#include <cuda_fp16.h>
#include <math.h>
#include <stdint.h>

// ---------------------------------------------------------------------------
// PhysicsGraphFusion: B=1024 graphs, N=7 nodes, D=1024 dim.
// Round 15: R14 GEMM pipeline + (a) single mega-pack launch, (b) qkv kept
// as packed f16 plane end-to-end (attn unpacks), (c) fused+physalign merged
// with smem-staged upd.
// ---------------------------------------------------------------------------

#define BB   1024
#define NN   7
#define DD   1024
#define MM   (BB*NN)          // 7168
#define NP   (5*DD)           // 5120 packed projection width
#define NP2  (NP/2)           // 2560 u32 row stride of packed qkv

static const size_t OFF_FUSED = 0;
static const size_t OFF_UPD   = (size_t)BB*DD;
static const size_t OFF_IMP   = OFF_UPD + (size_t)MM*DD;
static const size_t OFF_ATTN  = OFF_IMP + (size_t)MM;
static const size_t OFF_PHYS  = OFF_ATTN + (size_t)BB*NN*NN;
static const size_t OFF_ALIGN = OFF_PHYS + 1;

// ---------------- device scratch (static; no runtime allocation) -----------
__device__ uint32_t g_qkvp[ (size_t)MM*NP2 ];       // packed f16 q|k|v|la|rb
__device__ float    g_cc  [ (size_t)BB*DD ];
__device__ float    g_hid [ (size_t)MM*DD ];
__device__ float    g_bpack[ NP ];
__device__ float    g_implog[ MM ];
__device__ float    g_phys_part [ BB ];
__device__ float    g_align_part[ BB ];

// activation planes (single f16 plane, k-pair packed u32, row-major [M][K/2])
__device__ uint32_t g_nodes_h[ (size_t)MM*DD/2 ];
__device__ uint32_t g_msg_h  [ (size_t)MM*DD/2 ];
__device__ uint32_t g_upd_h  [ (size_t)MM*DD/2 ];
__device__ uint32_t g_hidp_h [ (size_t)MM*DD/2 ];

// weight planes (single f16 plane, k-pair packed u32 [K/2][Nc])
__device__ uint32_t g_Wproj_h[ (size_t)(DD/2)*NP ];
__device__ uint32_t g_Wc_h   [ (size_t)(DD/2)*DD ];
__device__ uint32_t g_Wu1_h  [ (size_t)DD*DD ];     // K=2048 -> 1024 rows
__device__ uint32_t g_Wu2_h  [ (size_t)(DD/2)*DD ];
__device__ uint32_t g_Wi1_h  [ (size_t)DD*DD ];

__constant__ float c_adj[49] = {
    1,1,0,0,1,1,1,
    1,1,1,1,1,1,1,
    0,1,1,0,1,0,1,
    0,1,0,1,1,1,1,
    1,1,1,1,1,1,1,
    1,1,0,1,1,1,1,
    1,1,1,1,1,1,1 };

__device__ __forceinline__ float geluf(float x) {
    return 0.5f * x * (1.0f + erff(x * 0.70710678118654752440f));
}

__device__ __forceinline__ unsigned short f16_rn(float x) {
    __half h = __float2half_rn(x);
    return *reinterpret_cast<unsigned short*>(&h);
}
__device__ __forceinline__ uint32_t pack16(float x0, float x1) {
    return (uint32_t)f16_rn(x0) | ((uint32_t)f16_rn(x1) << 16);
}
__device__ __forceinline__ float2 up16(uint32_t w) {
    __half2 h = *reinterpret_cast<__half2*>(&w);
    return __half22float2(h);
}

__device__ __forceinline__ void mma_f16(float* c,
    uint32_t a0, uint32_t a1, uint32_t a2, uint32_t a3,
    uint32_t b0, uint32_t b1)
{
    asm volatile(
        "mma.sync.aligned.m16n8k16.row.col.f32.f16.f16.f32 "
        "{%0,%1,%2,%3}, {%4,%5,%6,%7}, {%8,%9}, {%0,%1,%2,%3};\n"
        : "+f"(c[0]), "+f"(c[1]), "+f"(c[2]), "+f"(c[3])
        : "r"(a0), "r"(a1), "r"(a2), "r"(a3), "r"(b0), "r"(b1));
}

__device__ __forceinline__ void cp_async16(uint32_t saddr, const void* gptr) {
    asm volatile("cp.async.ca.shared.global [%0], [%1], 16;\n"
                 :: "r"(saddr), "l"(gptr));
}

// ---------------------------------------------------------------------------
// f16 tensor-core GEMM with dual A source (R14-proven).
// ---------------------------------------------------------------------------
#define A_ST 20
#define B_ST 136
#define A_PL (128*A_ST)           // 2560
#define B_PL (16*B_ST)            // 2176
#define BUF_U32 (A_PL + B_PL)     // 4736
#define SMEM_GEMM_BYTES (2*BUF_U32*4)  // 37888

__global__ __launch_bounds__(256, 2)
void gemm_f16_kernel(int M, int Nc, int K,
    const uint32_t* __restrict__ Ah,  int lda32,
    const uint32_t* __restrict__ Ah2, int lda2_32, int kSplit32, int rowmap2,
    const uint32_t* __restrict__ Bh,
    const float* __restrict__ bias,
    const float* __restrict__ resid,
    float* __restrict__ Cf,
    uint32_t* __restrict__ ChH,
    int applyGelu)
{
    extern __shared__ uint32_t smem[];
    const uint32_t smem_base = (uint32_t)__cvta_generic_to_shared(smem);

    const int tid  = threadIdx.x;
    const int lane = tid & 31;
    const int wid  = tid >> 5;
    const int wm   = wid & 3;
    const int wn   = wid >> 2;
    const int gid  = lane >> 2;
    const int tig  = lane & 3;

    const int brow = blockIdx.y;
    const int bcol = blockIdx.x;

    int aC[2]; uint32_t aSm[2];
    const uint32_t* aB1[2];
    const uint32_t* aB2[2];
    #pragma unroll
    for (int it = 0; it < 2; it++) {
        int idx = it * 256 + tid;
        int ar  = idx >> 2;
        aC[it]  = (idx & 3) << 2;
        aSm[it] = (uint32_t)(ar * A_ST + aC[it]);
        int gRow = brow * 128 + ar;
        aB1[it] = Ah + (size_t)gRow * lda32;
        int r2  = rowmap2 ? (gRow / 7) * 7 + 6 : gRow;
        aB2[it] = Ah2 + (size_t)r2 * lda2_32;
    }
    int bKp[2], bC[2]; uint32_t bSm[2];
    #pragma unroll
    for (int it = 0; it < 2; it++) {
        int idx = it * 256 + tid;
        bKp[it] = idx >> 5;  bC[it] = (idx & 31) << 2;
        bSm[it] = (uint32_t)(A_PL + bKp[it] * B_ST + bC[it]);
    }

    const uint32_t* Bsrc = Bh + bcol * 128;

    float acc[2][8][4];
    #pragma unroll
    for (int mi = 0; mi < 2; mi++)
        #pragma unroll
        for (int ni = 0; ni < 8; ni++)
            #pragma unroll
            for (int r = 0; r < 4; r++) acc[mi][ni][r] = 0.0f;

    #pragma unroll
    for (int it = 0; it < 2; it++) {
        const uint32_t* ap = (0 < kSplit32) ? aB1[it] : aB2[it];
        cp_async16(smem_base + aSm[it] * 4, ap + aC[it]);
        cp_async16(smem_base + bSm[it] * 4,
                   Bsrc + (size_t)bKp[it] * Nc + bC[it]);
    }
    asm volatile("cp.async.commit_group;\n");
    asm volatile("cp.async.wait_group 0;\n" ::: "memory");
    __syncthreads();

    const int nChunks = K >> 5;
    for (int c = 0; c < nChunks; c++) {
        const uint32_t* buf = smem + (size_t)(c & 1) * BUF_U32;
        const uint32_t* sAh = buf;
        const uint32_t* sBh = buf + A_PL;

        const bool more = (c + 1 < nChunks);
        if (more) {
            const uint32_t nb = (uint32_t)(((c + 1) & 1) * BUF_U32) * 4;
            const int kb32 = ((c + 1) << 5) >> 1;
            #pragma unroll
            for (int it = 0; it < 2; it++) {
                const uint32_t* ap = (kb32 < kSplit32)
                    ? (aB1[it] + kb32)
                    : (aB2[it] + (kb32 - kSplit32));
                cp_async16(smem_base + nb + aSm[it] * 4, ap + aC[it]);
                cp_async16(smem_base + nb + bSm[it] * 4,
                           Bsrc + (size_t)(kb32 + bKp[it]) * Nc + bC[it]);
            }
            asm volatile("cp.async.commit_group;\n");
        }

        #pragma unroll
        for (int ks = 0; ks < 2; ks++) {
            uint32_t fah[2][4];
            #pragma unroll
            for (int mi = 0; mi < 2; mi++) {
                int r0 = (wm * 32 + mi * 16 + gid) * A_ST + ks * 8 + tig;
                fah[mi][0] = sAh[r0];
                fah[mi][1] = sAh[r0 + 8 * A_ST];
                fah[mi][2] = sAh[r0 + 4];
                fah[mi][3] = sAh[r0 + 8 * A_ST + 4];
            }
            #pragma unroll
            for (int ni = 0; ni < 8; ni++) {
                int kb = (ks * 8 + tig) * B_ST + wn * 64 + ni * 8 + gid;
                uint32_t bh0 = sBh[kb];
                uint32_t bh1 = sBh[kb + 4 * B_ST];
                #pragma unroll
                for (int mi = 0; mi < 2; mi++)
                    mma_f16(acc[mi][ni], fah[mi][0], fah[mi][1], fah[mi][2], fah[mi][3], bh0, bh1);
            }
        }

        if (more)
            asm volatile("cp.async.wait_group 0;\n" ::: "memory");
        __syncthreads();
    }

    // ---- epilogue ----
    const int Nc2 = Nc >> 1;
    #pragma unroll
    for (int mi = 0; mi < 2; mi++) {
        #pragma unroll
        for (int ni = 0; ni < 8; ni++) {
            int row0 = brow * 128 + wm * 32 + mi * 16 + gid;
            int col0 = bcol * 128 + wn * 64 + ni * 8 + tig * 2;
            #pragma unroll
            for (int half = 0; half < 2; half++) {
                int row = row0 + half * 8;
                size_t base = (size_t)row * Nc + col0;
                float v0 = acc[mi][ni][half * 2 + 0];
                float v1 = acc[mi][ni][half * 2 + 1];
                if (bias) { v0 += bias[col0]; v1 += bias[col0 + 1]; }
                if (applyGelu) { v0 = geluf(v0); v1 = geluf(v1); }
                if (resid) { v0 += resid[base]; v1 += resid[base + 1]; }
                if (Cf) { Cf[base] = v0; Cf[base + 1] = v1; }
                if (ChH) {
                    size_t pidx = (size_t)row * Nc2 + (col0 >> 1);
                    ChH[pidx] = pack16(v0, v1);
                }
            }
        }
    }
}

// ---------------------------------------------------------------------------
// pre-pack: nodes plane (separate: reads harness input)
// ---------------------------------------------------------------------------
__global__ void split_nodes_kernel(const float* __restrict__ nodes)
{
    size_t i = (size_t)blockIdx.x * blockDim.x + threadIdx.x;
    if (i >= (size_t)MM * DD / 2) return;
    g_nodes_h[i] = pack16(nodes[2 * i], nodes[2 * i + 1]);
}

// one mega-pack launch: all weight planes + bias, region-dispatched
#define RP0 ((size_t)(DD/2)*NP)          // Wproj   2,621,440
#define RP1 (RP0 + (size_t)(DD/2)*DD)    // + Wc      524,288
#define RP2 (RP1 + (size_t)(DD/2)*DD)    // + Wu2     524,288
#define RP3 (RP2 + (size_t)DD*DD)        // + Wu1   1,048,576
#define RP4 (RP3 + (size_t)DD*DD)        // + Wi1   1,048,576
#define RP5 (RP4 + NP)                   // + bias      5,120

__global__ void pack_all_kernel(const float* __restrict__ Wq,
                                const float* __restrict__ Wk,
                                const float* __restrict__ Wv,
                                const float* __restrict__ We1,
                                const float* __restrict__ Wu1,
                                const float* __restrict__ Wu2,
                                const float* __restrict__ Wi1,
                                const float* __restrict__ bq,
                                const float* __restrict__ bk,
                                const float* __restrict__ bv)
{
    size_t i = (size_t)blockIdx.x * blockDim.x + threadIdx.x;
    if (i >= RP5) return;
    if (i < RP0) {
        int kp = (int)(i / NP);
        int c  = (int)(i % NP);
        int seg = c >> 10, cc = c & 1023;
        const float* src;
        if      (seg == 0) src = Wq;
        else if (seg == 1) src = Wk;
        else if (seg == 2) src = Wv;
        else if (seg == 3) src = We1;
        else               src = We1 + (size_t)DD * DD;
        g_Wproj_h[i] = pack16(src[(size_t)(2 * kp) * DD + cc],
                              src[(size_t)(2 * kp + 1) * DD + cc]);
    } else if (i < RP1) {
        size_t j = i - RP0;
        int kp = (int)(j / DD), n = (int)(j % DD);
        const float* W = We1 + (size_t)2 * DD * DD;
        g_Wc_h[j] = pack16(W[(size_t)(2 * kp) * DD + n],
                           W[(size_t)(2 * kp + 1) * DD + n]);
    } else if (i < RP2) {
        size_t j = i - RP1;
        int kp = (int)(j / DD), n = (int)(j % DD);
        g_Wu2_h[j] = pack16(Wu2[(size_t)(2 * kp) * DD + n],
                            Wu2[(size_t)(2 * kp + 1) * DD + n]);
    } else if (i < RP3) {
        size_t j = i - RP2;
        int kp = (int)(j / DD), n = (int)(j % DD);
        g_Wu1_h[j] = pack16(Wu1[(size_t)(2 * kp) * DD + n],
                            Wu1[(size_t)(2 * kp + 1) * DD + n]);
    } else if (i < RP4) {
        size_t j = i - RP3;
        int kp = (int)(j / DD), n = (int)(j % DD);
        g_Wi1_h[j] = pack16(Wi1[(size_t)(2 * kp) * DD + n],
                            Wi1[(size_t)(2 * kp + 1) * DD + n]);
    } else {
        int c = (int)(i - RP4);
        int seg = c >> 10, cc = c & 1023;
        float v = 0.0f;
        if      (seg == 0) v = bq[cc];
        else if (seg == 1) v = bk[cc];
        else if (seg == 2) v = bv[cc];
        g_bpack[c] = v;
    }
}

// ---------------------------------------------------------------------------
// attention: reads packed qkv plane, writes packed msg plane
// ---------------------------------------------------------------------------
__global__ __launch_bounds__(256)
void attn_kernel(const float* __restrict__ be1,
                 const float* __restrict__ We2,
                 const float* __restrict__ be2,
                 float* __restrict__ out_attn)
{
    const int b    = blockIdx.x;
    const int tid  = threadIdx.x;
    const int lane = tid & 31;
    const int wid  = tid >> 5;

    __shared__ float s_logit[49];
    __shared__ float s_attn[49];

    const uint32_t* basep = g_qkvp + (size_t)b * NN * NP2;
    const float*    cc    = g_cc   + (size_t)b * DD;

    for (int p = wid; p < 49; p += 8) {
        const int n = p / 7, m = p % 7;
        const uint32_t* qn  = basep + (size_t)n * NP2 + 0*(DD/2);
        const uint32_t* km  = basep + (size_t)m * NP2 + 1*(DD/2);
        const uint32_t* lan = basep + (size_t)n * NP2 + 3*(DD/2);
        const uint32_t* rbm = basep + (size_t)m * NP2 + 4*(DD/2);
        float qk = 0.0f, e = 0.0f;
        for (int dp = lane; dp < DD / 2; dp += 32) {
            float2 q2 = up16(qn[dp]);
            float2 k2 = up16(km[dp]);
            qk = fmaf(q2.x, k2.x, qk);
            qk = fmaf(q2.y, k2.y, qk);
            float2 l2 = up16(lan[dp]);
            float2 r2 = up16(rbm[dp]);
            int d0 = 2 * dp;
            float h0 = l2.x + r2.x + cc[d0]     + be1[d0];
            float h1 = l2.y + r2.y + cc[d0 + 1] + be1[d0 + 1];
            e = fmaf(geluf(h0), We2[d0],     e);
            e = fmaf(geluf(h1), We2[d0 + 1], e);
        }
        #pragma unroll
        for (int o = 16; o > 0; o >>= 1) {
            qk += __shfl_down_sync(0xffffffffu, qk, o);
            e  += __shfl_down_sync(0xffffffffu, e,  o);
        }
        if (lane == 0)
            s_logit[p] = qk * (1.0f / 32.0f) + e + be2[0]
                       + (c_adj[p] - 1.0f) * 10000.0f;
    }
    __syncthreads();

    if (tid < 7) {
        const int n = tid;
        float mx = -1e30f;
        #pragma unroll
        for (int m = 0; m < 7; m++) mx = fmaxf(mx, s_logit[n * 7 + m]);
        float ex[7], s = 0.0f;
        #pragma unroll
        for (int m = 0; m < 7; m++) { ex[m] = expf(s_logit[n * 7 + m] - mx); s += ex[m]; }
        #pragma unroll
        for (int m = 0; m < 7; m++) {
            float a = ex[m] / s;
            s_attn[n * 7 + m] = a;
            out_attn[(size_t)b * 49 + n * 7 + m] = a;
        }
    }
    __syncthreads();

    uint32_t* msgp = g_msg_h + (size_t)b * NN * (DD / 2);
    for (int dp = tid; dp < DD / 2; dp += 256) {
        float v0[7], v1[7];
        #pragma unroll
        for (int m = 0; m < 7; m++) {
            float2 v2 = up16(basep[(size_t)m * NP2 + 2*(DD/2) + dp]);
            v0[m] = v2.x; v1[m] = v2.y;
        }
        #pragma unroll
        for (int n = 0; n < 7; n++) {
            float a0 = 0.0f, a1 = 0.0f;
            #pragma unroll
            for (int m = 0; m < 7; m++) {
                a0 = fmaf(s_attn[n * 7 + m], v0[m], a0);
                a1 = fmaf(s_attn[n * 7 + m], v1[m], a1);
            }
            msgp[(size_t)n * (DD / 2) + dp] = pack16(a0, a1);
        }
    }
}

__global__ __launch_bounds__(128)
void gemv_imp_kernel(const float* __restrict__ Wi2, const float* __restrict__ bi2)
{
    const int row = blockIdx.x;
    const int tid = threadIdx.x;
    const float* h = g_hid + (size_t)row * DD;
    float s = 0.0f;
    for (int d = tid; d < DD; d += 128) s = fmaf(h[d], Wi2[d], s);
    #pragma unroll
    for (int o = 16; o > 0; o >>= 1) s += __shfl_down_sync(0xffffffffu, s, o);
    __shared__ float red[4];
    if ((tid & 31) == 0) red[tid >> 5] = s;
    __syncthreads();
    if (tid == 0)
        g_implog[row] = red[0] + red[1] + red[2] + red[3] + bi2[0];
}

__global__ void imp_kernel(float* __restrict__ out_imp)
{
    const int b = blockIdx.x;
    if (threadIdx.x != 0) return;
    float l[7], mx = -1e30f;
    #pragma unroll
    for (int n = 0; n < 7; n++) { l[n] = g_implog[b * 7 + n]; mx = fmaxf(mx, l[n]); }
    float s = 0.0f;
    #pragma unroll
    for (int n = 0; n < 7; n++) { l[n] = expf(l[n] - mx); s += l[n]; }
    float imp[7];
    #pragma unroll
    for (int n = 0; n < 7; n++) imp[n] = l[n] / s;

    const float cap[7] = {1.f,1.f,1.f,0.26f,1.f,1.f,0.24f};
    const float fr [7] = {1.f,1.f,1.f,0.f,  1.f,1.f,0.f };
    float capped[7], sc = 0.0f, fm = 0.0f;
    #pragma unroll
    for (int n = 0; n < 7; n++) {
        capped[n] = fminf(imp[n], cap[n]);
        sc += capped[n];
        fm += imp[n] * fr[n];
    }
    float residual = fmaxf(1.0f - sc, 0.0f);
    float redis[7], sr = 0.0f;
    #pragma unroll
    for (int n = 0; n < 7; n++) {
        float fs = (fm > 1e-6f) ? imp[n] * fr[n] / fmaxf(fm, 1e-6f) : fr[n] / 5.0f;
        redis[n] = capped[n] + fs * residual;
        sr += redis[n];
    }
    #pragma unroll
    for (int n = 0; n < 7; n++)
        out_imp[b * 7 + n] = redis[n] / fmaxf(sr, 1e-6f);
}

// ---------------------------------------------------------------------------
// fused output + physics/alignment in ONE kernel; upd staged in smem
// ---------------------------------------------------------------------------
__global__ __launch_bounds__(256)
void fusedphys_kernel(const float* __restrict__ out_imp,
                      const float* __restrict__ upd,
                      float* __restrict__ out_fused)
{
    const int b = blockIdx.x;
    const int tid = threadIdx.x;
    const int lane = tid & 31, wid = tid >> 5;

    __shared__ float su[NN * DD];    // 28 KB
    __shared__ float sf[DD];         // 4 KB
    __shared__ float w[7];
    __shared__ float dots[57];

    if (tid < 7) w[tid] = out_imp[b * 7 + tid];
    const float* u = upd + (size_t)b * NN * DD;
    for (int i = tid; i < NN * DD; i += 256) su[i] = u[i];
    __syncthreads();

    for (int d = tid; d < DD; d += 256) {
        float acc = 0.0f;
        #pragma unroll
        for (int n = 0; n < 7; n++) acc = fmaf(w[n], su[n * DD + d], acc);
        sf[d] = acc;
        out_fused[(size_t)b * DD + d] = acc;
    }
    __syncthreads();

    for (int t = wid; t < 57; t += 8) {
        const float *x, *y;
        if (t < 49)      { x = su + (t / 7) * DD; y = su + (t % 7) * DD; }
        else if (t < 56) { x = su + (t - 49) * DD; y = sf; }
        else             { x = sf; y = sf; }
        float s = 0.0f;
        for (int d = lane; d < DD; d += 32) s = fmaf(x[d], y[d], s);
        #pragma unroll
        for (int o = 16; o > 0; o >>= 1) s += __shfl_down_sync(0xffffffffu, s, o);
        if (lane == 0) dots[t] = s;
    }
    __syncthreads();

    if (tid == 0) {
        float norms[7];
        #pragma unroll
        for (int n = 0; n < 7; n++) norms[n] = sqrtf(dots[n * 7 + n]);
        float edge = 0.0f, non = 0.0f;
        #pragma unroll
        for (int n = 0; n < 7; n++) {
            #pragma unroll
            for (int m = 0; m < 7; m++) {
                float cs = dots[n * 7 + m] / fmaxf(norms[n] * norms[m], 1e-8f);
                float a = c_adj[n * 7 + m];
                edge += (1.0f - cs) * a;
                float nonmask = (1.0f - a) * ((n == m) ? 0.0f : 1.0f);
                non += fmaxf(cs - 0.35f, 0.0f) * nonmask;
            }
        }
        g_phys_part[b] = edge / 41.0f + 0.5f * non / 8.0f;

        float fn = sqrtf(dots[56]);
        float al = 0.0f;
        #pragma unroll
        for (int n = 0; n < 7; n++) {
            float cs = dots[49 + n] / (fmaxf(norms[n], 1e-12f) * fmaxf(fn, 1e-12f));
            al += 1.0f - cs;
        }
        g_align_part[b] = al;
    }
}

__global__ __launch_bounds__(256)
void final_reduce_kernel(float* __restrict__ out)
{
    const int tid = threadIdx.x;
    float p = 0.0f, a = 0.0f;
    for (int b = tid; b < BB; b += 256) { p += g_phys_part[b]; a += g_align_part[b]; }
    __shared__ float sp[256], sa[256];
    sp[tid] = p; sa[tid] = a;
    __syncthreads();
    for (int s = 128; s > 0; s >>= 1) {
        if (tid < s) { sp[tid] += sp[tid + s]; sa[tid] += sa[tid + s]; }
        __syncthreads();
    }
    if (tid == 0) {
        out[OFF_PHYS]  = sp[0];
        out[OFF_ALIGN] = sa[0] / (float)(BB * NN);
    }
}

// ---------------------------------------------------------------------------
extern "C" void kernel_launch(void* const* d_in, const int* in_sizes, int n_in,
                              void* d_out, int out_size)
{
    const float* nodes = (const float*)d_in[0];
    const float* Wq    = (const float*)d_in[1];
    const float* bq    = (const float*)d_in[2];
    const float* Wk    = (const float*)d_in[3];
    const float* bk    = (const float*)d_in[4];
    const float* Wv    = (const float*)d_in[5];
    const float* bv    = (const float*)d_in[6];
    const float* We1   = (const float*)d_in[7];
    const float* be1   = (const float*)d_in[8];
    const float* We2   = (const float*)d_in[9];
    const float* be2   = (const float*)d_in[10];
    const float* Wu1   = (const float*)d_in[11];
    const float* bu1   = (const float*)d_in[12];
    const float* Wu2   = (const float*)d_in[13];
    const float* bu2   = (const float*)d_in[14];
    const float* Wi1   = (const float*)d_in[15];
    const float* bi1   = (const float*)d_in[16];
    const float* Wi2   = (const float*)d_in[17];
    const float* bi2   = (const float*)d_in[18];

    float* out       = (float*)d_out;
    float* out_fused = out + OFF_FUSED;
    float* out_upd   = out + OFF_UPD;
    float* out_imp   = out + OFF_IMP;
    float* out_attn  = out + OFF_ATTN;

    float* cc  = nullptr; cudaGetSymbolAddress((void**)&cc,  g_cc);
    float* hid = nullptr; cudaGetSymbolAddress((void**)&hid, g_hid);
    float* bpk = nullptr; cudaGetSymbolAddress((void**)&bpk, g_bpack);

    uint32_t *qkvp=nullptr,*ndH=nullptr,*msgH=nullptr,*updH=nullptr,*hpH=nullptr;
    cudaGetSymbolAddress((void**)&qkvp, g_qkvp);
    cudaGetSymbolAddress((void**)&ndH,  g_nodes_h);
    cudaGetSymbolAddress((void**)&msgH, g_msg_h);
    cudaGetSymbolAddress((void**)&updH, g_upd_h);
    cudaGetSymbolAddress((void**)&hpH,  g_hidp_h);

    uint32_t *WprH=nullptr,*WcH=nullptr,*Wu1H=nullptr,*Wu2H=nullptr,*Wi1H=nullptr;
    cudaGetSymbolAddress((void**)&WprH, g_Wproj_h);
    cudaGetSymbolAddress((void**)&WcH,  g_Wc_h);
    cudaGetSymbolAddress((void**)&Wu1H, g_Wu1_h);
    cudaGetSymbolAddress((void**)&Wu2H, g_Wu2_h);
    cudaGetSymbolAddress((void**)&Wi1H, g_Wi1_h);

    cudaFuncSetAttribute(gemm_f16_kernel,
                         cudaFuncAttributeMaxDynamicSharedMemorySize,
                         SMEM_GEMM_BYTES);

    dim3 blk(256);
    const size_t shm = SMEM_GEMM_BYTES;
    const int HK = DD / 2;   // 512 u32 columns per 1024-K source

    // ---- pre-pack: 2 launches ----
    {
        size_t n = (size_t)MM * DD / 2;
        split_nodes_kernel<<<(unsigned)((n + 255) / 256), blk>>>(nodes);
        pack_all_kernel<<<(unsigned)((RP5 + 255) / 256), blk>>>(
            Wq, Wk, Wv, We1, Wu1, Wu2, Wi1, bq, bk, bv);
    }

    // ---- merged projections -> packed qkv plane ----
    dim3 grid_proj(NP / 128, MM / 128);     // 40 x 56
    gemm_f16_kernel<<<grid_proj, blk, shm>>>(MM, NP, DD,
        ndH, HK, ndH, HK, HK, 0,
        WprH, bpk, nullptr, nullptr, qkvp, 0);

    // ---- cc projection (last node rows), f32 out ----
    dim3 grid_cc(DD / 128, BB / 128);       // 8 x 8
    gemm_f16_kernel<<<grid_cc, blk, shm>>>(BB, DD, DD,
        ndH + (size_t)(NN - 1) * HK, NN * HK,
        ndH + (size_t)(NN - 1) * HK, NN * HK, HK, 0,
        WcH, nullptr, nullptr, cc, nullptr, 0);

    // ---- attention (packed in, packed msg out) ----
    attn_kernel<<<BB, blk>>>(be1, We2, be2, out_attn);

    // ---- update MLP: A = [nodes | msg] via dual source ----
    dim3 grid_big(DD / 128, MM / 128);      // 8 x 56
    gemm_f16_kernel<<<grid_big, blk, shm>>>(MM, DD, 2 * DD,
        ndH, HK, msgH, HK, HK, 0,
        Wu1H, bu1, nullptr, nullptr, hpH, 1);
    gemm_f16_kernel<<<grid_big, blk, shm>>>(MM, DD, DD,
        hpH, HK, hpH, HK, HK, 0,
        Wu2H, bu2, nodes, out_upd, updH, 0);

    // ---- importance MLP: A = [upd | upd_last] via dual source + row remap ----
    gemm_f16_kernel<<<grid_big, blk, shm>>>(MM, DD, 2 * DD,
        updH, HK, updH, HK, HK, 1,
        Wi1H, bi1, nullptr, hid, nullptr, 1);
    gemv_imp_kernel<<<MM, 128>>>(Wi2, bi2);
    imp_kernel<<<BB, 32>>>(out_imp);

    // ---- fused output + losses (merged) ----
    fusedphys_kernel<<<BB, blk>>>(out_imp, out_upd, out_fused);
    final_reduce_kernel<<<1, blk>>>(out);
}

// round 17
// speedup vs baseline: 2.3841x; 1.0193x over previous
#include <cuda_runtime.h>
#include <cuda_fp16.h>
#include <math.h>
#include <stdint.h>

// ---------------------------------------------------------------------------
// PhysicsGraphFusion: B=1024 graphs, N=7 nodes, D=1024 dim.
// Round 16: R15 structure + 4-stage cp.async pipeline in the GEMM
// (wait_group 2 steady state; latency hidden across 3 chunks).
// ---------------------------------------------------------------------------

#define BB   1024
#define NN   7
#define DD   1024
#define MM   (BB*NN)          // 7168
#define NP   (5*DD)           // 5120 packed projection width
#define NP2  (NP/2)           // 2560 u32 row stride of packed qkv

static const size_t OFF_FUSED = 0;
static const size_t OFF_UPD   = (size_t)BB*DD;
static const size_t OFF_IMP   = OFF_UPD + (size_t)MM*DD;
static const size_t OFF_ATTN  = OFF_IMP + (size_t)MM;
static const size_t OFF_PHYS  = OFF_ATTN + (size_t)BB*NN*NN;
static const size_t OFF_ALIGN = OFF_PHYS + 1;

// ---------------- device scratch (static; no runtime allocation) -----------
__device__ uint32_t g_qkvp[ (size_t)MM*NP2 ];       // packed f16 q|k|v|la|rb
__device__ float    g_cc  [ (size_t)BB*DD ];
__device__ float    g_hid [ (size_t)MM*DD ];
__device__ float    g_bpack[ NP ];
__device__ float    g_implog[ MM ];
__device__ float    g_phys_part [ BB ];
__device__ float    g_align_part[ BB ];

// activation planes (single f16 plane, k-pair packed u32, row-major [M][K/2])
__device__ uint32_t g_nodes_h[ (size_t)MM*DD/2 ];
__device__ uint32_t g_msg_h  [ (size_t)MM*DD/2 ];
__device__ uint32_t g_upd_h  [ (size_t)MM*DD/2 ];
__device__ uint32_t g_hidp_h [ (size_t)MM*DD/2 ];

// weight planes (single f16 plane, k-pair packed u32 [K/2][Nc])
__device__ uint32_t g_Wproj_h[ (size_t)(DD/2)*NP ];
__device__ uint32_t g_Wc_h   [ (size_t)(DD/2)*DD ];
__device__ uint32_t g_Wu1_h  [ (size_t)DD*DD ];     // K=2048 -> 1024 rows
__device__ uint32_t g_Wu2_h  [ (size_t)(DD/2)*DD ];
__device__ uint32_t g_Wi1_h  [ (size_t)DD*DD ];

__constant__ float c_adj[49] = {
    1,1,0,0,1,1,1,
    1,1,1,1,1,1,1,
    0,1,1,0,1,0,1,
    0,1,0,1,1,1,1,
    1,1,1,1,1,1,1,
    1,1,0,1,1,1,1,
    1,1,1,1,1,1,1 };

__device__ __forceinline__ float geluf(float x) {
    return 0.5f * x * (1.0f + erff(x * 0.70710678118654752440f));
}

__device__ __forceinline__ unsigned short f16_rn(float x) {
    __half h = __float2half_rn(x);
    return *reinterpret_cast<unsigned short*>(&h);
}
__device__ __forceinline__ uint32_t pack16(float x0, float x1) {
    return (uint32_t)f16_rn(x0) | ((uint32_t)f16_rn(x1) << 16);
}
__device__ __forceinline__ float2 up16(uint32_t w) {
    __half2 h = *reinterpret_cast<__half2*>(&w);
    return __half22float2(h);
}

__device__ __forceinline__ void mma_f16(float* c,
    uint32_t a0, uint32_t a1, uint32_t a2, uint32_t a3,
    uint32_t b0, uint32_t b1)
{
    asm volatile(
        "mma.sync.aligned.m16n8k16.row.col.f32.f16.f16.f32 "
        "{%0,%1,%2,%3}, {%4,%5,%6,%7}, {%8,%9}, {%0,%1,%2,%3};\n"
        : "+f"(c[0]), "+f"(c[1]), "+f"(c[2]), "+f"(c[3])
        : "r"(a0), "r"(a1), "r"(a2), "r"(a3), "r"(b0), "r"(b1));
}

__device__ __forceinline__ void cp_async16(uint32_t saddr, const void* gptr) {
    asm volatile("cp.async.ca.shared.global [%0], [%1], 16;\n"
                 :: "r"(saddr), "l"(gptr));
}

// ---------------------------------------------------------------------------
// f16 tensor-core GEMM with dual A source; 4-stage cp.async pipeline.
// BM=BN=128, BK=32. 256 threads = 8 warps (4x2), warp tile 32x64.
// Per-stage buffer: Ah[128][20] Bh[16][136] (u32 words). 2 CTAs/SM.
// ---------------------------------------------------------------------------
#define A_ST 20
#define B_ST 136
#define A_PL (128*A_ST)           // 2560
#define B_PL (16*B_ST)            // 2176
#define BUF_U32 (A_PL + B_PL)     // 4736
#define NSTAGE 4
#define SMEM_GEMM_BYTES (NSTAGE*BUF_U32*4)  // 75776

__global__ __launch_bounds__(256, 2)
void gemm_f16_kernel(int M, int Nc, int K,
    const uint32_t* __restrict__ Ah,  int lda32,
    const uint32_t* __restrict__ Ah2, int lda2_32, int kSplit32, int rowmap2,
    const uint32_t* __restrict__ Bh,
    const float* __restrict__ bias,
    const float* __restrict__ resid,
    float* __restrict__ Cf,
    uint32_t* __restrict__ ChH,
    int applyGelu)
{
    extern __shared__ uint32_t smem[];
    const uint32_t smem_base = (uint32_t)__cvta_generic_to_shared(smem);

    const int tid  = threadIdx.x;
    const int lane = tid & 31;
    const int wid  = tid >> 5;
    const int wm   = wid & 3;
    const int wn   = wid >> 2;
    const int gid  = lane >> 2;
    const int tig  = lane & 3;

    const int brow = blockIdx.y;
    const int bcol = blockIdx.x;

    int aC[2]; uint32_t aSm[2];
    const uint32_t* aB1[2];
    const uint32_t* aB2[2];
    #pragma unroll
    for (int it = 0; it < 2; it++) {
        int idx = it * 256 + tid;
        int ar  = idx >> 2;
        aC[it]  = (idx & 3) << 2;
        aSm[it] = (uint32_t)(ar * A_ST + aC[it]);
        int gRow = brow * 128 + ar;
        aB1[it] = Ah + (size_t)gRow * lda32;
        int r2  = rowmap2 ? (gRow / 7) * 7 + 6 : gRow;
        aB2[it] = Ah2 + (size_t)r2 * lda2_32;
    }
    int bKp[2], bC[2]; uint32_t bSm[2];
    #pragma unroll
    for (int it = 0; it < 2; it++) {
        int idx = it * 256 + tid;
        bKp[it] = idx >> 5;  bC[it] = (idx & 31) << 2;
        bSm[it] = (uint32_t)(A_PL + bKp[it] * B_ST + bC[it]);
    }

    const uint32_t* Bsrc = Bh + bcol * 128;

    float acc[2][8][4];
    #pragma unroll
    for (int mi = 0; mi < 2; mi++)
        #pragma unroll
        for (int ni = 0; ni < 8; ni++)
            #pragma unroll
            for (int r = 0; r < 4; r++) acc[mi][ni][r] = 0.0f;

    const int nChunks = K >> 5;

    // issue one chunk's loads into stage buffer and commit the group
    auto issue_chunk = [&](int chunk) {
        const uint32_t sb = smem_base + (uint32_t)((chunk & (NSTAGE - 1)) * BUF_U32) * 4;
        const int kb32 = chunk << 4;   // chunk * 16 u32 columns
        #pragma unroll
        for (int it = 0; it < 2; it++) {
            const uint32_t* ap = (kb32 < kSplit32)
                ? (aB1[it] + kb32)
                : (aB2[it] + (kb32 - kSplit32));
            cp_async16(sb + aSm[it] * 4, ap + aC[it]);
            cp_async16(sb + bSm[it] * 4,
                       Bsrc + (size_t)(kb32 + bKp[it]) * Nc + bC[it]);
        }
        asm volatile("cp.async.commit_group;\n");
    };

    // prologue: fill 3 stages
    #pragma unroll
    for (int pc = 0; pc < NSTAGE - 1; pc++)
        if (pc < nChunks) issue_chunk(pc);

    for (int c = 0; c < nChunks; c++) {
        // wait until chunk c's group has landed
        const int rem = nChunks - 1 - c;
        if (rem >= 2)      asm volatile("cp.async.wait_group 2;\n" ::: "memory");
        else if (rem == 1) asm volatile("cp.async.wait_group 1;\n" ::: "memory");
        else               asm volatile("cp.async.wait_group 0;\n" ::: "memory");
        __syncthreads();

        // refill the stage just freed (read completely in iteration c-1)
        if (c + NSTAGE - 1 < nChunks) issue_chunk(c + NSTAGE - 1);

        const uint32_t* buf = smem + (size_t)(c & (NSTAGE - 1)) * BUF_U32;
        const uint32_t* sAh = buf;
        const uint32_t* sBh = buf + A_PL;

        #pragma unroll
        for (int ks = 0; ks < 2; ks++) {
            uint32_t fah[2][4];
            #pragma unroll
            for (int mi = 0; mi < 2; mi++) {
                int r0 = (wm * 32 + mi * 16 + gid) * A_ST + ks * 8 + tig;
                fah[mi][0] = sAh[r0];
                fah[mi][1] = sAh[r0 + 8 * A_ST];
                fah[mi][2] = sAh[r0 + 4];
                fah[mi][3] = sAh[r0 + 8 * A_ST + 4];
            }
            #pragma unroll
            for (int ni = 0; ni < 8; ni++) {
                int kb = (ks * 8 + tig) * B_ST + wn * 64 + ni * 8 + gid;
                uint32_t bh0 = sBh[kb];
                uint32_t bh1 = sBh[kb + 4 * B_ST];
                #pragma unroll
                for (int mi = 0; mi < 2; mi++)
                    mma_f16(acc[mi][ni], fah[mi][0], fah[mi][1], fah[mi][2], fah[mi][3], bh0, bh1);
            }
        }
    }

    // ---- epilogue ----
    const int Nc2 = Nc >> 1;
    #pragma unroll
    for (int mi = 0; mi < 2; mi++) {
        #pragma unroll
        for (int ni = 0; ni < 8; ni++) {
            int row0 = brow * 128 + wm * 32 + mi * 16 + gid;
            int col0 = bcol * 128 + wn * 64 + ni * 8 + tig * 2;
            #pragma unroll
            for (int half = 0; half < 2; half++) {
                int row = row0 + half * 8;
                size_t base = (size_t)row * Nc + col0;
                float v0 = acc[mi][ni][half * 2 + 0];
                float v1 = acc[mi][ni][half * 2 + 1];
                if (bias) { v0 += bias[col0]; v1 += bias[col0 + 1]; }
                if (applyGelu) { v0 = geluf(v0); v1 = geluf(v1); }
                if (resid) { v0 += resid[base]; v1 += resid[base + 1]; }
                if (Cf) { Cf[base] = v0; Cf[base + 1] = v1; }
                if (ChH) {
                    size_t pidx = (size_t)row * Nc2 + (col0 >> 1);
                    ChH[pidx] = pack16(v0, v1);
                }
            }
        }
    }
}

// ---------------------------------------------------------------------------
// pre-pack: nodes plane
// ---------------------------------------------------------------------------
__global__ void split_nodes_kernel(const float* __restrict__ nodes)
{
    size_t i = (size_t)blockIdx.x * blockDim.x + threadIdx.x;
    if (i >= (size_t)MM * DD / 2) return;
    g_nodes_h[i] = pack16(nodes[2 * i], nodes[2 * i + 1]);
}

// one mega-pack launch: all weight planes + bias, region-dispatched
#define RP0 ((size_t)(DD/2)*NP)
#define RP1 (RP0 + (size_t)(DD/2)*DD)
#define RP2 (RP1 + (size_t)(DD/2)*DD)
#define RP3 (RP2 + (size_t)DD*DD)
#define RP4 (RP3 + (size_t)DD*DD)
#define RP5 (RP4 + NP)

__global__ void pack_all_kernel(const float* __restrict__ Wq,
                                const float* __restrict__ Wk,
                                const float* __restrict__ Wv,
                                const float* __restrict__ We1,
                                const float* __restrict__ Wu1,
                                const float* __restrict__ Wu2,
                                const float* __restrict__ Wi1,
                                const float* __restrict__ bq,
                                const float* __restrict__ bk,
                                const float* __restrict__ bv)
{
    size_t i = (size_t)blockIdx.x * blockDim.x + threadIdx.x;
    if (i >= RP5) return;
    if (i < RP0) {
        int kp = (int)(i / NP);
        int c  = (int)(i % NP);
        int seg = c >> 10, cc = c & 1023;
        const float* src;
        if      (seg == 0) src = Wq;
        else if (seg == 1) src = Wk;
        else if (seg == 2) src = Wv;
        else if (seg == 3) src = We1;
        else               src = We1 + (size_t)DD * DD;
        g_Wproj_h[i] = pack16(src[(size_t)(2 * kp) * DD + cc],
                              src[(size_t)(2 * kp + 1) * DD + cc]);
    } else if (i < RP1) {
        size_t j = i - RP0;
        int kp = (int)(j / DD), n = (int)(j % DD);
        const float* W = We1 + (size_t)2 * DD * DD;
        g_Wc_h[j] = pack16(W[(size_t)(2 * kp) * DD + n],
                           W[(size_t)(2 * kp + 1) * DD + n]);
    } else if (i < RP2) {
        size_t j = i - RP1;
        int kp = (int)(j / DD), n = (int)(j % DD);
        g_Wu2_h[j] = pack16(Wu2[(size_t)(2 * kp) * DD + n],
                            Wu2[(size_t)(2 * kp + 1) * DD + n]);
    } else if (i < RP3) {
        size_t j = i - RP2;
        int kp = (int)(j / DD), n = (int)(j % DD);
        g_Wu1_h[j] = pack16(Wu1[(size_t)(2 * kp) * DD + n],
                            Wu1[(size_t)(2 * kp + 1) * DD + n]);
    } else if (i < RP4) {
        size_t j = i - RP3;
        int kp = (int)(j / DD), n = (int)(j % DD);
        g_Wi1_h[j] = pack16(Wi1[(size_t)(2 * kp) * DD + n],
                            Wi1[(size_t)(2 * kp + 1) * DD + n]);
    } else {
        int c = (int)(i - RP4);
        int seg = c >> 10, cc = c & 1023;
        float v = 0.0f;
        if      (seg == 0) v = bq[cc];
        else if (seg == 1) v = bk[cc];
        else if (seg == 2) v = bv[cc];
        g_bpack[c] = v;
    }
}

// ---------------------------------------------------------------------------
// attention: reads packed qkv plane, writes packed msg plane
// ---------------------------------------------------------------------------
__global__ __launch_bounds__(256)
void attn_kernel(const float* __restrict__ be1,
                 const float* __restrict__ We2,
                 const float* __restrict__ be2,
                 float* __restrict__ out_attn)
{
    const int b    = blockIdx.x;
    const int tid  = threadIdx.x;
    const int lane = tid & 31;
    const int wid  = tid >> 5;

    __shared__ float s_logit[49];
    __shared__ float s_attn[49];

    const uint32_t* basep = g_qkvp + (size_t)b * NN * NP2;
    const float*    cc    = g_cc   + (size_t)b * DD;

    for (int p = wid; p < 49; p += 8) {
        const int n = p / 7, m = p % 7;
        const uint32_t* qn  = basep + (size_t)n * NP2 + 0*(DD/2);
        const uint32_t* km  = basep + (size_t)m * NP2 + 1*(DD/2);
        const uint32_t* lan = basep + (size_t)n * NP2 + 3*(DD/2);
        const uint32_t* rbm = basep + (size_t)m * NP2 + 4*(DD/2);
        float qk = 0.0f, e = 0.0f;
        for (int dp = lane; dp < DD / 2; dp += 32) {
            float2 q2 = up16(qn[dp]);
            float2 k2 = up16(km[dp]);
            qk = fmaf(q2.x, k2.x, qk);
            qk = fmaf(q2.y, k2.y, qk);
            float2 l2 = up16(lan[dp]);
            float2 r2 = up16(rbm[dp]);
            int d0 = 2 * dp;
            float h0 = l2.x + r2.x + cc[d0]     + be1[d0];
            float h1 = l2.y + r2.y + cc[d0 + 1] + be1[d0 + 1];
            e = fmaf(geluf(h0), We2[d0],     e);
            e = fmaf(geluf(h1), We2[d0 + 1], e);
        }
        #pragma unroll
        for (int o = 16; o > 0; o >>= 1) {
            qk += __shfl_down_sync(0xffffffffu, qk, o);
            e  += __shfl_down_sync(0xffffffffu, e,  o);
        }
        if (lane == 0)
            s_logit[p] = qk * (1.0f / 32.0f) + e + be2[0]
                       + (c_adj[p] - 1.0f) * 10000.0f;
    }
    __syncthreads();

    if (tid < 7) {
        const int n = tid;
        float mx = -1e30f;
        #pragma unroll
        for (int m = 0; m < 7; m++) mx = fmaxf(mx, s_logit[n * 7 + m]);
        float ex[7], s = 0.0f;
        #pragma unroll
        for (int m = 0; m < 7; m++) { ex[m] = expf(s_logit[n * 7 + m] - mx); s += ex[m]; }
        #pragma unroll
        for (int m = 0; m < 7; m++) {
            float a = ex[m] / s;
            s_attn[n * 7 + m] = a;
            out_attn[(size_t)b * 49 + n * 7 + m] = a;
        }
    }
    __syncthreads();

    uint32_t* msgp = g_msg_h + (size_t)b * NN * (DD / 2);
    for (int dp = tid; dp < DD / 2; dp += 256) {
        float v0[7], v1[7];
        #pragma unroll
        for (int m = 0; m < 7; m++) {
            float2 v2 = up16(basep[(size_t)m * NP2 + 2*(DD/2) + dp]);
            v0[m] = v2.x; v1[m] = v2.y;
        }
        #pragma unroll
        for (int n = 0; n < 7; n++) {
            float a0 = 0.0f, a1 = 0.0f;
            #pragma unroll
            for (int m = 0; m < 7; m++) {
                a0 = fmaf(s_attn[n * 7 + m], v0[m], a0);
                a1 = fmaf(s_attn[n * 7 + m], v1[m], a1);
            }
            msgp[(size_t)n * (DD / 2) + dp] = pack16(a0, a1);
        }
    }
}

__global__ __launch_bounds__(128)
void gemv_imp_kernel(const float* __restrict__ Wi2, const float* __restrict__ bi2)
{
    const int row = blockIdx.x;
    const int tid = threadIdx.x;
    const float* h = g_hid + (size_t)row * DD;
    float s = 0.0f;
    for (int d = tid; d < DD; d += 128) s = fmaf(h[d], Wi2[d], s);
    #pragma unroll
    for (int o = 16; o > 0; o >>= 1) s += __shfl_down_sync(0xffffffffu, s, o);
    __shared__ float red[4];
    if ((tid & 31) == 0) red[tid >> 5] = s;
    __syncthreads();
    if (tid == 0)
        g_implog[row] = red[0] + red[1] + red[2] + red[3] + bi2[0];
}

__global__ void imp_kernel(float* __restrict__ out_imp)
{
    const int b = blockIdx.x;
    if (threadIdx.x != 0) return;
    float l[7], mx = -1e30f;
    #pragma unroll
    for (int n = 0; n < 7; n++) { l[n] = g_implog[b * 7 + n]; mx = fmaxf(mx, l[n]); }
    float s = 0.0f;
    #pragma unroll
    for (int n = 0; n < 7; n++) { l[n] = expf(l[n] - mx); s += l[n]; }
    float imp[7];
    #pragma unroll
    for (int n = 0; n < 7; n++) imp[n] = l[n] / s;

    const float cap[7] = {1.f,1.f,1.f,0.26f,1.f,1.f,0.24f};
    const float fr [7] = {1.f,1.f,1.f,0.f,  1.f,1.f,0.f };
    float capped[7], sc = 0.0f, fm = 0.0f;
    #pragma unroll
    for (int n = 0; n < 7; n++) {
        capped[n] = fminf(imp[n], cap[n]);
        sc += capped[n];
        fm += imp[n] * fr[n];
    }
    float residual = fmaxf(1.0f - sc, 0.0f);
    float redis[7], sr = 0.0f;
    #pragma unroll
    for (int n = 0; n < 7; n++) {
        float fs = (fm > 1e-6f) ? imp[n] * fr[n] / fmaxf(fm, 1e-6f) : fr[n] / 5.0f;
        redis[n] = capped[n] + fs * residual;
        sr += redis[n];
    }
    #pragma unroll
    for (int n = 0; n < 7; n++)
        out_imp[b * 7 + n] = redis[n] / fmaxf(sr, 1e-6f);
}

// ---------------------------------------------------------------------------
// fused output + physics/alignment in ONE kernel; upd staged in smem
// ---------------------------------------------------------------------------
__global__ __launch_bounds__(256)
void fusedphys_kernel(const float* __restrict__ out_imp,
                      const float* __restrict__ upd,
                      float* __restrict__ out_fused)
{
    const int b = blockIdx.x;
    const int tid = threadIdx.x;
    const int lane = tid & 31, wid = tid >> 5;

    __shared__ float su[NN * DD];
    __shared__ float sf[DD];
    __shared__ float w[7];
    __shared__ float dots[57];

    if (tid < 7) w[tid] = out_imp[b * 7 + tid];
    const float* u = upd + (size_t)b * NN * DD;
    for (int i = tid; i < NN * DD; i += 256) su[i] = u[i];
    __syncthreads();

    for (int d = tid; d < DD; d += 256) {
        float acc = 0.0f;
        #pragma unroll
        for (int n = 0; n < 7; n++) acc = fmaf(w[n], su[n * DD + d], acc);
        sf[d] = acc;
        out_fused[(size_t)b * DD + d] = acc;
    }
    __syncthreads();

    for (int t = wid; t < 57; t += 8) {
        const float *x, *y;
        if (t < 49)      { x = su + (t / 7) * DD; y = su + (t % 7) * DD; }
        else if (t < 56) { x = su + (t - 49) * DD; y = sf; }
        else             { x = sf; y = sf; }
        float s = 0.0f;
        for (int d = lane; d < DD; d += 32) s = fmaf(x[d], y[d], s);
        #pragma unroll
        for (int o = 16; o > 0; o >>= 1) s += __shfl_down_sync(0xffffffffu, s, o);
        if (lane == 0) dots[t] = s;
    }
    __syncthreads();

    if (tid == 0) {
        float norms[7];
        #pragma unroll
        for (int n = 0; n < 7; n++) norms[n] = sqrtf(dots[n * 7 + n]);
        float edge = 0.0f, non = 0.0f;
        #pragma unroll
        for (int n = 0; n < 7; n++) {
            #pragma unroll
            for (int m = 0; m < 7; m++) {
                float cs = dots[n * 7 + m] / fmaxf(norms[n] * norms[m], 1e-8f);
                float a = c_adj[n * 7 + m];
                edge += (1.0f - cs) * a;
                float nonmask = (1.0f - a) * ((n == m) ? 0.0f : 1.0f);
                non += fmaxf(cs - 0.35f, 0.0f) * nonmask;
            }
        }
        g_phys_part[b] = edge / 41.0f + 0.5f * non / 8.0f;

        float fn = sqrtf(dots[56]);
        float al = 0.0f;
        #pragma unroll
        for (int n = 0; n < 7; n++) {
            float cs = dots[49 + n] / (fmaxf(norms[n], 1e-12f) * fmaxf(fn, 1e-12f));
            al += 1.0f - cs;
        }
        g_align_part[b] = al;
    }
}

__global__ __launch_bounds__(256)
void final_reduce_kernel(float* __restrict__ out)
{
    const int tid = threadIdx.x;
    float p = 0.0f, a = 0.0f;
    for (int b = tid; b < BB; b += 256) { p += g_phys_part[b]; a += g_align_part[b]; }
    __shared__ float sp[256], sa[256];
    sp[tid] = p; sa[tid] = a;
    __syncthreads();
    for (int s = 128; s > 0; s >>= 1) {
        if (tid < s) { sp[tid] += sp[tid + s]; sa[tid] += sa[tid + s]; }
        __syncthreads();
    }
    if (tid == 0) {
        out[OFF_PHYS]  = sp[0];
        out[OFF_ALIGN] = sa[0] / (float)(BB * NN);
    }
}

// ---------------------------------------------------------------------------
extern "C" void kernel_launch(void* const* d_in, const int* in_sizes, int n_in,
                              void* d_out, int out_size)
{
    const float* nodes = (const float*)d_in[0];
    const float* Wq    = (const float*)d_in[1];
    const float* bq    = (const float*)d_in[2];
    const float* Wk    = (const float*)d_in[3];
    const float* bk    = (const float*)d_in[4];
    const float* Wv    = (const float*)d_in[5];
    const float* bv    = (const float*)d_in[6];
    const float* We1   = (const float*)d_in[7];
    const float* be1   = (const float*)d_in[8];
    const float* We2   = (const float*)d_in[9];
    const float* be2   = (const float*)d_in[10];
    const float* Wu1   = (const float*)d_in[11];
    const float* bu1   = (const float*)d_in[12];
    const float* Wu2   = (const float*)d_in[13];
    const float* bu2   = (const float*)d_in[14];
    const float* Wi1   = (const float*)d_in[15];
    const float* bi1   = (const float*)d_in[16];
    const float* Wi2   = (const float*)d_in[17];
    const float* bi2   = (const float*)d_in[18];

    float* out       = (float*)d_out;
    float* out_fused = out + OFF_FUSED;
    float* out_upd   = out + OFF_UPD;
    float* out_imp   = out + OFF_IMP;
    float* out_attn  = out + OFF_ATTN;

    float* cc  = nullptr; cudaGetSymbolAddress((void**)&cc,  g_cc);
    float* hid = nullptr; cudaGetSymbolAddress((void**)&hid, g_hid);
    float* bpk = nullptr; cudaGetSymbolAddress((void**)&bpk, g_bpack);

    uint32_t *qkvp=nullptr,*ndH=nullptr,*msgH=nullptr,*updH=nullptr,*hpH=nullptr;
    cudaGetSymbolAddress((void**)&qkvp, g_qkvp);
    cudaGetSymbolAddress((void**)&ndH,  g_nodes_h);
    cudaGetSymbolAddress((void**)&msgH, g_msg_h);
    cudaGetSymbolAddress((void**)&updH, g_upd_h);
    cudaGetSymbolAddress((void**)&hpH,  g_hidp_h);

    uint32_t *WprH=nullptr,*WcH=nullptr,*Wu1H=nullptr,*Wu2H=nullptr,*Wi1H=nullptr;
    cudaGetSymbolAddress((void**)&WprH, g_Wproj_h);
    cudaGetSymbolAddress((void**)&WcH,  g_Wc_h);
    cudaGetSymbolAddress((void**)&Wu1H, g_Wu1_h);
    cudaGetSymbolAddress((void**)&Wu2H, g_Wu2_h);
    cudaGetSymbolAddress((void**)&Wi1H, g_Wi1_h);

    cudaFuncSetAttribute(gemm_f16_kernel,
                         cudaFuncAttributeMaxDynamicSharedMemorySize,
                         SMEM_GEMM_BYTES);

    dim3 blk(256);
    const size_t shm = SMEM_GEMM_BYTES;
    const int HK = DD / 2;

    // ---- pre-pack: 2 launches ----
    {
        size_t n = (size_t)MM * DD / 2;
        split_nodes_kernel<<<(unsigned)((n + 255) / 256), blk>>>(nodes);
        pack_all_kernel<<<(unsigned)((RP5 + 255) / 256), blk>>>(
            Wq, Wk, Wv, We1, Wu1, Wu2, Wi1, bq, bk, bv);
    }

    // ---- merged projections -> packed qkv plane ----
    dim3 grid_proj(NP / 128, MM / 128);     // 40 x 56
    gemm_f16_kernel<<<grid_proj, blk, shm>>>(MM, NP, DD,
        ndH, HK, ndH, HK, HK, 0,
        WprH, bpk, nullptr, nullptr, qkvp, 0);

    // ---- cc projection (last node rows), f32 out ----
    dim3 grid_cc(DD / 128, BB / 128);       // 8 x 8
    gemm_f16_kernel<<<grid_cc, blk, shm>>>(BB, DD, DD,
        ndH + (size_t)(NN - 1) * HK, NN * HK,
        ndH + (size_t)(NN - 1) * HK, NN * HK, HK, 0,
        WcH, nullptr, nullptr, cc, nullptr, 0);

    // ---- attention (packed in, packed msg out) ----
    attn_kernel<<<BB, blk>>>(be1, We2, be2, out_attn);

    // ---- update MLP: A = [nodes | msg] via dual source ----
    dim3 grid_big(DD / 128, MM / 128);      // 8 x 56
    gemm_f16_kernel<<<grid_big, blk, shm>>>(MM, DD, 2 * DD,
        ndH, HK, msgH, HK, HK, 0,
        Wu1H, bu1, nullptr, nullptr, hpH, 1);
    gemm_f16_kernel<<<grid_big, blk, shm>>>(MM, DD, DD,
        hpH, HK, hpH, HK, HK, 0,
        Wu2H, bu2, nodes, out_upd, updH, 0);

    // ---- importance MLP: A = [upd | upd_last] via dual source + row remap ----
    gemm_f16_kernel<<<grid_big, blk, shm>>>(MM, DD, 2 * DD,
        updH, HK, updH, HK, HK, 1,
        Wi1H, bi1, nullptr, hid, nullptr, 1);
    gemv_imp_kernel<<<MM, 128>>>(Wi2, bi2);
    imp_kernel<<<BB, 32>>>(out_imp);

    // ---- fused output + losses (merged) ----
    fusedphys_kernel<<<BB, blk>>>(out_imp, out_upd, out_fused);
    final_reduce_kernel<<<1, blk>>>(out);
}